// round 1
// baseline (speedup 1.0000x reference)
#include <cuda_runtime.h>
#include <math.h>

// Problem constants
#define B_   4
#define S_   1024
#define H_   1024
#define NH_  16
#define HD_  64
#define NREL 257   // 2*128+1

// Scratch buffers (device globals — no cudaMalloc allowed)
__device__ float g_Q[B_ * S_ * H_];
__device__ float g_K[B_ * S_ * H_];
__device__ float g_V[B_ * S_ * H_];
__device__ float g_ATT[B_ * S_ * H_];

// ---------------------------------------------------------------------------
// GEMM: C[M,N] = A[M,K] @ B[N,K]^T + bias[N]
// 128x128 tile, BK=16, 256 threads, 8x8 per-thread microtile.
// ---------------------------------------------------------------------------
__global__ __launch_bounds__(256) void gemm_bt_bias(
    const float* __restrict__ A, const float* __restrict__ Bm,
    const float* __restrict__ bias, float* __restrict__ C,
    int M, int N, int K)
{
    const int BM = 128, BN = 128, BK = 16;
    __shared__ float As[BK][BM];
    __shared__ float Bs[BK][BN];

    int tid = threadIdx.x;
    int m0 = blockIdx.y * BM;
    int n0 = blockIdx.x * BN;
    int ty = tid / 16;   // 0..15
    int tx = tid % 16;   // 0..15

    float acc[8][8];
#pragma unroll
    for (int i = 0; i < 8; i++)
#pragma unroll
        for (int j = 0; j < 8; j++) acc[i][j] = 0.f;

    for (int k0 = 0; k0 < K; k0 += BK) {
        // load A tile (128 rows x 16 cols) and B tile, transposed into smem
#pragma unroll
        for (int l = 0; l < 2; l++) {
            int idx = tid + l * 256;          // 0..511
            int r = idx >> 2;                 // 0..127
            int c = (idx & 3) * 4;            // 0,4,8,12
            float4 va = *(const float4*)&A[(size_t)(m0 + r) * K + k0 + c];
            As[c + 0][r] = va.x; As[c + 1][r] = va.y;
            As[c + 2][r] = va.z; As[c + 3][r] = va.w;
            float4 vb = *(const float4*)&Bm[(size_t)(n0 + r) * K + k0 + c];
            Bs[c + 0][r] = vb.x; Bs[c + 1][r] = vb.y;
            Bs[c + 2][r] = vb.z; Bs[c + 3][r] = vb.w;
        }
        __syncthreads();

#pragma unroll
        for (int k = 0; k < BK; k++) {
            float a[8], b[8];
            *(float4*)&a[0] = *(float4*)&As[k][ty * 8];
            *(float4*)&a[4] = *(float4*)&As[k][ty * 8 + 4];
            *(float4*)&b[0] = *(float4*)&Bs[k][tx * 8];
            *(float4*)&b[4] = *(float4*)&Bs[k][tx * 8 + 4];
#pragma unroll
            for (int i = 0; i < 8; i++)
#pragma unroll
                for (int j = 0; j < 8; j++)
                    acc[i][j] = fmaf(a[i], b[j], acc[i][j]);
        }
        __syncthreads();
    }

#pragma unroll
    for (int i = 0; i < 8; i++) {
        size_t row = (size_t)(m0 + ty * 8 + i);
#pragma unroll
        for (int j = 0; j < 8; j++) {
            int col = n0 + tx * 8 + j;
            C[row * N + col] = acc[i][j] + bias[col];
        }
    }
}

// ---------------------------------------------------------------------------
// Attention with relative-position bias, online softmax.
// Block: 128 threads, handles 16 queries of one (b, head). Key tiles of 32.
// bias(q,k) = P[q][clip(k-q,-128,128)+128], P[q][r] = Q[q] . rel_emb[r]
// computed per-block into shared memory.
// ---------------------------------------------------------------------------
#define TQ 16
#define TK 32

__global__ __launch_bounds__(128) void attn_kernel(
    const float* __restrict__ Q, const float* __restrict__ K,
    const float* __restrict__ V, const float* __restrict__ rel_emb,
    float* __restrict__ O)
{
    __shared__ float Qs[TQ][68];
    __shared__ float Ks[TK][68];
    __shared__ float Vs[TK][68];
    __shared__ float Ss[TQ][33];
    __shared__ float Ps[TQ][NREL];

    const int b = blockIdx.z;
    const int n = blockIdx.y;
    const int q0 = blockIdx.x * TQ;
    const int tid = threadIdx.x;

    const float* Qb = Q + ((size_t)b * S_) * H_ + n * HD_;
    const float* Kb = K + ((size_t)b * S_) * H_ + n * HD_;
    const float* Vb = V + ((size_t)b * S_) * H_ + n * HD_;

    // Load Q tile: 16 rows x 64 floats
    for (int i = tid; i < TQ * 16; i += 128) {
        int r = i / 16, c = (i % 16) * 4;
        float4 v = *(const float4*)&Qb[(size_t)(q0 + r) * H_ + c];
        Qs[r][c + 0] = v.x; Qs[r][c + 1] = v.y;
        Qs[r][c + 2] = v.z; Qs[r][c + 3] = v.w;
    }
    __syncthreads();

    // Precompute P[q][r] = Q[q] . rel_emb[r]
    for (int i = tid; i < TQ * NREL; i += 128) {
        int q = i / NREL, r = i % NREL;
        const float* e = rel_emb + r * HD_;
        float s = 0.f;
#pragma unroll
        for (int d = 0; d < HD_; d++) s = fmaf(Qs[q][d], e[d], s);
        Ps[q][r] = s;
    }
    __syncthreads();

    const int q = tid >> 3;   // 0..15 — this thread's query
    const int u = tid & 7;    // team lane 0..7, owns dims u*8..u*8+7

    float run_max = -INFINITY;
    float run_sum = 0.f;
    float acc[8];
#pragma unroll
    for (int d = 0; d < 8; d++) acc[d] = 0.f;

    for (int k0 = 0; k0 < S_; k0 += TK) {
        // Load K/V tiles: 32 rows x 64 floats each
        for (int i = tid; i < TK * 16; i += 128) {
            int r = i / 16, c = (i % 16) * 4;
            float4 kv = *(const float4*)&Kb[(size_t)(k0 + r) * H_ + c];
            Ks[r][c + 0] = kv.x; Ks[r][c + 1] = kv.y;
            Ks[r][c + 2] = kv.z; Ks[r][c + 3] = kv.w;
            float4 vv = *(const float4*)&Vb[(size_t)(k0 + r) * H_ + c];
            Vs[r][c + 0] = vv.x; Vs[r][c + 1] = vv.y;
            Vs[r][c + 2] = vv.z; Vs[r][c + 3] = vv.w;
        }
        __syncthreads();

        // Scores: each thread computes 4 scores (j = u + 8*i)
        float m_tile = -INFINITY;
#pragma unroll
        for (int i = 0; i < 4; i++) {
            int j = u + 8 * i;
            float s = 0.f;
#pragma unroll
            for (int d = 0; d < HD_; d++) s = fmaf(Qs[q][d], Ks[j][d], s);
            int rel = k0 + j - (q0 + q);
            rel = min(128, max(-128, rel));
            s = (s + Ps[q][rel + 128]) * 0.125f;   // 1/sqrt(64)
            Ss[q][j] = s;
            m_tile = fmaxf(m_tile, s);
        }
        // reduce max within 8-lane team
#pragma unroll
        for (int off = 4; off >= 1; off >>= 1)
            m_tile = fmaxf(m_tile, __shfl_xor_sync(0xffffffffu, m_tile, off, 8));

        float new_max = fmaxf(run_max, m_tile);
        float scale = __expf(run_max - new_max);
        run_max = new_max;

        float psum = 0.f;
#pragma unroll
        for (int i = 0; i < 4; i++) {
            int j = u + 8 * i;
            float p = __expf(Ss[q][j] - new_max);
            Ss[q][j] = p;
            psum += p;
        }
#pragma unroll
        for (int off = 4; off >= 1; off >>= 1)
            psum += __shfl_xor_sync(0xffffffffu, psum, off, 8);
        run_sum = run_sum * scale + psum;

#pragma unroll
        for (int d = 0; d < 8; d++) acc[d] *= scale;
        __syncwarp();   // team wrote p values into Ss row; same warp reads all 32

        // acc[d] += sum_j p_j * V[j][u*8+d]
#pragma unroll 8
        for (int j = 0; j < TK; j++) {
            float p = Ss[q][j];
#pragma unroll
            for (int d = 0; d < 8; d++)
                acc[d] = fmaf(p, Vs[j][u * 8 + d], acc[d]);
        }
        __syncthreads();   // protect Ks/Vs/Ss before next tile load
    }

    float inv = 1.f / run_sum;
    float* Ob = O + ((size_t)b * S_) * H_ + n * HD_;
#pragma unroll
    for (int d = 0; d < 8; d++)
        Ob[(size_t)(q0 + q) * H_ + u * 8 + d] = acc[d] * inv;
}

// ---------------------------------------------------------------------------
// Launch
// ---------------------------------------------------------------------------
extern "C" void kernel_launch(void* const* d_in, const int* in_sizes, int n_in,
                              void* d_out, int out_size)
{
    const float* x   = (const float*)d_in[0];
    const float* Wq  = (const float*)d_in[1];
    const float* bq  = (const float*)d_in[2];
    const float* Wk  = (const float*)d_in[3];
    const float* bk  = (const float*)d_in[4];
    const float* Wv  = (const float*)d_in[5];
    const float* bv  = (const float*)d_in[6];
    const float* Wo  = (const float*)d_in[7];
    const float* bo  = (const float*)d_in[8];
    const float* rel = (const float*)d_in[9];
    float* out = (float*)d_out;

    float *pQ, *pK, *pV, *pA;
    cudaGetSymbolAddress((void**)&pQ, g_Q);
    cudaGetSymbolAddress((void**)&pK, g_K);
    cudaGetSymbolAddress((void**)&pV, g_V);
    cudaGetSymbolAddress((void**)&pA, g_ATT);

    const int M = B_ * S_;   // 4096
    const int N = H_;        // 1024
    const int K = H_;        // 1024

    dim3 gemm_grid(N / 128, M / 128);
    gemm_bt_bias<<<gemm_grid, 256>>>(x, Wq, bq, pQ, M, N, K);
    gemm_bt_bias<<<gemm_grid, 256>>>(x, Wk, bk, pK, M, N, K);
    gemm_bt_bias<<<gemm_grid, 256>>>(x, Wv, bv, pV, M, N, K);

    dim3 attn_grid(S_ / TQ, NH_, B_);
    attn_kernel<<<attn_grid, 128>>>(pQ, pK, pV, rel, pA);

    gemm_bt_bias<<<gemm_grid, 256>>>(pA, Wo, bo, out, M, N, K);
}

// round 4
// speedup vs baseline: 2.0344x; 2.0344x over previous
#include <cuda_runtime.h>
#include <cuda_bf16.h>
#include <math.h>
#include <stdint.h>

// ---------------------------------------------------------------------------
// Problem constants
// ---------------------------------------------------------------------------
#define B_   4
#define S_   1024
#define H_   1024
#define NH_  16
#define HD_  64
#define NREL 257   // 2*128+1
#define MTOT (B_ * S_)   // 4096

// ---------------------------------------------------------------------------
// Scratch (device globals — no cudaMalloc allowed)
// ---------------------------------------------------------------------------
__device__ float g_Q[MTOT * H_];
__device__ float g_K[MTOT * H_];
__device__ float g_V[MTOT * H_];
__device__ float g_ATT[MTOT * H_];

__device__ __nv_bfloat16 g_xh[MTOT * H_];
__device__ __nv_bfloat16 g_xl[MTOT * H_];
__device__ __nv_bfloat16 g_Wqh[H_ * H_];
__device__ __nv_bfloat16 g_Wql[H_ * H_];
__device__ __nv_bfloat16 g_Wkh[H_ * H_];
__device__ __nv_bfloat16 g_Wkl[H_ * H_];
__device__ __nv_bfloat16 g_Wvh[H_ * H_];
__device__ __nv_bfloat16 g_Wvl[H_ * H_];
__device__ __nv_bfloat16 g_Woh[H_ * H_];
__device__ __nv_bfloat16 g_Wol[H_ * H_];
__device__ __nv_bfloat16 g_ah[MTOT * H_];
__device__ __nv_bfloat16 g_al[MTOT * H_];

// ---------------------------------------------------------------------------
// Split fp32 -> (bf16 hi, bf16 lo) elementwise
// ---------------------------------------------------------------------------
__global__ __launch_bounds__(256) void split_kernel(
    const float4* __restrict__ src, uint2* __restrict__ hi, uint2* __restrict__ lo, int n4)
{
    int i = blockIdx.x * blockDim.x + threadIdx.x;
    if (i >= n4) return;
    float4 v = src[i];
    __nv_bfloat16 h0 = __float2bfloat16(v.x);
    __nv_bfloat16 h1 = __float2bfloat16(v.y);
    __nv_bfloat16 h2 = __float2bfloat16(v.z);
    __nv_bfloat16 h3 = __float2bfloat16(v.w);
    __nv_bfloat16 l0 = __float2bfloat16(v.x - __bfloat162float(h0));
    __nv_bfloat16 l1 = __float2bfloat16(v.y - __bfloat162float(h1));
    __nv_bfloat16 l2 = __float2bfloat16(v.z - __bfloat162float(h2));
    __nv_bfloat16 l3 = __float2bfloat16(v.w - __bfloat162float(h3));
    uint2 hw, lw;
    hw.x = (uint32_t)__bfloat16_as_ushort(h0) | ((uint32_t)__bfloat16_as_ushort(h1) << 16);
    hw.y = (uint32_t)__bfloat16_as_ushort(h2) | ((uint32_t)__bfloat16_as_ushort(h3) << 16);
    lw.x = (uint32_t)__bfloat16_as_ushort(l0) | ((uint32_t)__bfloat16_as_ushort(l1) << 16);
    lw.y = (uint32_t)__bfloat16_as_ushort(l2) | ((uint32_t)__bfloat16_as_ushort(l3) << 16);
    hi[i] = hw;
    lo[i] = lw;
}

// ---------------------------------------------------------------------------
// mma.sync helpers
// ---------------------------------------------------------------------------
__device__ __forceinline__ void mma16816(float* c,
    uint32_t a0, uint32_t a1, uint32_t a2, uint32_t a3, uint32_t b0, uint32_t b1)
{
    asm volatile(
        "mma.sync.aligned.m16n8k16.row.col.f32.bf16.bf16.f32 "
        "{%0,%1,%2,%3}, {%4,%5,%6,%7}, {%8,%9}, {%0,%1,%2,%3};\n"
        : "+f"(c[0]), "+f"(c[1]), "+f"(c[2]), "+f"(c[3])
        : "r"(a0), "r"(a1), "r"(a2), "r"(a3), "r"(b0), "r"(b1));
}

// Swizzled smem byte offset within a 128-row x 64-byte tile.
// offset = row*64 + ((seg ^ ((row>>1)&3))<<4) + (kbyte&15), seg = kbyte>>4
__device__ __forceinline__ uint32_t swz(int row, int kbyte)
{
    return (uint32_t)(row * 64 + ((((kbyte >> 4) ^ ((row >> 1) & 3)) << 4) | (kbyte & 15)));
}

__device__ __forceinline__ uint32_t lds32(const uint8_t* base, int row, int kbyte)
{
    return *(const uint32_t*)(base + swz(row, kbyte));
}

// ---------------------------------------------------------------------------
// Tensor-core GEMM: C[M,1024] = A[M,1024] @ B[1024,1024]^T + bias
// A,B in bf16 hi/lo split; 3 HMMA passes (Ah*Bh + Ah*Bl + Al*Bh), fp32 acc.
// Block tile 128x128x32, 256 threads (8 warps of 32x64).
// ---------------------------------------------------------------------------
__global__ __launch_bounds__(256) void gemm_mma(
    const __nv_bfloat16* __restrict__ Ahg, const __nv_bfloat16* __restrict__ Alg,
    const __nv_bfloat16* __restrict__ Bhg, const __nv_bfloat16* __restrict__ Blg,
    const float* __restrict__ bias, float* __restrict__ C)
{
    __shared__ __align__(16) uint8_t sAh[128 * 64];
    __shared__ __align__(16) uint8_t sAl[128 * 64];
    __shared__ __align__(16) uint8_t sBh[128 * 64];
    __shared__ __align__(16) uint8_t sBl[128 * 64];

    const int tid = threadIdx.x;
    const int lane = tid & 31;
    const int wid = tid >> 5;
    const int warp_m = wid >> 1;     // 0..3
    const int warp_n = wid & 1;      // 0..1
    const int m0 = blockIdx.y * 128;
    const int n0 = blockIdx.x * 128;
    const int g = lane >> 2;         // 0..7
    const int t4 = lane & 3;         // 0..3

    float acc[2][8][4];
#pragma unroll
    for (int mt = 0; mt < 2; mt++)
#pragma unroll
        for (int nt = 0; nt < 8; nt++)
#pragma unroll
            for (int i = 0; i < 4; i++) acc[mt][nt][i] = 0.f;

#pragma unroll 1
    for (int kt = 0; kt < 32; kt++) {
        // Load k-tile: 128 rows x 32 bf16 (64B) per matrix; 512 16B segs each.
#pragma unroll
        for (int l = 0; l < 2; l++) {
            int s = tid + l * 256;
            int row = s >> 2;
            int seg = s & 3;
            uint32_t soff = (uint32_t)(row * 64 + ((seg ^ ((row >> 1) & 3)) << 4));
            size_t ga = (size_t)(m0 + row) * H_ + kt * 32 + seg * 8;
            size_t gb = (size_t)(n0 + row) * H_ + kt * 32 + seg * 8;
            *(uint4*)(sAh + soff) = *(const uint4*)(Ahg + ga);
            *(uint4*)(sAl + soff) = *(const uint4*)(Alg + ga);
            *(uint4*)(sBh + soff) = *(const uint4*)(Bhg + gb);
            *(uint4*)(sBl + soff) = *(const uint4*)(Blg + gb);
        }
        __syncthreads();

#pragma unroll
        for (int kk = 0; kk < 64; kk += 32) {   // kbyte base: 0, 32 (k = 0, 16)
            const int kb = kk + t4 * 4;
            uint32_t ah[2][4], al[2][4];
#pragma unroll
            for (int mt = 0; mt < 2; mt++) {
                int r = warp_m * 32 + mt * 16 + g;
                ah[mt][0] = lds32(sAh, r, kb);
                ah[mt][1] = lds32(sAh, r + 8, kb);
                ah[mt][2] = lds32(sAh, r, kb + 16);
                ah[mt][3] = lds32(sAh, r + 8, kb + 16);
                al[mt][0] = lds32(sAl, r, kb);
                al[mt][1] = lds32(sAl, r + 8, kb);
                al[mt][2] = lds32(sAl, r, kb + 16);
                al[mt][3] = lds32(sAl, r + 8, kb + 16);
            }
#pragma unroll
            for (int nt = 0; nt < 8; nt++) {
                int n = warp_n * 64 + nt * 8 + g;
                uint32_t bh0 = lds32(sBh, n, kb);
                uint32_t bh1 = lds32(sBh, n, kb + 16);
                uint32_t bl0 = lds32(sBl, n, kb);
                uint32_t bl1 = lds32(sBl, n, kb + 16);
#pragma unroll
                for (int mt = 0; mt < 2; mt++) {
                    mma16816(acc[mt][nt], ah[mt][0], ah[mt][1], ah[mt][2], ah[mt][3], bh0, bh1);
                    mma16816(acc[mt][nt], ah[mt][0], ah[mt][1], ah[mt][2], ah[mt][3], bl0, bl1);
                    mma16816(acc[mt][nt], al[mt][0], al[mt][1], al[mt][2], al[mt][3], bh0, bh1);
                }
            }
        }
        __syncthreads();
    }

    // Epilogue: bias add + store (float2 per fragment half)
#pragma unroll
    for (int mt = 0; mt < 2; mt++) {
        int row = m0 + warp_m * 32 + mt * 16 + g;
#pragma unroll
        for (int nt = 0; nt < 8; nt++) {
            int col = n0 + warp_n * 64 + nt * 8 + t4 * 2;
            float2 bv = *(const float2*)&bias[col];
            float2 o0, o1;
            o0.x = acc[mt][nt][0] + bv.x; o0.y = acc[mt][nt][1] + bv.y;
            o1.x = acc[mt][nt][2] + bv.x; o1.y = acc[mt][nt][3] + bv.y;
            *(float2*)&C[(size_t)row * H_ + col] = o0;
            *(float2*)&C[(size_t)(row + 8) * H_ + col] = o1;
        }
    }
}

// ---------------------------------------------------------------------------
// Attention with relative-position bias, online softmax. float4-vectorized.
// Block: 128 threads, 16 queries of one (b,head). Key tiles of 32.
// ---------------------------------------------------------------------------
#define TQ 16
#define TK 32

__global__ __launch_bounds__(128) void attn_kernel(
    const float* __restrict__ Q, const float* __restrict__ K,
    const float* __restrict__ V, const float* __restrict__ rel_emb,
    float* __restrict__ O)
{
    __shared__ float Qs[TQ][68];
    __shared__ float Ks[TK][68];
    __shared__ float Vs[TK][68];
    __shared__ float Ss[TQ][33];
    __shared__ float Ps[TQ][NREL];

    const int b = blockIdx.z;
    const int n = blockIdx.y;
    const int q0 = blockIdx.x * TQ;
    const int tid = threadIdx.x;

    const float* Qb = Q + ((size_t)b * S_) * H_ + n * HD_;
    const float* Kb = K + ((size_t)b * S_) * H_ + n * HD_;
    const float* Vb = V + ((size_t)b * S_) * H_ + n * HD_;

    // Load Q tile
    for (int i = tid; i < TQ * 16; i += 128) {
        int r = i / 16, c = (i % 16) * 4;
        float4 v = *(const float4*)&Qb[(size_t)(q0 + r) * H_ + c];
        *(float4*)&Qs[r][c] = v;
    }
    __syncthreads();

    // Precompute P[q][r] = Q[q] . rel_emb[r]  (float4)
    for (int i = tid; i < TQ * NREL; i += 128) {
        int q = i / NREL, r = i % NREL;
        const float4* e = (const float4*)(rel_emb + r * HD_);
        float s = 0.f;
#pragma unroll
        for (int d4 = 0; d4 < 16; d4++) {
            float4 qv = *(const float4*)&Qs[q][d4 * 4];
            float4 ev = __ldg(&e[d4]);
            s = fmaf(qv.x, ev.x, s); s = fmaf(qv.y, ev.y, s);
            s = fmaf(qv.z, ev.z, s); s = fmaf(qv.w, ev.w, s);
        }
        Ps[q][r] = s;
    }
    __syncthreads();

    const int q = tid >> 3;   // 0..15
    const int u = tid & 7;    // 0..7, owns dims u*8..u*8+7

    float run_max = -INFINITY;
    float run_sum = 0.f;
    float4 accA = make_float4(0.f, 0.f, 0.f, 0.f);
    float4 accB = make_float4(0.f, 0.f, 0.f, 0.f);

    for (int k0 = 0; k0 < S_; k0 += TK) {
        // Load K/V tiles
        for (int i = tid; i < TK * 16; i += 128) {
            int r = i / 16, c = (i % 16) * 4;
            *(float4*)&Ks[r][c] = *(const float4*)&Kb[(size_t)(k0 + r) * H_ + c];
            *(float4*)&Vs[r][c] = *(const float4*)&Vb[(size_t)(k0 + r) * H_ + c];
        }
        __syncthreads();

        // Scores: 4 per thread (j = u + 8*i), float4 inner product
        float s0 = 0.f, s1 = 0.f, s2 = 0.f, s3 = 0.f;
#pragma unroll
        for (int d4 = 0; d4 < 16; d4++) {
            float4 qv = *(const float4*)&Qs[q][d4 * 4];
            float4 k0v = *(const float4*)&Ks[u][d4 * 4];
            float4 k1v = *(const float4*)&Ks[u + 8][d4 * 4];
            float4 k2v = *(const float4*)&Ks[u + 16][d4 * 4];
            float4 k3v = *(const float4*)&Ks[u + 24][d4 * 4];
            s0 = fmaf(qv.x, k0v.x, s0); s0 = fmaf(qv.y, k0v.y, s0);
            s0 = fmaf(qv.z, k0v.z, s0); s0 = fmaf(qv.w, k0v.w, s0);
            s1 = fmaf(qv.x, k1v.x, s1); s1 = fmaf(qv.y, k1v.y, s1);
            s1 = fmaf(qv.z, k1v.z, s1); s1 = fmaf(qv.w, k1v.w, s1);
            s2 = fmaf(qv.x, k2v.x, s2); s2 = fmaf(qv.y, k2v.y, s2);
            s2 = fmaf(qv.z, k2v.z, s2); s2 = fmaf(qv.w, k2v.w, s2);
            s3 = fmaf(qv.x, k3v.x, s3); s3 = fmaf(qv.y, k3v.y, s3);
            s3 = fmaf(qv.z, k3v.z, s3); s3 = fmaf(qv.w, k3v.w, s3);
        }
        float sc[4] = {s0, s1, s2, s3};
        float m_tile = -INFINITY;
#pragma unroll
        for (int i = 0; i < 4; i++) {
            int j = u + 8 * i;
            int rel = k0 + j - (q0 + q);
            rel = min(128, max(-128, rel));
            float s = (sc[i] + Ps[q][rel + 128]) * 0.125f;   // 1/sqrt(64)
            sc[i] = s;
            m_tile = fmaxf(m_tile, s);
        }
#pragma unroll
        for (int off = 4; off >= 1; off >>= 1)
            m_tile = fmaxf(m_tile, __shfl_xor_sync(0xffffffffu, m_tile, off, 8));

        float new_max = fmaxf(run_max, m_tile);
        float scale = __expf(run_max - new_max);
        run_max = new_max;

        float psum = 0.f;
#pragma unroll
        for (int i = 0; i < 4; i++) {
            int j = u + 8 * i;
            float p = __expf(sc[i] - new_max);
            Ss[q][j] = p;
            psum += p;
        }
#pragma unroll
        for (int off = 4; off >= 1; off >>= 1)
            psum += __shfl_xor_sync(0xffffffffu, psum, off, 8);
        run_sum = run_sum * scale + psum;

        accA.x *= scale; accA.y *= scale; accA.z *= scale; accA.w *= scale;
        accB.x *= scale; accB.y *= scale; accB.z *= scale; accB.w *= scale;
        __syncwarp();   // team wrote p into Ss row; warp reads all 32

#pragma unroll 8
        for (int j = 0; j < TK; j++) {
            float p = Ss[q][j];
            float4 v0 = *(const float4*)&Vs[j][u * 8];
            float4 v1 = *(const float4*)&Vs[j][u * 8 + 4];
            accA.x = fmaf(p, v0.x, accA.x); accA.y = fmaf(p, v0.y, accA.y);
            accA.z = fmaf(p, v0.z, accA.z); accA.w = fmaf(p, v0.w, accA.w);
            accB.x = fmaf(p, v1.x, accB.x); accB.y = fmaf(p, v1.y, accB.y);
            accB.z = fmaf(p, v1.z, accB.z); accB.w = fmaf(p, v1.w, accB.w);
        }
        __syncthreads();
    }

    float inv = 1.f / run_sum;
    float* Ob = O + ((size_t)b * S_) * H_ + n * HD_ + (size_t)(q0 + q) * H_ + u * 8;
    accA.x *= inv; accA.y *= inv; accA.z *= inv; accA.w *= inv;
    accB.x *= inv; accB.y *= inv; accB.z *= inv; accB.w *= inv;
    *(float4*)&Ob[0] = accA;
    *(float4*)&Ob[4] = accB;
}

// ---------------------------------------------------------------------------
// Launch
// ---------------------------------------------------------------------------
extern "C" void kernel_launch(void* const* d_in, const int* in_sizes, int n_in,
                              void* d_out, int out_size)
{
    const float* x   = (const float*)d_in[0];
    const float* Wq  = (const float*)d_in[1];
    const float* bq  = (const float*)d_in[2];
    const float* Wk  = (const float*)d_in[3];
    const float* bk  = (const float*)d_in[4];
    const float* Wv  = (const float*)d_in[5];
    const float* bv  = (const float*)d_in[6];
    const float* Wo  = (const float*)d_in[7];
    const float* bo  = (const float*)d_in[8];
    const float* rel = (const float*)d_in[9];
    float* out = (float*)d_out;

    float *pQ, *pK, *pV, *pA;
    __nv_bfloat16 *xh, *xl, *wqh, *wql, *wkh, *wkl, *wvh, *wvl, *woh, *wol, *ah, *al;
    cudaGetSymbolAddress((void**)&pQ, g_Q);
    cudaGetSymbolAddress((void**)&pK, g_K);
    cudaGetSymbolAddress((void**)&pV, g_V);
    cudaGetSymbolAddress((void**)&pA, g_ATT);
    cudaGetSymbolAddress((void**)&xh, g_xh);
    cudaGetSymbolAddress((void**)&xl, g_xl);
    cudaGetSymbolAddress((void**)&wqh, g_Wqh);
    cudaGetSymbolAddress((void**)&wql, g_Wql);
    cudaGetSymbolAddress((void**)&wkh, g_Wkh);
    cudaGetSymbolAddress((void**)&wkl, g_Wkl);
    cudaGetSymbolAddress((void**)&wvh, g_Wvh);
    cudaGetSymbolAddress((void**)&wvl, g_Wvl);
    cudaGetSymbolAddress((void**)&woh, g_Woh);
    cudaGetSymbolAddress((void**)&wol, g_Wol);
    cudaGetSymbolAddress((void**)&ah, g_ah);
    cudaGetSymbolAddress((void**)&al, g_al);

    const int nx4 = MTOT * H_ / 4;   // 1M float4
    const int nw4 = H_ * H_ / 4;     // 256K float4

    split_kernel<<<(nx4 + 255) / 256, 256>>>((const float4*)x, (uint2*)xh, (uint2*)xl, nx4);
    split_kernel<<<(nw4 + 255) / 256, 256>>>((const float4*)Wq, (uint2*)wqh, (uint2*)wql, nw4);
    split_kernel<<<(nw4 + 255) / 256, 256>>>((const float4*)Wk, (uint2*)wkh, (uint2*)wkl, nw4);
    split_kernel<<<(nw4 + 255) / 256, 256>>>((const float4*)Wv, (uint2*)wvh, (uint2*)wvl, nw4);
    split_kernel<<<(nw4 + 255) / 256, 256>>>((const float4*)Wo, (uint2*)woh, (uint2*)wol, nw4);

    dim3 gemm_grid(H_ / 128, MTOT / 128);   // (8, 32)
    gemm_mma<<<gemm_grid, 256>>>(xh, xl, wqh, wql, bq, pQ);
    gemm_mma<<<gemm_grid, 256>>>(xh, xl, wkh, wkl, bk, pK);
    gemm_mma<<<gemm_grid, 256>>>(xh, xl, wvh, wvl, bv, pV);

    dim3 attn_grid(S_ / TQ, NH_, B_);
    attn_kernel<<<attn_grid, 128>>>(pQ, pK, pV, rel, pA);

    split_kernel<<<(nx4 + 255) / 256, 256>>>((const float4*)pA, (uint2*)ah, (uint2*)al, nx4);
    gemm_mma<<<gemm_grid, 256>>>(ah, al, woh, wol, bo, out);
}

// round 6
// speedup vs baseline: 4.7786x; 2.3489x over previous
#include <cuda_runtime.h>
#include <cuda_bf16.h>
#include <math.h>
#include <stdint.h>

// ---------------------------------------------------------------------------
// Problem constants
// ---------------------------------------------------------------------------
#define B_   4
#define S_   1024
#define H_   1024
#define NH_  16
#define HD_  64
#define NREL 257   // 2*128+1
#define MTOT (B_ * S_)   // 4096

// ---------------------------------------------------------------------------
// Scratch (device globals — no cudaMalloc allowed)
// ---------------------------------------------------------------------------
__device__ float g_Q[MTOT * H_];
__device__ float g_K[MTOT * H_];
__device__ float g_V[MTOT * H_];
__device__ float g_ATT[MTOT * H_];

__device__ __nv_bfloat16 g_xh[MTOT * H_];
__device__ __nv_bfloat16 g_xl[MTOT * H_];
__device__ __nv_bfloat16 g_Wqh[H_ * H_];
__device__ __nv_bfloat16 g_Wql[H_ * H_];
__device__ __nv_bfloat16 g_Wkh[H_ * H_];
__device__ __nv_bfloat16 g_Wkl[H_ * H_];
__device__ __nv_bfloat16 g_Wvh[H_ * H_];
__device__ __nv_bfloat16 g_Wvl[H_ * H_];
__device__ __nv_bfloat16 g_Woh[H_ * H_];
__device__ __nv_bfloat16 g_Wol[H_ * H_];
__device__ __nv_bfloat16 g_ah[MTOT * H_];
__device__ __nv_bfloat16 g_al[MTOT * H_];

// ---------------------------------------------------------------------------
// Split fp32 -> (bf16 hi, bf16 lo) elementwise
// ---------------------------------------------------------------------------
__global__ __launch_bounds__(256) void split_kernel(
    const float4* __restrict__ src, uint2* __restrict__ hi, uint2* __restrict__ lo, int n4)
{
    int i = blockIdx.x * blockDim.x + threadIdx.x;
    if (i >= n4) return;
    float4 v = src[i];
    __nv_bfloat16 h0 = __float2bfloat16(v.x);
    __nv_bfloat16 h1 = __float2bfloat16(v.y);
    __nv_bfloat16 h2 = __float2bfloat16(v.z);
    __nv_bfloat16 h3 = __float2bfloat16(v.w);
    __nv_bfloat16 l0 = __float2bfloat16(v.x - __bfloat162float(h0));
    __nv_bfloat16 l1 = __float2bfloat16(v.y - __bfloat162float(h1));
    __nv_bfloat16 l2 = __float2bfloat16(v.z - __bfloat162float(h2));
    __nv_bfloat16 l3 = __float2bfloat16(v.w - __bfloat162float(h3));
    uint2 hw, lw;
    hw.x = (uint32_t)__bfloat16_as_ushort(h0) | ((uint32_t)__bfloat16_as_ushort(h1) << 16);
    hw.y = (uint32_t)__bfloat16_as_ushort(h2) | ((uint32_t)__bfloat16_as_ushort(h3) << 16);
    lw.x = (uint32_t)__bfloat16_as_ushort(l0) | ((uint32_t)__bfloat16_as_ushort(l1) << 16);
    lw.y = (uint32_t)__bfloat16_as_ushort(l2) | ((uint32_t)__bfloat16_as_ushort(l3) << 16);
    hi[i] = hw;
    lo[i] = lw;
}

// ---------------------------------------------------------------------------
// mma.sync helpers
// ---------------------------------------------------------------------------
__device__ __forceinline__ void mma16816(float* c,
    uint32_t a0, uint32_t a1, uint32_t a2, uint32_t a3, uint32_t b0, uint32_t b1)
{
    asm volatile(
        "mma.sync.aligned.m16n8k16.row.col.f32.bf16.bf16.f32 "
        "{%0,%1,%2,%3}, {%4,%5,%6,%7}, {%8,%9}, {%0,%1,%2,%3};\n"
        : "+f"(c[0]), "+f"(c[1]), "+f"(c[2]), "+f"(c[3])
        : "r"(a0), "r"(a1), "r"(a2), "r"(a3), "r"(b0), "r"(b1));
}

// Swizzled offset within a tile of 64-byte rows (32 bf16). For gemm_mma.
__device__ __forceinline__ uint32_t swz(int row, int kbyte)
{
    return (uint32_t)(row * 64 + ((((kbyte >> 4) ^ ((row >> 1) & 3)) << 4) | (kbyte & 15)));
}
__device__ __forceinline__ uint32_t lds32(const uint8_t* base, int row, int kbyte)
{
    return *(const uint32_t*)(base + swz(row, kbyte));
}

// Swizzled offset within a tile of 128-byte rows (64 bf16). For attention.
__device__ __forceinline__ uint32_t swzb(int row, int kbyte)
{
    return (uint32_t)(row * 128 + ((((kbyte >> 4) ^ (row & 7)) << 4) | (kbyte & 15)));
}
__device__ __forceinline__ uint32_t lds32b(const uint8_t* base, int row, int kbyte)
{
    return *(const uint32_t*)(base + swzb(row, kbyte));
}

// Pack two fp32 into bf16x2 hi word + residual lo word.
__device__ __forceinline__ void pack_hl(float x0, float x1, uint32_t& h, uint32_t& l)
{
    asm("cvt.rn.bf16x2.f32 %0, %1, %2;" : "=r"(h) : "f"(x1), "f"(x0));
    float f0 = __uint_as_float(h << 16);
    float f1 = __uint_as_float(h & 0xffff0000u);
    float r0 = x0 - f0, r1 = x1 - f1;
    asm("cvt.rn.bf16x2.f32 %0, %1, %2;" : "=r"(l) : "f"(r1), "f"(r0));
}

// ---------------------------------------------------------------------------
// Tensor-core GEMM: C[M,1024] = A[M,1024] @ B[1024,1024]^T + bias
// ---------------------------------------------------------------------------
__global__ __launch_bounds__(256) void gemm_mma(
    const __nv_bfloat16* __restrict__ Ahg, const __nv_bfloat16* __restrict__ Alg,
    const __nv_bfloat16* __restrict__ Bhg, const __nv_bfloat16* __restrict__ Blg,
    const float* __restrict__ bias, float* __restrict__ C)
{
    __shared__ __align__(16) uint8_t sAh[128 * 64];
    __shared__ __align__(16) uint8_t sAl[128 * 64];
    __shared__ __align__(16) uint8_t sBh[128 * 64];
    __shared__ __align__(16) uint8_t sBl[128 * 64];

    const int tid = threadIdx.x;
    const int lane = tid & 31;
    const int wid = tid >> 5;
    const int warp_m = wid >> 1;
    const int warp_n = wid & 1;
    const int m0 = blockIdx.y * 128;
    const int n0 = blockIdx.x * 128;
    const int g = lane >> 2;
    const int t4 = lane & 3;

    float acc[2][8][4];
#pragma unroll
    for (int mt = 0; mt < 2; mt++)
#pragma unroll
        for (int nt = 0; nt < 8; nt++)
#pragma unroll
            for (int i = 0; i < 4; i++) acc[mt][nt][i] = 0.f;

#pragma unroll 1
    for (int kt = 0; kt < 32; kt++) {
#pragma unroll
        for (int l = 0; l < 2; l++) {
            int s = tid + l * 256;
            int row = s >> 2;
            int seg = s & 3;
            uint32_t soff = (uint32_t)(row * 64 + ((seg ^ ((row >> 1) & 3)) << 4));
            size_t ga = (size_t)(m0 + row) * H_ + kt * 32 + seg * 8;
            size_t gb = (size_t)(n0 + row) * H_ + kt * 32 + seg * 8;
            *(uint4*)(sAh + soff) = *(const uint4*)(Ahg + ga);
            *(uint4*)(sAl + soff) = *(const uint4*)(Alg + ga);
            *(uint4*)(sBh + soff) = *(const uint4*)(Bhg + gb);
            *(uint4*)(sBl + soff) = *(const uint4*)(Blg + gb);
        }
        __syncthreads();

#pragma unroll
        for (int kk = 0; kk < 64; kk += 32) {
            const int kb = kk + t4 * 4;
            uint32_t ah[2][4], al[2][4];
#pragma unroll
            for (int mt = 0; mt < 2; mt++) {
                int r = warp_m * 32 + mt * 16 + g;
                ah[mt][0] = lds32(sAh, r, kb);
                ah[mt][1] = lds32(sAh, r + 8, kb);
                ah[mt][2] = lds32(sAh, r, kb + 16);
                ah[mt][3] = lds32(sAh, r + 8, kb + 16);
                al[mt][0] = lds32(sAl, r, kb);
                al[mt][1] = lds32(sAl, r + 8, kb);
                al[mt][2] = lds32(sAl, r, kb + 16);
                al[mt][3] = lds32(sAl, r + 8, kb + 16);
            }
#pragma unroll
            for (int nt = 0; nt < 8; nt++) {
                int n = warp_n * 64 + nt * 8 + g;
                uint32_t bh0 = lds32(sBh, n, kb);
                uint32_t bh1 = lds32(sBh, n, kb + 16);
                uint32_t bl0 = lds32(sBl, n, kb);
                uint32_t bl1 = lds32(sBl, n, kb + 16);
#pragma unroll
                for (int mt = 0; mt < 2; mt++) {
                    mma16816(acc[mt][nt], ah[mt][0], ah[mt][1], ah[mt][2], ah[mt][3], bh0, bh1);
                    mma16816(acc[mt][nt], ah[mt][0], ah[mt][1], ah[mt][2], ah[mt][3], bl0, bl1);
                    mma16816(acc[mt][nt], al[mt][0], al[mt][1], al[mt][2], al[mt][3], bh0, bh1);
                }
            }
        }
        __syncthreads();
    }

#pragma unroll
    for (int mt = 0; mt < 2; mt++) {
        int row = m0 + warp_m * 32 + mt * 16 + g;
#pragma unroll
        for (int nt = 0; nt < 8; nt++) {
            int col = n0 + warp_n * 64 + nt * 8 + t4 * 2;
            float2 bv = *(const float2*)&bias[col];
            float2 o0, o1;
            o0.x = acc[mt][nt][0] + bv.x; o0.y = acc[mt][nt][1] + bv.y;
            o1.x = acc[mt][nt][2] + bv.x; o1.y = acc[mt][nt][3] + bv.y;
            *(float2*)&C[(size_t)row * H_ + col] = o0;
            *(float2*)&C[(size_t)(row + 8) * H_ + col] = o1;
        }
    }
}

// ---------------------------------------------------------------------------
// Tensor-core flash attention with relative-position bias.
// Block: 128 threads / 4 warps; q-tile 64 (16 rows per warp); k-tiles of 64.
// QK^T and PV via bf16 hi/lo split mma (3 passes each), fp32 softmax.
// ---------------------------------------------------------------------------
#define ASM_QH 0
#define ASM_QL 8192
#define ASM_KH 16384
#define ASM_KL 24576
#define ASM_VH 32768
#define ASM_VL 40960
#define ASM_QF 49152                 // float[64][68] = 17408 B
#define ASM_PT (49152 + 17408)       // float[64][257] = 65792 B
#define ATTN_SMEM (49152 + 17408 + 65792)

__global__ __launch_bounds__(128) void attn_mma(
    const float* __restrict__ Q, const float* __restrict__ K,
    const float* __restrict__ V, const float* __restrict__ rel_emb,
    float* __restrict__ O)
{
    extern __shared__ __align__(16) uint8_t dynsm[];
    uint8_t* sQh = dynsm + ASM_QH;
    uint8_t* sQl = dynsm + ASM_QL;
    uint8_t* sKh = dynsm + ASM_KH;
    uint8_t* sKl = dynsm + ASM_KL;
    uint8_t* sVh = dynsm + ASM_VH;
    uint8_t* sVl = dynsm + ASM_VL;
    float*   Qf  = (float*)(dynsm + ASM_QF);
    float*   Pt  = (float*)(dynsm + ASM_PT);

    const int b  = blockIdx.z;
    const int n  = blockIdx.y;
    const int q0 = blockIdx.x * 64;
    const int tid = threadIdx.x;
    const int lane = tid & 31;
    const int w = tid >> 5;
    const int g = lane >> 2;
    const int t4 = lane & 3;

    const float* Qb = Q + ((size_t)b * S_ + q0) * H_ + n * HD_;
    const float* Kb = K + ((size_t)b * S_) * H_ + n * HD_;
    const float* Vb = V + ((size_t)b * S_) * H_ + n * HD_;

    // Phase 0: load Q tile -> Qf (fp32) + Qh/Ql (bf16 swizzled)
    for (int idx = tid; idx < 1024; idx += 128) {
        int row = idx >> 4, c4 = idx & 15;
        float4 v = *(const float4*)&Qb[(size_t)row * H_ + c4 * 4];
        *(float4*)&Qf[row * 68 + c4 * 4] = v;
        __nv_bfloat16 h0 = __float2bfloat16(v.x);
        __nv_bfloat16 h1 = __float2bfloat16(v.y);
        __nv_bfloat16 h2 = __float2bfloat16(v.z);
        __nv_bfloat16 h3 = __float2bfloat16(v.w);
        uint2 hw, lw;
        hw.x = (uint32_t)__bfloat16_as_ushort(h0) | ((uint32_t)__bfloat16_as_ushort(h1) << 16);
        hw.y = (uint32_t)__bfloat16_as_ushort(h2) | ((uint32_t)__bfloat16_as_ushort(h3) << 16);
        __nv_bfloat16 l0 = __float2bfloat16(v.x - __bfloat162float(h0));
        __nv_bfloat16 l1 = __float2bfloat16(v.y - __bfloat162float(h1));
        __nv_bfloat16 l2 = __float2bfloat16(v.z - __bfloat162float(h2));
        __nv_bfloat16 l3 = __float2bfloat16(v.w - __bfloat162float(h3));
        lw.x = (uint32_t)__bfloat16_as_ushort(l0) | ((uint32_t)__bfloat16_as_ushort(l1) << 16);
        lw.y = (uint32_t)__bfloat16_as_ushort(l2) | ((uint32_t)__bfloat16_as_ushort(l3) << 16);
        uint32_t off = swzb(row, c4 * 8);
        *(uint2*)(sQh + off) = hw;
        *(uint2*)(sQl + off) = lw;
    }
    __syncthreads();

    // Phase 1: P table Pt[q][r] = Q[q] . rel_emb[r]  (fp32 exact)
    {
        const int qsel = tid & 63;
        float4 Qr[16];
#pragma unroll
        for (int i = 0; i < 16; i++) Qr[i] = *(const float4*)&Qf[qsel * 68 + i * 4];
        for (int r = (tid >> 6); r < NREL; r += 2) {
            const float4* e = (const float4*)(rel_emb + r * HD_);
            float s = 0.f;
#pragma unroll
            for (int i = 0; i < 16; i++) {
                float4 ev = __ldg(&e[i]);
                s = fmaf(Qr[i].x, ev.x, s); s = fmaf(Qr[i].y, ev.y, s);
                s = fmaf(Qr[i].z, ev.z, s); s = fmaf(Qr[i].w, ev.w, s);
            }
            Pt[qsel * NREL + r] = s;
        }
    }

    // Resident Q A-frags (rows 16w+g, 16w+g+8)
    uint32_t qah[4][4], qal[4][4];
    {
        int r = 16 * w + g;
#pragma unroll
        for (int kb = 0; kb < 4; kb++) {
            int kbase = kb * 32 + t4 * 4;
            qah[kb][0] = lds32b(sQh, r, kbase);
            qah[kb][1] = lds32b(sQh, r + 8, kbase);
            qah[kb][2] = lds32b(sQh, r, kbase + 16);
            qah[kb][3] = lds32b(sQh, r + 8, kbase + 16);
            qal[kb][0] = lds32b(sQl, r, kbase);
            qal[kb][1] = lds32b(sQl, r + 8, kbase);
            qal[kb][2] = lds32b(sQl, r, kbase + 16);
            qal[kb][3] = lds32b(sQl, r + 8, kbase + 16);
        }
    }

    float oacc[8][4];
#pragma unroll
    for (int j = 0; j < 8; j++)
#pragma unroll
        for (int i = 0; i < 4; i++) oacc[j][i] = 0.f;
    float rmax0 = -INFINITY, rmax1 = -INFINITY;
    float rsum0 = 0.f, rsum1 = 0.f;

    const int qg0 = q0 + 16 * w + g;
    const int ql0 = 16 * w + g;

#pragma unroll 1
    for (int kt = 0; kt < 16; kt++) {
        const int k0 = kt * 64;
        __syncthreads();
        // Load K tile (bf16 hi/lo, row-major) and V tile (transposed)
        for (int idx = tid; idx < 1024; idx += 128) {
            int row = idx >> 4, c4 = idx & 15;
            float4 v = *(const float4*)&Kb[(size_t)(k0 + row) * H_ + c4 * 4];
            __nv_bfloat16 h0 = __float2bfloat16(v.x);
            __nv_bfloat16 h1 = __float2bfloat16(v.y);
            __nv_bfloat16 h2 = __float2bfloat16(v.z);
            __nv_bfloat16 h3 = __float2bfloat16(v.w);
            uint2 hw, lw;
            hw.x = (uint32_t)__bfloat16_as_ushort(h0) | ((uint32_t)__bfloat16_as_ushort(h1) << 16);
            hw.y = (uint32_t)__bfloat16_as_ushort(h2) | ((uint32_t)__bfloat16_as_ushort(h3) << 16);
            __nv_bfloat16 l0 = __float2bfloat16(v.x - __bfloat162float(h0));
            __nv_bfloat16 l1 = __float2bfloat16(v.y - __bfloat162float(h1));
            __nv_bfloat16 l2 = __float2bfloat16(v.z - __bfloat162float(h2));
            __nv_bfloat16 l3 = __float2bfloat16(v.w - __bfloat162float(h3));
            lw.x = (uint32_t)__bfloat16_as_ushort(l0) | ((uint32_t)__bfloat16_as_ushort(l1) << 16);
            lw.y = (uint32_t)__bfloat16_as_ushort(l2) | ((uint32_t)__bfloat16_as_ushort(l3) << 16);
            uint32_t off = swzb(row, c4 * 8);
            *(uint2*)(sKh + off) = hw;
            *(uint2*)(sKl + off) = lw;

            float4 vv = *(const float4*)&Vb[(size_t)(k0 + row) * H_ + c4 * 4];
            float ve[4] = {vv.x, vv.y, vv.z, vv.w};
#pragma unroll
            for (int i = 0; i < 4; i++) {
                int d = c4 * 4 + i;
                __nv_bfloat16 vh = __float2bfloat16(ve[i]);
                __nv_bfloat16 vl = __float2bfloat16(ve[i] - __bfloat162float(vh));
                uint32_t voff = swzb(d, row * 2);
                *(uint16_t*)(sVh + voff) = __bfloat16_as_ushort(vh);
                *(uint16_t*)(sVl + voff) = __bfloat16_as_ushort(vl);
            }
        }
        __syncthreads();

        // QK^T: scores 16x64 per warp (8 n-frags)
        float sc[8][4];
#pragma unroll
        for (int j = 0; j < 8; j++)
#pragma unroll
            for (int i = 0; i < 4; i++) sc[j][i] = 0.f;
#pragma unroll
        for (int kb = 0; kb < 4; kb++) {
            int kbase = kb * 32 + t4 * 4;
#pragma unroll
            for (int j = 0; j < 8; j++) {
                int krow = 8 * j + g;
                uint32_t bh0 = lds32b(sKh, krow, kbase);
                uint32_t bh1 = lds32b(sKh, krow, kbase + 16);
                uint32_t bl0 = lds32b(sKl, krow, kbase);
                uint32_t bl1 = lds32b(sKl, krow, kbase + 16);
                mma16816(sc[j], qah[kb][0], qah[kb][1], qah[kb][2], qah[kb][3], bh0, bh1);
                mma16816(sc[j], qah[kb][0], qah[kb][1], qah[kb][2], qah[kb][3], bl0, bl1);
                mma16816(sc[j], qal[kb][0], qal[kb][1], qal[kb][2], qal[kb][3], bh0, bh1);
            }
        }

        // Bias + scale
#pragma unroll
        for (int j = 0; j < 8; j++) {
            int col = k0 + 8 * j + 2 * t4;
            int r00 = min(128, max(-128, col     - qg0)) + 128;
            int r01 = min(128, max(-128, col + 1 - qg0)) + 128;
            int r10 = min(128, max(-128, col     - qg0 - 8)) + 128;
            int r11 = min(128, max(-128, col + 1 - qg0 - 8)) + 128;
            sc[j][0] = (sc[j][0] + Pt[ql0 * NREL + r00]) * 0.125f;
            sc[j][1] = (sc[j][1] + Pt[ql0 * NREL + r01]) * 0.125f;
            sc[j][2] = (sc[j][2] + Pt[(ql0 + 8) * NREL + r10]) * 0.125f;
            sc[j][3] = (sc[j][3] + Pt[(ql0 + 8) * NREL + r11]) * 0.125f;
        }

        // Online softmax (rows g and g+8)
        float m0 = -INFINITY, m1 = -INFINITY;
#pragma unroll
        for (int j = 0; j < 8; j++) {
            m0 = fmaxf(m0, fmaxf(sc[j][0], sc[j][1]));
            m1 = fmaxf(m1, fmaxf(sc[j][2], sc[j][3]));
        }
        m0 = fmaxf(m0, __shfl_xor_sync(0xffffffffu, m0, 1, 4));
        m0 = fmaxf(m0, __shfl_xor_sync(0xffffffffu, m0, 2, 4));
        m1 = fmaxf(m1, __shfl_xor_sync(0xffffffffu, m1, 1, 4));
        m1 = fmaxf(m1, __shfl_xor_sync(0xffffffffu, m1, 2, 4));

        float nm0 = fmaxf(rmax0, m0);
        float nm1 = fmaxf(rmax1, m1);
        float esc0 = __expf(rmax0 - nm0);
        float esc1 = __expf(rmax1 - nm1);
        rmax0 = nm0; rmax1 = nm1;

        float s0 = 0.f, s1 = 0.f;
#pragma unroll
        for (int j = 0; j < 8; j++) {
            sc[j][0] = __expf(sc[j][0] - nm0);
            sc[j][1] = __expf(sc[j][1] - nm0);
            sc[j][2] = __expf(sc[j][2] - nm1);
            sc[j][3] = __expf(sc[j][3] - nm1);
            s0 += sc[j][0] + sc[j][1];
            s1 += sc[j][2] + sc[j][3];
        }
        s0 += __shfl_xor_sync(0xffffffffu, s0, 1, 4);
        s0 += __shfl_xor_sync(0xffffffffu, s0, 2, 4);
        s1 += __shfl_xor_sync(0xffffffffu, s1, 1, 4);
        s1 += __shfl_xor_sync(0xffffffffu, s1, 2, 4);
        rsum0 = rsum0 * esc0 + s0;
        rsum1 = rsum1 * esc1 + s1;

#pragma unroll
        for (int j = 0; j < 8; j++) {
            oacc[j][0] *= esc0; oacc[j][1] *= esc0;
            oacc[j][2] *= esc1; oacc[j][3] *= esc1;
        }

        // PV: A = softmax probs (from sc frags), B = V^T
#pragma unroll
        for (int kb = 0; kb < 4; kb++) {
            uint32_t ah0, ah1, ah2, ah3, al0, al1, al2, al3;
            pack_hl(sc[2 * kb][0], sc[2 * kb][1], ah0, al0);
            pack_hl(sc[2 * kb][2], sc[2 * kb][3], ah1, al1);
            pack_hl(sc[2 * kb + 1][0], sc[2 * kb + 1][1], ah2, al2);
            pack_hl(sc[2 * kb + 1][2], sc[2 * kb + 1][3], ah3, al3);
            int kbase = kb * 32 + t4 * 4;
#pragma unroll
            for (int j = 0; j < 8; j++) {
                int vrow = 8 * j + g;
                uint32_t bh0 = lds32b(sVh, vrow, kbase);
                uint32_t bh1 = lds32b(sVh, vrow, kbase + 16);
                uint32_t bl0 = lds32b(sVl, vrow, kbase);
                uint32_t bl1 = lds32b(sVl, vrow, kbase + 16);
                mma16816(oacc[j], ah0, ah1, ah2, ah3, bh0, bh1);
                mma16816(oacc[j], ah0, ah1, ah2, ah3, bl0, bl1);
                mma16816(oacc[j], al0, al1, al2, al3, bh0, bh1);
            }
        }
    }

    // Epilogue
    float inv0 = 1.f / rsum0;
    float inv1 = 1.f / rsum1;
    float* Ob = O + ((size_t)b * S_ + q0) * H_ + n * HD_;
#pragma unroll
    for (int j = 0; j < 8; j++) {
        int col = 8 * j + 2 * t4;
        float2 o0, o1;
        o0.x = oacc[j][0] * inv0; o0.y = oacc[j][1] * inv0;
        o1.x = oacc[j][2] * inv1; o1.y = oacc[j][3] * inv1;
        *(float2*)&Ob[(size_t)(16 * w + g) * H_ + col] = o0;
        *(float2*)&Ob[(size_t)(16 * w + g + 8) * H_ + col] = o1;
    }
}

// ---------------------------------------------------------------------------
// Launch
// ---------------------------------------------------------------------------
extern "C" void kernel_launch(void* const* d_in, const int* in_sizes, int n_in,
                              void* d_out, int out_size)
{
    const float* x   = (const float*)d_in[0];
    const float* Wq  = (const float*)d_in[1];
    const float* bq  = (const float*)d_in[2];
    const float* Wk  = (const float*)d_in[3];
    const float* bk  = (const float*)d_in[4];
    const float* Wv  = (const float*)d_in[5];
    const float* bv  = (const float*)d_in[6];
    const float* Wo  = (const float*)d_in[7];
    const float* bo  = (const float*)d_in[8];
    const float* rel = (const float*)d_in[9];
    float* out = (float*)d_out;

    float *pQ, *pK, *pV, *pA;
    __nv_bfloat16 *xh, *xl, *wqh, *wql, *wkh, *wkl, *wvh, *wvl, *woh, *wol, *ah, *al;
    cudaGetSymbolAddress((void**)&pQ, g_Q);
    cudaGetSymbolAddress((void**)&pK, g_K);
    cudaGetSymbolAddress((void**)&pV, g_V);
    cudaGetSymbolAddress((void**)&pA, g_ATT);
    cudaGetSymbolAddress((void**)&xh, g_xh);
    cudaGetSymbolAddress((void**)&xl, g_xl);
    cudaGetSymbolAddress((void**)&wqh, g_Wqh);
    cudaGetSymbolAddress((void**)&wql, g_Wql);
    cudaGetSymbolAddress((void**)&wkh, g_Wkh);
    cudaGetSymbolAddress((void**)&wkl, g_Wkl);
    cudaGetSymbolAddress((void**)&wvh, g_Wvh);
    cudaGetSymbolAddress((void**)&wvl, g_Wvl);
    cudaGetSymbolAddress((void**)&woh, g_Woh);
    cudaGetSymbolAddress((void**)&wol, g_Wol);
    cudaGetSymbolAddress((void**)&ah, g_ah);
    cudaGetSymbolAddress((void**)&al, g_al);

    cudaFuncSetAttribute(attn_mma, cudaFuncAttributeMaxDynamicSharedMemorySize,
                         ATTN_SMEM);

    const int nx4 = MTOT * H_ / 4;
    const int nw4 = H_ * H_ / 4;

    split_kernel<<<(nx4 + 255) / 256, 256>>>((const float4*)x, (uint2*)xh, (uint2*)xl, nx4);
    split_kernel<<<(nw4 + 255) / 256, 256>>>((const float4*)Wq, (uint2*)wqh, (uint2*)wql, nw4);
    split_kernel<<<(nw4 + 255) / 256, 256>>>((const float4*)Wk, (uint2*)wkh, (uint2*)wkl, nw4);
    split_kernel<<<(nw4 + 255) / 256, 256>>>((const float4*)Wv, (uint2*)wvh, (uint2*)wvl, nw4);
    split_kernel<<<(nw4 + 255) / 256, 256>>>((const float4*)Wo, (uint2*)woh, (uint2*)wol, nw4);

    dim3 gemm_grid(H_ / 128, MTOT / 128);
    gemm_mma<<<gemm_grid, 256>>>(xh, xl, wqh, wql, bq, pQ);
    gemm_mma<<<gemm_grid, 256>>>(xh, xl, wkh, wkl, bk, pK);
    gemm_mma<<<gemm_grid, 256>>>(xh, xl, wvh, wvl, bv, pV);

    dim3 attn_grid(S_ / 64, NH_, B_);
    attn_mma<<<attn_grid, 128, ATTN_SMEM>>>(pQ, pK, pV, rel, pA);

    split_kernel<<<(nx4 + 255) / 256, 256>>>((const float4*)pA, (uint2*)ah, (uint2*)al, nx4);
    gemm_mma<<<gemm_grid, 256>>>(ah, al, woh, wol, bo, out);
}

// round 7
// speedup vs baseline: 7.7385x; 1.6194x over previous
#include <cuda_runtime.h>
#include <cuda_bf16.h>
#include <math.h>
#include <stdint.h>

// ---------------------------------------------------------------------------
// Problem constants
// ---------------------------------------------------------------------------
#define B_   4
#define S_   1024
#define H_   1024
#define NH_  16
#define HD_  64
#define NREL 257   // 2*128+1
#define MTOT (B_ * S_)   // 4096

// ---------------------------------------------------------------------------
// Scratch (device globals — no cudaMalloc allowed)
// ---------------------------------------------------------------------------
__device__ float g_Q[MTOT * H_];
__device__ float g_K[MTOT * H_];
__device__ float g_V[MTOT * H_];
__device__ float g_ATT[MTOT * H_];

__device__ __nv_bfloat16 g_xh[MTOT * H_];
__device__ __nv_bfloat16 g_xl[MTOT * H_];
__device__ __nv_bfloat16 g_Wqh[H_ * H_];
__device__ __nv_bfloat16 g_Wql[H_ * H_];
__device__ __nv_bfloat16 g_Wkh[H_ * H_];
__device__ __nv_bfloat16 g_Wkl[H_ * H_];
__device__ __nv_bfloat16 g_Wvh[H_ * H_];
__device__ __nv_bfloat16 g_Wvl[H_ * H_];
__device__ __nv_bfloat16 g_Woh[H_ * H_];
__device__ __nv_bfloat16 g_Wol[H_ * H_];
__device__ __nv_bfloat16 g_ah[MTOT * H_];
__device__ __nv_bfloat16 g_al[MTOT * H_];

__device__ __nv_bfloat16 g_Qh[MTOT * H_];
__device__ __nv_bfloat16 g_Ql[MTOT * H_];
__device__ __nv_bfloat16 g_Kh[MTOT * H_];
__device__ __nv_bfloat16 g_Kl[MTOT * H_];
__device__ __nv_bfloat16 g_Vth[MTOT * H_];   // [b][head][d][s]
__device__ __nv_bfloat16 g_Vtl[MTOT * H_];

// ---------------------------------------------------------------------------
// Helpers
// ---------------------------------------------------------------------------
__device__ __forceinline__ uint32_t smem_u32(const void* p) {
    uint32_t a;
    asm("{ .reg .u64 t; cvta.to.shared.u64 t, %1; cvt.u32.u64 %0, t; }"
        : "=r"(a) : "l"(p));
    return a;
}

#define CP16(dst_u32, src_ptr) \
    asm volatile("cp.async.cg.shared.global [%0], [%1], 16;" \
        :: "r"(dst_u32), "l"(src_ptr))

__device__ __forceinline__ void mma16816(float* c,
    uint32_t a0, uint32_t a1, uint32_t a2, uint32_t a3, uint32_t b0, uint32_t b1)
{
    asm volatile(
        "mma.sync.aligned.m16n8k16.row.col.f32.bf16.bf16.f32 "
        "{%0,%1,%2,%3}, {%4,%5,%6,%7}, {%8,%9}, {%0,%1,%2,%3};\n"
        : "+f"(c[0]), "+f"(c[1]), "+f"(c[2]), "+f"(c[3])
        : "r"(a0), "r"(a1), "r"(a2), "r"(a3), "r"(b0), "r"(b1));
}

// Swizzled offset within a tile of 64-byte rows (32 bf16). For gemm_mma.
__device__ __forceinline__ uint32_t swz(int row, int kbyte)
{
    return (uint32_t)(row * 64 + ((((kbyte >> 4) ^ ((row >> 1) & 3)) << 4) | (kbyte & 15)));
}
__device__ __forceinline__ uint32_t lds32(const uint8_t* base, int row, int kbyte)
{
    return *(const uint32_t*)(base + swz(row, kbyte));
}

// Swizzled offset within a tile of 128-byte rows (64 bf16). For attention.
__device__ __forceinline__ uint32_t swzb(int row, int kbyte)
{
    return (uint32_t)(row * 128 + ((((kbyte >> 4) ^ (row & 7)) << 4) | (kbyte & 15)));
}
__device__ __forceinline__ uint32_t lds32b(const uint8_t* base, int row, int kbyte)
{
    return *(const uint32_t*)(base + swzb(row, kbyte));
}

// Pack two fp32 into bf16x2 hi word + residual lo word.
__device__ __forceinline__ void pack_hl(float x0, float x1, uint32_t& h, uint32_t& l)
{
    asm("cvt.rn.bf16x2.f32 %0, %1, %2;" : "=r"(h) : "f"(x1), "f"(x0));
    float f0 = __uint_as_float(h << 16);
    float f1 = __uint_as_float(h & 0xffff0000u);
    float r0 = x0 - f0, r1 = x1 - f1;
    asm("cvt.rn.bf16x2.f32 %0, %1, %2;" : "=r"(l) : "f"(r1), "f"(r0));
}

// ---------------------------------------------------------------------------
// Split fp32 -> (bf16 hi, bf16 lo) elementwise
// ---------------------------------------------------------------------------
__global__ __launch_bounds__(256) void split_kernel(
    const float4* __restrict__ src, uint2* __restrict__ hi, uint2* __restrict__ lo, int n4)
{
    int i = blockIdx.x * blockDim.x + threadIdx.x;
    if (i >= n4) return;
    float4 v = src[i];
    __nv_bfloat16 h0 = __float2bfloat16(v.x);
    __nv_bfloat16 h1 = __float2bfloat16(v.y);
    __nv_bfloat16 h2 = __float2bfloat16(v.z);
    __nv_bfloat16 h3 = __float2bfloat16(v.w);
    __nv_bfloat16 l0 = __float2bfloat16(v.x - __bfloat162float(h0));
    __nv_bfloat16 l1 = __float2bfloat16(v.y - __bfloat162float(h1));
    __nv_bfloat16 l2 = __float2bfloat16(v.z - __bfloat162float(h2));
    __nv_bfloat16 l3 = __float2bfloat16(v.w - __bfloat162float(h3));
    uint2 hw, lw;
    hw.x = (uint32_t)__bfloat16_as_ushort(h0) | ((uint32_t)__bfloat16_as_ushort(h1) << 16);
    hw.y = (uint32_t)__bfloat16_as_ushort(h2) | ((uint32_t)__bfloat16_as_ushort(h3) << 16);
    lw.x = (uint32_t)__bfloat16_as_ushort(l0) | ((uint32_t)__bfloat16_as_ushort(l1) << 16);
    lw.y = (uint32_t)__bfloat16_as_ushort(l2) | ((uint32_t)__bfloat16_as_ushort(l3) << 16);
    hi[i] = hw;
    lo[i] = lw;
}

// ---------------------------------------------------------------------------
// Transpose + split V: [b,s,head*64+d] fp32 -> [b,head,d,s] bf16 hi/lo
// ---------------------------------------------------------------------------
__global__ __launch_bounds__(256) void vtrans_kernel(
    const float* __restrict__ V, __nv_bfloat16* __restrict__ Vth,
    __nv_bfloat16* __restrict__ Vtl)
{
    __shared__ float t[64][68];
    const int s0 = blockIdx.x * 64;
    const int n = blockIdx.y;
    const int b = blockIdx.z;
    const int tid = threadIdx.x;

    for (int idx = tid; idx < 1024; idx += 256) {
        int row = idx >> 4, c4 = idx & 15;
        float4 v = *(const float4*)&V[((size_t)(b * S_) + s0 + row) * H_ + n * HD_ + c4 * 4];
        *(float4*)&t[row][c4 * 4] = v;
    }
    __syncthreads();
    for (int idx = tid; idx < 1024; idx += 256) {
        int d = idx >> 4, sg = idx & 15;
        float v0 = t[sg * 4 + 0][d];
        float v1 = t[sg * 4 + 1][d];
        float v2 = t[sg * 4 + 2][d];
        float v3 = t[sg * 4 + 3][d];
        __nv_bfloat16 h0 = __float2bfloat16(v0);
        __nv_bfloat16 h1 = __float2bfloat16(v1);
        __nv_bfloat16 h2 = __float2bfloat16(v2);
        __nv_bfloat16 h3 = __float2bfloat16(v3);
        uint2 hw, lw;
        hw.x = (uint32_t)__bfloat16_as_ushort(h0) | ((uint32_t)__bfloat16_as_ushort(h1) << 16);
        hw.y = (uint32_t)__bfloat16_as_ushort(h2) | ((uint32_t)__bfloat16_as_ushort(h3) << 16);
        __nv_bfloat16 l0 = __float2bfloat16(v0 - __bfloat162float(h0));
        __nv_bfloat16 l1 = __float2bfloat16(v1 - __bfloat162float(h1));
        __nv_bfloat16 l2 = __float2bfloat16(v2 - __bfloat162float(h2));
        __nv_bfloat16 l3 = __float2bfloat16(v3 - __bfloat162float(h3));
        lw.x = (uint32_t)__bfloat16_as_ushort(l0) | ((uint32_t)__bfloat16_as_ushort(l1) << 16);
        lw.y = (uint32_t)__bfloat16_as_ushort(l2) | ((uint32_t)__bfloat16_as_ushort(l3) << 16);
        size_t o = ((size_t)((b * NH_ + n) * HD_) + d) * S_ + s0 + sg * 4;
        *(uint2*)(Vth + o) = hw;
        *(uint2*)(Vtl + o) = lw;
    }
}

// ---------------------------------------------------------------------------
// Tensor-core GEMM with cp.async double buffering.
// C[M,1024] = A[M,1024] @ B[1024,1024]^T + bias
// Dynamic smem: 2 stages x (Ah,Al,Bh,Bl) x 8KB = 64KB.
// ---------------------------------------------------------------------------
#define GEMM_SMEM 65536

__global__ __launch_bounds__(256) void gemm_mma(
    const __nv_bfloat16* __restrict__ Ahg, const __nv_bfloat16* __restrict__ Alg,
    const __nv_bfloat16* __restrict__ Bhg, const __nv_bfloat16* __restrict__ Blg,
    const float* __restrict__ bias, float* __restrict__ C)
{
    extern __shared__ __align__(16) uint8_t gsm[];
    const uint32_t sb = smem_u32(gsm);

    const int tid = threadIdx.x;
    const int lane = tid & 31;
    const int wid = tid >> 5;
    const int warp_m = wid >> 1;
    const int warp_n = wid & 1;
    const int m0 = blockIdx.y * 128;
    const int n0 = blockIdx.x * 128;
    const int g = lane >> 2;
    const int t4 = lane & 3;

    float acc[2][8][4];
#pragma unroll
    for (int mt = 0; mt < 2; mt++)
#pragma unroll
        for (int nt = 0; nt < 8; nt++)
#pragma unroll
            for (int i = 0; i < 4; i++) acc[mt][nt][i] = 0.f;

    auto issue = [&](int kt, int buf) {
#pragma unroll
        for (int l = 0; l < 2; l++) {
            int s2 = tid + l * 256;
            int row = s2 >> 2;
            int seg = s2 & 3;
            uint32_t soff = (uint32_t)(buf * 32768 + row * 64 + ((seg ^ ((row >> 1) & 3)) << 4));
            size_t ga = (size_t)(m0 + row) * H_ + kt * 32 + seg * 8;
            size_t gb = (size_t)(n0 + row) * H_ + kt * 32 + seg * 8;
            CP16(sb + soff,         Ahg + ga);
            CP16(sb + soff + 8192,  Alg + ga);
            CP16(sb + soff + 16384, Bhg + gb);
            CP16(sb + soff + 24576, Blg + gb);
        }
    };

    issue(0, 0);
    asm volatile("cp.async.commit_group;");

#pragma unroll 1
    for (int kt = 0; kt < 32; kt++) {
        const int cur = kt & 1;
        if (kt < 31) {
            issue(kt + 1, cur ^ 1);
            asm volatile("cp.async.commit_group;");
            asm volatile("cp.async.wait_group 1;");
        } else {
            asm volatile("cp.async.wait_group 0;");
        }
        __syncthreads();

        const uint8_t* bAh = gsm + cur * 32768;
        const uint8_t* bAl = bAh + 8192;
        const uint8_t* bBh = bAh + 16384;
        const uint8_t* bBl = bAh + 24576;

#pragma unroll
        for (int kk = 0; kk < 64; kk += 32) {
            const int kb = kk + t4 * 4;
            uint32_t ah[2][4], al[2][4];
#pragma unroll
            for (int mt = 0; mt < 2; mt++) {
                int r = warp_m * 32 + mt * 16 + g;
                ah[mt][0] = lds32(bAh, r, kb);
                ah[mt][1] = lds32(bAh, r + 8, kb);
                ah[mt][2] = lds32(bAh, r, kb + 16);
                ah[mt][3] = lds32(bAh, r + 8, kb + 16);
                al[mt][0] = lds32(bAl, r, kb);
                al[mt][1] = lds32(bAl, r + 8, kb);
                al[mt][2] = lds32(bAl, r, kb + 16);
                al[mt][3] = lds32(bAl, r + 8, kb + 16);
            }
#pragma unroll
            for (int nt = 0; nt < 8; nt++) {
                int n = warp_n * 64 + nt * 8 + g;
                uint32_t bh0 = lds32(bBh, n, kb);
                uint32_t bh1 = lds32(bBh, n, kb + 16);
                uint32_t bl0 = lds32(bBl, n, kb);
                uint32_t bl1 = lds32(bBl, n, kb + 16);
#pragma unroll
                for (int mt = 0; mt < 2; mt++) {
                    mma16816(acc[mt][nt], ah[mt][0], ah[mt][1], ah[mt][2], ah[mt][3], bh0, bh1);
                    mma16816(acc[mt][nt], ah[mt][0], ah[mt][1], ah[mt][2], ah[mt][3], bl0, bl1);
                    mma16816(acc[mt][nt], al[mt][0], al[mt][1], al[mt][2], al[mt][3], bh0, bh1);
                }
            }
        }
        __syncthreads();
    }

#pragma unroll
    for (int mt = 0; mt < 2; mt++) {
        int row = m0 + warp_m * 32 + mt * 16 + g;
#pragma unroll
        for (int nt = 0; nt < 8; nt++) {
            int col = n0 + warp_n * 64 + nt * 8 + t4 * 2;
            float2 bv = *(const float2*)&bias[col];
            float2 o0, o1;
            o0.x = acc[mt][nt][0] + bv.x; o0.y = acc[mt][nt][1] + bv.y;
            o1.x = acc[mt][nt][2] + bv.x; o1.y = acc[mt][nt][3] + bv.y;
            *(float2*)&C[(size_t)row * H_ + col] = o0;
            *(float2*)&C[(size_t)(row + 8) * H_ + col] = o1;
        }
    }
}

// ---------------------------------------------------------------------------
// Tensor-core flash attention. 128 threads / 4 warps; q-tile 64; k-tiles 64.
// Inputs pre-split bf16 hi/lo; V pre-transposed. Pt table in bf16.
// smem = 6*8KB tiles + 33KB Pt = 82KB -> 2 CTAs/SM.
// ---------------------------------------------------------------------------
#define ASM_QH 0
#define ASM_QL 8192
#define ASM_KH 16384
#define ASM_KL 24576
#define ASM_VH 32768
#define ASM_VL 40960
#define ASM_PT 49152                    // bf16[64][257] = 32896 B
#define ATTN_SMEM (49152 + 32896)

__global__ __launch_bounds__(128) void attn_mma(
    const __nv_bfloat16* __restrict__ Qh, const __nv_bfloat16* __restrict__ Ql,
    const __nv_bfloat16* __restrict__ Kh, const __nv_bfloat16* __restrict__ Kl,
    const __nv_bfloat16* __restrict__ Vth, const __nv_bfloat16* __restrict__ Vtl,
    const float* __restrict__ Qf, const float* __restrict__ rel_emb,
    float* __restrict__ O)
{
    extern __shared__ __align__(16) uint8_t dynsm[];
    uint8_t* sQh = dynsm + ASM_QH;
    uint8_t* sQl = dynsm + ASM_QL;
    uint8_t* sKh = dynsm + ASM_KH;
    uint8_t* sKl = dynsm + ASM_KL;
    uint8_t* sVh = dynsm + ASM_VH;
    uint8_t* sVl = dynsm + ASM_VL;
    __nv_bfloat16* PtB = (__nv_bfloat16*)(dynsm + ASM_PT);

    const int b  = blockIdx.z;
    const int n  = blockIdx.y;
    const int q0 = blockIdx.x * 64;
    const int tid = threadIdx.x;
    const int lane = tid & 31;
    const int w = tid >> 5;
    const int g = lane >> 2;
    const int t4 = lane & 3;

    // Q tile load (pure copy, swizzled)
    for (int idx = tid; idx < 512; idx += 128) {
        int row = idx >> 3, seg = idx & 7;
        uint32_t off = (uint32_t)(row * 128 + ((seg ^ (row & 7)) << 4));
        size_t gq = ((size_t)(b * S_) + q0 + row) * H_ + n * HD_ + seg * 8;
        *(uint4*)(sQh + off) = *(const uint4*)(Qh + gq);
        *(uint4*)(sQl + off) = *(const uint4*)(Ql + gq);
    }

    // Pt[q][r] = Q[q].rel_emb[r], fp32 compute, bf16 store
    {
        const int qsel = tid & 63;
        const int half = tid >> 6;
        const float4* qrow = (const float4*)(Qf + ((size_t)(b * S_) + q0 + qsel) * H_ + n * HD_);
        float4 Qr[16];
#pragma unroll
        for (int i = 0; i < 16; i++) Qr[i] = __ldg(&qrow[i]);
        for (int r = half; r < NREL; r += 2) {
            const float4* e = (const float4*)(rel_emb + r * HD_);
            float s = 0.f;
#pragma unroll
            for (int i = 0; i < 16; i++) {
                float4 ev = __ldg(&e[i]);
                s = fmaf(Qr[i].x, ev.x, s); s = fmaf(Qr[i].y, ev.y, s);
                s = fmaf(Qr[i].z, ev.z, s); s = fmaf(Qr[i].w, ev.w, s);
            }
            PtB[qsel * NREL + r] = __float2bfloat16(s);
        }
    }
    __syncthreads();

    // Resident Q A-frags (rows 16w+g, 16w+g+8)
    uint32_t qah[4][4], qal[4][4];
    {
        int r = 16 * w + g;
#pragma unroll
        for (int kb = 0; kb < 4; kb++) {
            int kbase = kb * 32 + t4 * 4;
            qah[kb][0] = lds32b(sQh, r, kbase);
            qah[kb][1] = lds32b(sQh, r + 8, kbase);
            qah[kb][2] = lds32b(sQh, r, kbase + 16);
            qah[kb][3] = lds32b(sQh, r + 8, kbase + 16);
            qal[kb][0] = lds32b(sQl, r, kbase);
            qal[kb][1] = lds32b(sQl, r + 8, kbase);
            qal[kb][2] = lds32b(sQl, r, kbase + 16);
            qal[kb][3] = lds32b(sQl, r + 8, kbase + 16);
        }
    }

    float oacc[8][4];
#pragma unroll
    for (int j = 0; j < 8; j++)
#pragma unroll
        for (int i = 0; i < 4; i++) oacc[j][i] = 0.f;
    float rmax0 = -INFINITY, rmax1 = -INFINITY;
    float rsum0 = 0.f, rsum1 = 0.f;

    const int qg0 = q0 + 16 * w + g;
    const int ql0 = 16 * w + g;

    const __nv_bfloat16* Vhb = Vth + (size_t)((b * NH_ + n) * HD_) * S_;
    const __nv_bfloat16* Vlb = Vtl + (size_t)((b * NH_ + n) * HD_) * S_;

#pragma unroll 1
    for (int kt = 0; kt < 16; kt++) {
        const int k0 = kt * 64;
        __syncthreads();
        // K tile rows = keys; V tile rows = dims (pre-transposed). Pure copies.
        for (int idx = tid; idx < 512; idx += 128) {
            int row = idx >> 3, seg = idx & 7;
            uint32_t off = (uint32_t)(row * 128 + ((seg ^ (row & 7)) << 4));
            size_t gk = ((size_t)(b * S_) + k0 + row) * H_ + n * HD_ + seg * 8;
            size_t gv = (size_t)row * S_ + k0 + seg * 8;
            *(uint4*)(sKh + off) = *(const uint4*)(Kh + gk);
            *(uint4*)(sKl + off) = *(const uint4*)(Kl + gk);
            *(uint4*)(sVh + off) = *(const uint4*)(Vhb + gv);
            *(uint4*)(sVl + off) = *(const uint4*)(Vlb + gv);
        }
        __syncthreads();

        // QK^T
        float sc[8][4];
#pragma unroll
        for (int j = 0; j < 8; j++)
#pragma unroll
            for (int i = 0; i < 4; i++) sc[j][i] = 0.f;
#pragma unroll
        for (int kb = 0; kb < 4; kb++) {
            int kbase = kb * 32 + t4 * 4;
#pragma unroll
            for (int j = 0; j < 8; j++) {
                int krow = 8 * j + g;
                uint32_t bh0 = lds32b(sKh, krow, kbase);
                uint32_t bh1 = lds32b(sKh, krow, kbase + 16);
                uint32_t bl0 = lds32b(sKl, krow, kbase);
                uint32_t bl1 = lds32b(sKl, krow, kbase + 16);
                mma16816(sc[j], qah[kb][0], qah[kb][1], qah[kb][2], qah[kb][3], bh0, bh1);
                mma16816(sc[j], qah[kb][0], qah[kb][1], qah[kb][2], qah[kb][3], bl0, bl1);
                mma16816(sc[j], qal[kb][0], qal[kb][1], qal[kb][2], qal[kb][3], bh0, bh1);
            }
        }

        // Bias + scale
#pragma unroll
        for (int j = 0; j < 8; j++) {
            int col = k0 + 8 * j + 2 * t4;
            int r00 = min(128, max(-128, col     - qg0)) + 128;
            int r01 = min(128, max(-128, col + 1 - qg0)) + 128;
            int r10 = min(128, max(-128, col     - qg0 - 8)) + 128;
            int r11 = min(128, max(-128, col + 1 - qg0 - 8)) + 128;
            sc[j][0] = (sc[j][0] + __bfloat162float(PtB[ql0 * NREL + r00])) * 0.125f;
            sc[j][1] = (sc[j][1] + __bfloat162float(PtB[ql0 * NREL + r01])) * 0.125f;
            sc[j][2] = (sc[j][2] + __bfloat162float(PtB[(ql0 + 8) * NREL + r10])) * 0.125f;
            sc[j][3] = (sc[j][3] + __bfloat162float(PtB[(ql0 + 8) * NREL + r11])) * 0.125f;
        }

        // Online softmax
        float m0 = -INFINITY, m1 = -INFINITY;
#pragma unroll
        for (int j = 0; j < 8; j++) {
            m0 = fmaxf(m0, fmaxf(sc[j][0], sc[j][1]));
            m1 = fmaxf(m1, fmaxf(sc[j][2], sc[j][3]));
        }
        m0 = fmaxf(m0, __shfl_xor_sync(0xffffffffu, m0, 1, 4));
        m0 = fmaxf(m0, __shfl_xor_sync(0xffffffffu, m0, 2, 4));
        m1 = fmaxf(m1, __shfl_xor_sync(0xffffffffu, m1, 1, 4));
        m1 = fmaxf(m1, __shfl_xor_sync(0xffffffffu, m1, 2, 4));

        float nm0 = fmaxf(rmax0, m0);
        float nm1 = fmaxf(rmax1, m1);
        float esc0 = __expf(rmax0 - nm0);
        float esc1 = __expf(rmax1 - nm1);
        rmax0 = nm0; rmax1 = nm1;

        float s0 = 0.f, s1 = 0.f;
#pragma unroll
        for (int j = 0; j < 8; j++) {
            sc[j][0] = __expf(sc[j][0] - nm0);
            sc[j][1] = __expf(sc[j][1] - nm0);
            sc[j][2] = __expf(sc[j][2] - nm1);
            sc[j][3] = __expf(sc[j][3] - nm1);
            s0 += sc[j][0] + sc[j][1];
            s1 += sc[j][2] + sc[j][3];
        }
        s0 += __shfl_xor_sync(0xffffffffu, s0, 1, 4);
        s0 += __shfl_xor_sync(0xffffffffu, s0, 2, 4);
        s1 += __shfl_xor_sync(0xffffffffu, s1, 1, 4);
        s1 += __shfl_xor_sync(0xffffffffu, s1, 2, 4);
        rsum0 = rsum0 * esc0 + s0;
        rsum1 = rsum1 * esc1 + s1;

#pragma unroll
        for (int j = 0; j < 8; j++) {
            oacc[j][0] *= esc0; oacc[j][1] *= esc0;
            oacc[j][2] *= esc1; oacc[j][3] *= esc1;
        }

        // PV
#pragma unroll
        for (int kb = 0; kb < 4; kb++) {
            uint32_t ah0, ah1, ah2, ah3, al0, al1, al2, al3;
            pack_hl(sc[2 * kb][0], sc[2 * kb][1], ah0, al0);
            pack_hl(sc[2 * kb][2], sc[2 * kb][3], ah1, al1);
            pack_hl(sc[2 * kb + 1][0], sc[2 * kb + 1][1], ah2, al2);
            pack_hl(sc[2 * kb + 1][2], sc[2 * kb + 1][3], ah3, al3);
            int kbase = kb * 32 + t4 * 4;
#pragma unroll
            for (int j = 0; j < 8; j++) {
                int vrow = 8 * j + g;
                uint32_t bh0 = lds32b(sVh, vrow, kbase);
                uint32_t bh1 = lds32b(sVh, vrow, kbase + 16);
                uint32_t bl0 = lds32b(sVl, vrow, kbase);
                uint32_t bl1 = lds32b(sVl, vrow, kbase + 16);
                mma16816(oacc[j], ah0, ah1, ah2, ah3, bh0, bh1);
                mma16816(oacc[j], ah0, ah1, ah2, ah3, bl0, bl1);
                mma16816(oacc[j], al0, al1, al2, al3, bh0, bh1);
            }
        }
    }

    // Epilogue
    float inv0 = 1.f / rsum0;
    float inv1 = 1.f / rsum1;
    float* Ob = O + ((size_t)b * S_ + q0) * H_ + n * HD_;
#pragma unroll
    for (int j = 0; j < 8; j++) {
        int col = 8 * j + 2 * t4;
        float2 o0, o1;
        o0.x = oacc[j][0] * inv0; o0.y = oacc[j][1] * inv0;
        o1.x = oacc[j][2] * inv1; o1.y = oacc[j][3] * inv1;
        *(float2*)&Ob[(size_t)(16 * w + g) * H_ + col] = o0;
        *(float2*)&Ob[(size_t)(16 * w + g + 8) * H_ + col] = o1;
    }
}

// ---------------------------------------------------------------------------
// Launch
// ---------------------------------------------------------------------------
extern "C" void kernel_launch(void* const* d_in, const int* in_sizes, int n_in,
                              void* d_out, int out_size)
{
    const float* x   = (const float*)d_in[0];
    const float* Wq  = (const float*)d_in[1];
    const float* bq  = (const float*)d_in[2];
    const float* Wk  = (const float*)d_in[3];
    const float* bk  = (const float*)d_in[4];
    const float* Wv  = (const float*)d_in[5];
    const float* bv  = (const float*)d_in[6];
    const float* Wo  = (const float*)d_in[7];
    const float* bo  = (const float*)d_in[8];
    const float* rel = (const float*)d_in[9];
    float* out = (float*)d_out;

    float *pQ, *pK, *pV, *pA;
    __nv_bfloat16 *xh, *xl, *wqh, *wql, *wkh, *wkl, *wvh, *wvl, *woh, *wol, *ah, *al;
    __nv_bfloat16 *qh, *ql, *kh, *kl, *vth, *vtl;
    cudaGetSymbolAddress((void**)&pQ, g_Q);
    cudaGetSymbolAddress((void**)&pK, g_K);
    cudaGetSymbolAddress((void**)&pV, g_V);
    cudaGetSymbolAddress((void**)&pA, g_ATT);
    cudaGetSymbolAddress((void**)&xh, g_xh);
    cudaGetSymbolAddress((void**)&xl, g_xl);
    cudaGetSymbolAddress((void**)&wqh, g_Wqh);
    cudaGetSymbolAddress((void**)&wql, g_Wql);
    cudaGetSymbolAddress((void**)&wkh, g_Wkh);
    cudaGetSymbolAddress((void**)&wkl, g_Wkl);
    cudaGetSymbolAddress((void**)&wvh, g_Wvh);
    cudaGetSymbolAddress((void**)&wvl, g_Wvl);
    cudaGetSymbolAddress((void**)&woh, g_Woh);
    cudaGetSymbolAddress((void**)&wol, g_Wol);
    cudaGetSymbolAddress((void**)&ah, g_ah);
    cudaGetSymbolAddress((void**)&al, g_al);
    cudaGetSymbolAddress((void**)&qh, g_Qh);
    cudaGetSymbolAddress((void**)&ql, g_Ql);
    cudaGetSymbolAddress((void**)&kh, g_Kh);
    cudaGetSymbolAddress((void**)&kl, g_Kl);
    cudaGetSymbolAddress((void**)&vth, g_Vth);
    cudaGetSymbolAddress((void**)&vtl, g_Vtl);

    cudaFuncSetAttribute(attn_mma, cudaFuncAttributeMaxDynamicSharedMemorySize, ATTN_SMEM);
    cudaFuncSetAttribute(gemm_mma, cudaFuncAttributeMaxDynamicSharedMemorySize, GEMM_SMEM);

    const int nx4 = MTOT * H_ / 4;
    const int nw4 = H_ * H_ / 4;

    split_kernel<<<(nx4 + 255) / 256, 256>>>((const float4*)x, (uint2*)xh, (uint2*)xl, nx4);
    split_kernel<<<(nw4 + 255) / 256, 256>>>((const float4*)Wq, (uint2*)wqh, (uint2*)wql, nw4);
    split_kernel<<<(nw4 + 255) / 256, 256>>>((const float4*)Wk, (uint2*)wkh, (uint2*)wkl, nw4);
    split_kernel<<<(nw4 + 255) / 256, 256>>>((const float4*)Wv, (uint2*)wvh, (uint2*)wvl, nw4);
    split_kernel<<<(nw4 + 255) / 256, 256>>>((const float4*)Wo, (uint2*)woh, (uint2*)wol, nw4);

    dim3 gemm_grid(H_ / 128, MTOT / 128);
    gemm_mma<<<gemm_grid, 256, GEMM_SMEM>>>(xh, xl, wqh, wql, bq, pQ);
    gemm_mma<<<gemm_grid, 256, GEMM_SMEM>>>(xh, xl, wkh, wkl, bk, pK);
    gemm_mma<<<gemm_grid, 256, GEMM_SMEM>>>(xh, xl, wvh, wvl, bv, pV);

    split_kernel<<<(nx4 + 255) / 256, 256>>>((const float4*)pQ, (uint2*)qh, (uint2*)ql, nx4);
    split_kernel<<<(nx4 + 255) / 256, 256>>>((const float4*)pK, (uint2*)kh, (uint2*)kl, nx4);
    vtrans_kernel<<<dim3(S_ / 64, NH_, B_), 256>>>(pV, vth, vtl);

    dim3 attn_grid(S_ / 64, NH_, B_);
    attn_mma<<<attn_grid, 128, ATTN_SMEM>>>(qh, ql, kh, kl, vth, vtl, pQ, rel, pA);

    split_kernel<<<(nx4 + 255) / 256, 256>>>((const float4*)pA, (uint2*)ah, (uint2*)al, nx4);
    gemm_mma<<<gemm_grid, 256, GEMM_SMEM>>>(ah, al, woh, wol, bo, out);
}

// round 8
// speedup vs baseline: 9.0926x; 1.1750x over previous
#include <cuda_runtime.h>
#include <cuda_bf16.h>
#include <math.h>
#include <stdint.h>

// ---------------------------------------------------------------------------
// Problem constants
// ---------------------------------------------------------------------------
#define B_   4
#define S_   1024
#define H_   1024
#define NH_  16
#define HD_  64
#define NREL 257   // 2*128+1
#define MTOT (B_ * S_)   // 4096

// ---------------------------------------------------------------------------
// Scratch (device globals — no cudaMalloc allowed)
// ---------------------------------------------------------------------------
__device__ float g_V[MTOT * H_];

__device__ __nv_bfloat16 g_xh[MTOT * H_];
__device__ __nv_bfloat16 g_xl[MTOT * H_];
__device__ __nv_bfloat16 g_Wqh[H_ * H_];
__device__ __nv_bfloat16 g_Wql[H_ * H_];
__device__ __nv_bfloat16 g_Wkh[H_ * H_];
__device__ __nv_bfloat16 g_Wkl[H_ * H_];
__device__ __nv_bfloat16 g_Wvh[H_ * H_];
__device__ __nv_bfloat16 g_Wvl[H_ * H_];
__device__ __nv_bfloat16 g_Woh[H_ * H_];
__device__ __nv_bfloat16 g_Wol[H_ * H_];
__device__ __nv_bfloat16 g_ah[MTOT * H_];
__device__ __nv_bfloat16 g_al[MTOT * H_];

__device__ __nv_bfloat16 g_Qh[MTOT * H_];
__device__ __nv_bfloat16 g_Ql[MTOT * H_];
__device__ __nv_bfloat16 g_Kh[MTOT * H_];
__device__ __nv_bfloat16 g_Kl[MTOT * H_];
__device__ __nv_bfloat16 g_Vth[MTOT * H_];   // [b][head][d][s]
__device__ __nv_bfloat16 g_Vtl[MTOT * H_];

// ---------------------------------------------------------------------------
// Helpers
// ---------------------------------------------------------------------------
__device__ __forceinline__ uint32_t smem_u32(const void* p) {
    uint32_t a;
    asm("{ .reg .u64 t; cvta.to.shared.u64 t, %1; cvt.u32.u64 %0, t; }"
        : "=r"(a) : "l"(p));
    return a;
}

#define CP16(dst_u32, src_ptr) \
    asm volatile("cp.async.cg.shared.global [%0], [%1], 16;" \
        :: "r"(dst_u32), "l"(src_ptr))

__device__ __forceinline__ void mma16816(float* c,
    uint32_t a0, uint32_t a1, uint32_t a2, uint32_t a3, uint32_t b0, uint32_t b1)
{
    asm volatile(
        "mma.sync.aligned.m16n8k16.row.col.f32.bf16.bf16.f32 "
        "{%0,%1,%2,%3}, {%4,%5,%6,%7}, {%8,%9}, {%0,%1,%2,%3};\n"
        : "+f"(c[0]), "+f"(c[1]), "+f"(c[2]), "+f"(c[3])
        : "r"(a0), "r"(a1), "r"(a2), "r"(a3), "r"(b0), "r"(b1));
}

// Swizzled offset within a tile of 64-byte rows (32 bf16). For GEMM.
__device__ __forceinline__ uint32_t swz(int row, int kbyte)
{
    return (uint32_t)(row * 64 + ((((kbyte >> 4) ^ ((row >> 1) & 3)) << 4) | (kbyte & 15)));
}
__device__ __forceinline__ uint32_t lds32(const uint8_t* base, int row, int kbyte)
{
    return *(const uint32_t*)(base + swz(row, kbyte));
}

// Swizzled offset within a tile of 128-byte rows (64 bf16). For attention.
__device__ __forceinline__ uint32_t swzb(int row, int kbyte)
{
    return (uint32_t)(row * 128 + ((((kbyte >> 4) ^ (row & 7)) << 4) | (kbyte & 15)));
}
__device__ __forceinline__ uint32_t lds32b(const uint8_t* base, int row, int kbyte)
{
    return *(const uint32_t*)(base + swzb(row, kbyte));
}

// Pack two fp32 into bf16x2 hi word + residual lo word.
__device__ __forceinline__ void pack_hl(float x0, float x1, uint32_t& h, uint32_t& l)
{
    asm("cvt.rn.bf16x2.f32 %0, %1, %2;" : "=r"(h) : "f"(x1), "f"(x0));
    float f0 = __uint_as_float(h << 16);
    float f1 = __uint_as_float(h & 0xffff0000u);
    float r0 = x0 - f0, r1 = x1 - f1;
    asm("cvt.rn.bf16x2.f32 %0, %1, %2;" : "=r"(l) : "f"(r1), "f"(r0));
}

__device__ __forceinline__ float bfl(uint32_t w) { return __uint_as_float(w << 16); }
__device__ __forceinline__ float bfh(uint32_t w) { return __uint_as_float(w & 0xffff0000u); }

// ---------------------------------------------------------------------------
// Split fp32 -> (bf16 hi, bf16 lo) elementwise
// ---------------------------------------------------------------------------
__global__ __launch_bounds__(256) void split_kernel(
    const float4* __restrict__ src, uint2* __restrict__ hi, uint2* __restrict__ lo, int n4)
{
    int i = blockIdx.x * blockDim.x + threadIdx.x;
    if (i >= n4) return;
    float4 v = src[i];
    uint32_t h0, l0, h1, l1;
    pack_hl(v.x, v.y, h0, l0);
    pack_hl(v.z, v.w, h1, l1);
    hi[i] = make_uint2(h0, h1);
    lo[i] = make_uint2(l0, l1);
}

// ---------------------------------------------------------------------------
// Transpose + split V: [b,s,head*64+d] fp32 -> [b,head,d,s] bf16 hi/lo
// ---------------------------------------------------------------------------
__global__ __launch_bounds__(256) void vtrans_kernel(
    const float* __restrict__ V, __nv_bfloat16* __restrict__ Vth,
    __nv_bfloat16* __restrict__ Vtl)
{
    __shared__ float t[64][68];
    const int s0 = blockIdx.x * 64;
    const int n = blockIdx.y;
    const int b = blockIdx.z;
    const int tid = threadIdx.x;

    for (int idx = tid; idx < 1024; idx += 256) {
        int row = idx >> 4, c4 = idx & 15;
        float4 v = *(const float4*)&V[((size_t)(b * S_) + s0 + row) * H_ + n * HD_ + c4 * 4];
        *(float4*)&t[row][c4 * 4] = v;
    }
    __syncthreads();
    for (int idx = tid; idx < 1024; idx += 256) {
        int d = idx >> 4, sg = idx & 15;
        float v0 = t[sg * 4 + 0][d];
        float v1 = t[sg * 4 + 1][d];
        float v2 = t[sg * 4 + 2][d];
        float v3 = t[sg * 4 + 3][d];
        uint32_t h0, l0, h1, l1;
        pack_hl(v0, v1, h0, l0);
        pack_hl(v2, v3, h1, l1);
        size_t o = ((size_t)((b * NH_ + n) * HD_) + d) * S_ + s0 + sg * 4;
        *(uint2*)(Vth + o) = make_uint2(h0, h1);
        *(uint2*)(Vtl + o) = make_uint2(l0, l1);
    }
}

// ---------------------------------------------------------------------------
// Fused QKV GEMM (gridDim.z = 3 selects weight/output set).
// C = x @ W^T + bias; z=0 -> Qh/Ql (bf16 split), z=1 -> Kh/Kl, z=2 -> V fp32.
// cp.async double-buffered, 128x128x32 tiles, 256 threads.
// ---------------------------------------------------------------------------
#define GEMM_SMEM 65536

__global__ __launch_bounds__(256) void gemm_qkv(
    const __nv_bfloat16* __restrict__ Ahg, const __nv_bfloat16* __restrict__ Alg,
    const __nv_bfloat16* __restrict__ Wqh, const __nv_bfloat16* __restrict__ Wql,
    const float* __restrict__ bq, __nv_bfloat16* __restrict__ Qh, __nv_bfloat16* __restrict__ Ql,
    const __nv_bfloat16* __restrict__ Wkh, const __nv_bfloat16* __restrict__ Wkl,
    const float* __restrict__ bk, __nv_bfloat16* __restrict__ Kh, __nv_bfloat16* __restrict__ Kl,
    const __nv_bfloat16* __restrict__ Wvh, const __nv_bfloat16* __restrict__ Wvl,
    const float* __restrict__ bv, float* __restrict__ V)
{
    extern __shared__ __align__(16) uint8_t gsm[];
    const uint32_t sb = smem_u32(gsm);

    const int z = blockIdx.z;
    const __nv_bfloat16* Bhg = (z == 0) ? Wqh : (z == 1) ? Wkh : Wvh;
    const __nv_bfloat16* Blg = (z == 0) ? Wql : (z == 1) ? Wkl : Wvl;
    const float* bias = (z == 0) ? bq : (z == 1) ? bk : bv;

    const int tid = threadIdx.x;
    const int lane = tid & 31;
    const int wid = tid >> 5;
    const int warp_m = wid >> 1;
    const int warp_n = wid & 1;
    const int m0 = blockIdx.y * 128;
    const int n0 = blockIdx.x * 128;
    const int g = lane >> 2;
    const int t4 = lane & 3;

    float acc[2][8][4];
#pragma unroll
    for (int mt = 0; mt < 2; mt++)
#pragma unroll
        for (int nt = 0; nt < 8; nt++)
#pragma unroll
            for (int i = 0; i < 4; i++) acc[mt][nt][i] = 0.f;

    auto issue = [&](int kt, int buf) {
#pragma unroll
        for (int l = 0; l < 2; l++) {
            int s2 = tid + l * 256;
            int row = s2 >> 2;
            int seg = s2 & 3;
            uint32_t soff = (uint32_t)(buf * 32768 + row * 64 + ((seg ^ ((row >> 1) & 3)) << 4));
            size_t ga = (size_t)(m0 + row) * H_ + kt * 32 + seg * 8;
            size_t gb = (size_t)(n0 + row) * H_ + kt * 32 + seg * 8;
            CP16(sb + soff,         Ahg + ga);
            CP16(sb + soff + 8192,  Alg + ga);
            CP16(sb + soff + 16384, Bhg + gb);
            CP16(sb + soff + 24576, Blg + gb);
        }
    };

    issue(0, 0);
    asm volatile("cp.async.commit_group;");

#pragma unroll 1
    for (int kt = 0; kt < 32; kt++) {
        const int cur = kt & 1;
        if (kt < 31) {
            issue(kt + 1, cur ^ 1);
            asm volatile("cp.async.commit_group;");
            asm volatile("cp.async.wait_group 1;");
        } else {
            asm volatile("cp.async.wait_group 0;");
        }
        __syncthreads();

        const uint8_t* bAh = gsm + cur * 32768;
        const uint8_t* bAl = bAh + 8192;
        const uint8_t* bBh = bAh + 16384;
        const uint8_t* bBl = bAh + 24576;

#pragma unroll
        for (int kk = 0; kk < 64; kk += 32) {
            const int kb = kk + t4 * 4;
            uint32_t ah[2][4], al[2][4];
#pragma unroll
            for (int mt = 0; mt < 2; mt++) {
                int r = warp_m * 32 + mt * 16 + g;
                ah[mt][0] = lds32(bAh, r, kb);
                ah[mt][1] = lds32(bAh, r + 8, kb);
                ah[mt][2] = lds32(bAh, r, kb + 16);
                ah[mt][3] = lds32(bAh, r + 8, kb + 16);
                al[mt][0] = lds32(bAl, r, kb);
                al[mt][1] = lds32(bAl, r + 8, kb);
                al[mt][2] = lds32(bAl, r, kb + 16);
                al[mt][3] = lds32(bAl, r + 8, kb + 16);
            }
#pragma unroll
            for (int nt = 0; nt < 8; nt++) {
                int n = warp_n * 64 + nt * 8 + g;
                uint32_t bh0 = lds32(bBh, n, kb);
                uint32_t bh1 = lds32(bBh, n, kb + 16);
                uint32_t bl0 = lds32(bBl, n, kb);
                uint32_t bl1 = lds32(bBl, n, kb + 16);
#pragma unroll
                for (int mt = 0; mt < 2; mt++) {
                    mma16816(acc[mt][nt], ah[mt][0], ah[mt][1], ah[mt][2], ah[mt][3], bh0, bh1);
                    mma16816(acc[mt][nt], ah[mt][0], ah[mt][1], ah[mt][2], ah[mt][3], bl0, bl1);
                    mma16816(acc[mt][nt], al[mt][0], al[mt][1], al[mt][2], al[mt][3], bh0, bh1);
                }
            }
        }
        __syncthreads();
    }

    __nv_bfloat16* Oh = (z == 0) ? Qh : Kh;
    __nv_bfloat16* Ol = (z == 0) ? Ql : Kl;
#pragma unroll
    for (int mt = 0; mt < 2; mt++) {
        int row = m0 + warp_m * 32 + mt * 16 + g;
#pragma unroll
        for (int nt = 0; nt < 8; nt++) {
            int col = n0 + warp_n * 64 + nt * 8 + t4 * 2;
            float2 bv2 = *(const float2*)&bias[col];
            float v0 = acc[mt][nt][0] + bv2.x, v1 = acc[mt][nt][1] + bv2.y;
            float v2 = acc[mt][nt][2] + bv2.x, v3 = acc[mt][nt][3] + bv2.y;
            if (z == 2) {
                *(float2*)&V[(size_t)row * H_ + col] = make_float2(v0, v1);
                *(float2*)&V[(size_t)(row + 8) * H_ + col] = make_float2(v2, v3);
            } else {
                uint32_t h0, l0, h1, l1;
                pack_hl(v0, v1, h0, l0);
                pack_hl(v2, v3, h1, l1);
                *(uint32_t*)(Oh + (size_t)row * H_ + col) = h0;
                *(uint32_t*)(Ol + (size_t)row * H_ + col) = l0;
                *(uint32_t*)(Oh + (size_t)(row + 8) * H_ + col) = h1;
                *(uint32_t*)(Ol + (size_t)(row + 8) * H_ + col) = l1;
            }
        }
    }
}

// ---------------------------------------------------------------------------
// Final output GEMM (fp32 epilogue): out = A @ Wo^T + bo
// ---------------------------------------------------------------------------
__global__ __launch_bounds__(256) void gemm_mma(
    const __nv_bfloat16* __restrict__ Ahg, const __nv_bfloat16* __restrict__ Alg,
    const __nv_bfloat16* __restrict__ Bhg, const __nv_bfloat16* __restrict__ Blg,
    const float* __restrict__ bias, float* __restrict__ C)
{
    extern __shared__ __align__(16) uint8_t gsm[];
    const uint32_t sb = smem_u32(gsm);

    const int tid = threadIdx.x;
    const int lane = tid & 31;
    const int wid = tid >> 5;
    const int warp_m = wid >> 1;
    const int warp_n = wid & 1;
    const int m0 = blockIdx.y * 128;
    const int n0 = blockIdx.x * 128;
    const int g = lane >> 2;
    const int t4 = lane & 3;

    float acc[2][8][4];
#pragma unroll
    for (int mt = 0; mt < 2; mt++)
#pragma unroll
        for (int nt = 0; nt < 8; nt++)
#pragma unroll
            for (int i = 0; i < 4; i++) acc[mt][nt][i] = 0.f;

    auto issue = [&](int kt, int buf) {
#pragma unroll
        for (int l = 0; l < 2; l++) {
            int s2 = tid + l * 256;
            int row = s2 >> 2;
            int seg = s2 & 3;
            uint32_t soff = (uint32_t)(buf * 32768 + row * 64 + ((seg ^ ((row >> 1) & 3)) << 4));
            size_t ga = (size_t)(m0 + row) * H_ + kt * 32 + seg * 8;
            size_t gb = (size_t)(n0 + row) * H_ + kt * 32 + seg * 8;
            CP16(sb + soff,         Ahg + ga);
            CP16(sb + soff + 8192,  Alg + ga);
            CP16(sb + soff + 16384, Bhg + gb);
            CP16(sb + soff + 24576, Blg + gb);
        }
    };

    issue(0, 0);
    asm volatile("cp.async.commit_group;");

#pragma unroll 1
    for (int kt = 0; kt < 32; kt++) {
        const int cur = kt & 1;
        if (kt < 31) {
            issue(kt + 1, cur ^ 1);
            asm volatile("cp.async.commit_group;");
            asm volatile("cp.async.wait_group 1;");
        } else {
            asm volatile("cp.async.wait_group 0;");
        }
        __syncthreads();

        const uint8_t* bAh = gsm + cur * 32768;
        const uint8_t* bAl = bAh + 8192;
        const uint8_t* bBh = bAh + 16384;
        const uint8_t* bBl = bAh + 24576;

#pragma unroll
        for (int kk = 0; kk < 64; kk += 32) {
            const int kb = kk + t4 * 4;
            uint32_t ah[2][4], al[2][4];
#pragma unroll
            for (int mt = 0; mt < 2; mt++) {
                int r = warp_m * 32 + mt * 16 + g;
                ah[mt][0] = lds32(bAh, r, kb);
                ah[mt][1] = lds32(bAh, r + 8, kb);
                ah[mt][2] = lds32(bAh, r, kb + 16);
                ah[mt][3] = lds32(bAh, r + 8, kb + 16);
                al[mt][0] = lds32(bAl, r, kb);
                al[mt][1] = lds32(bAl, r + 8, kb);
                al[mt][2] = lds32(bAl, r, kb + 16);
                al[mt][3] = lds32(bAl, r + 8, kb + 16);
            }
#pragma unroll
            for (int nt = 0; nt < 8; nt++) {
                int n = warp_n * 64 + nt * 8 + g;
                uint32_t bh0 = lds32(bBh, n, kb);
                uint32_t bh1 = lds32(bBh, n, kb + 16);
                uint32_t bl0 = lds32(bBl, n, kb);
                uint32_t bl1 = lds32(bBl, n, kb + 16);
#pragma unroll
                for (int mt = 0; mt < 2; mt++) {
                    mma16816(acc[mt][nt], ah[mt][0], ah[mt][1], ah[mt][2], ah[mt][3], bh0, bh1);
                    mma16816(acc[mt][nt], ah[mt][0], ah[mt][1], ah[mt][2], ah[mt][3], bl0, bl1);
                    mma16816(acc[mt][nt], al[mt][0], al[mt][1], al[mt][2], al[mt][3], bh0, bh1);
                }
            }
        }
        __syncthreads();
    }

#pragma unroll
    for (int mt = 0; mt < 2; mt++) {
        int row = m0 + warp_m * 32 + mt * 16 + g;
#pragma unroll
        for (int nt = 0; nt < 8; nt++) {
            int col = n0 + warp_n * 64 + nt * 8 + t4 * 2;
            float2 bv = *(const float2*)&bias[col];
            float2 o0, o1;
            o0.x = acc[mt][nt][0] + bv.x; o0.y = acc[mt][nt][1] + bv.y;
            o1.x = acc[mt][nt][2] + bv.x; o1.y = acc[mt][nt][3] + bv.y;
            *(float2*)&C[(size_t)row * H_ + col] = o0;
            *(float2*)&C[(size_t)(row + 8) * H_ + col] = o1;
        }
    }
}

// ---------------------------------------------------------------------------
// Tensor-core flash attention. 128 threads / 4 warps; q-tile 64; k-tiles 64.
// K/V tiles cp.async double-buffered. Epilogue writes bf16 hi/lo (ah/al).
// smem = Q 16KB + 2 stages x 32KB + Pt 33KB = 112.1KB -> 2 CTAs/SM.
// ---------------------------------------------------------------------------
#define AAT_Q  0
#define AAT_ST 16384                 // stage s at 16384 + s*32768
#define AAT_PT (16384 + 65536)       // bf16[64][257] = 32896 B
#define ATTN_SMEM (16384 + 65536 + 32896)

__global__ __launch_bounds__(128) void attn_mma(
    const __nv_bfloat16* __restrict__ Qh, const __nv_bfloat16* __restrict__ Ql,
    const __nv_bfloat16* __restrict__ Kh, const __nv_bfloat16* __restrict__ Kl,
    const __nv_bfloat16* __restrict__ Vth, const __nv_bfloat16* __restrict__ Vtl,
    const float* __restrict__ rel_emb,
    __nv_bfloat16* __restrict__ Aout_h, __nv_bfloat16* __restrict__ Aout_l)
{
    extern __shared__ __align__(16) uint8_t dynsm[];
    const uint32_t sbase = smem_u32(dynsm);
    uint8_t* sQh = dynsm + AAT_Q;
    uint8_t* sQl = dynsm + AAT_Q + 8192;
    __nv_bfloat16* PtB = (__nv_bfloat16*)(dynsm + AAT_PT);

    const int b  = blockIdx.z;
    const int n  = blockIdx.y;
    const int q0 = blockIdx.x * 64;
    const int tid = threadIdx.x;
    const int lane = tid & 31;
    const int w = tid >> 5;
    const int g = lane >> 2;
    const int t4 = lane & 3;

    const __nv_bfloat16* Vhb = Vth + (size_t)((b * NH_ + n) * HD_) * S_;
    const __nv_bfloat16* Vlb = Vtl + (size_t)((b * NH_ + n) * HD_) * S_;

    auto issue_kv = [&](int kt, int buf) {
        const int k0 = kt * 64;
        const uint32_t st = sbase + AAT_ST + buf * 32768;
#pragma unroll
        for (int l = 0; l < 4; l++) {
            int idx = tid + l * 128;
            int row = idx >> 3, seg = idx & 7;
            uint32_t off = (uint32_t)(row * 128 + ((seg ^ (row & 7)) << 4));
            size_t gk = ((size_t)(b * S_) + k0 + row) * H_ + n * HD_ + seg * 8;
            size_t gv = (size_t)row * S_ + k0 + seg * 8;
            CP16(st + off,         Kh + gk);
            CP16(st + off + 8192,  Kl + gk);
            CP16(st + off + 16384, Vhb + gv);
            CP16(st + off + 24576, Vlb + gv);
        }
    };

    // Q tile (regular stores, swizzled)
    for (int idx = tid; idx < 512; idx += 128) {
        int row = idx >> 3, seg = idx & 7;
        uint32_t off = (uint32_t)(row * 128 + ((seg ^ (row & 7)) << 4));
        size_t gq = ((size_t)(b * S_) + q0 + row) * H_ + n * HD_ + seg * 8;
        *(uint4*)(sQh + off) = *(const uint4*)(Qh + gq);
        *(uint4*)(sQl + off) = *(const uint4*)(Ql + gq);
    }

    // Prefetch first K/V tile while computing Pt
    issue_kv(0, 0);
    asm volatile("cp.async.commit_group;");

    // Pt[q][r] = Q[q].rel_emb[r] (Q reconstructed from hi+lo), bf16 store
    {
        const int qsel = tid & 63;
        const int half = tid >> 6;
        const uint4* qh4 = (const uint4*)(Qh + ((size_t)(b * S_) + q0 + qsel) * H_ + n * HD_);
        const uint4* ql4 = (const uint4*)(Ql + ((size_t)(b * S_) + q0 + qsel) * H_ + n * HD_);
        float Qr[64];
#pragma unroll
        for (int i = 0; i < 8; i++) {
            uint4 hw = __ldg(&qh4[i]);
            uint4 lw = __ldg(&ql4[i]);
            Qr[i * 8 + 0] = bfl(hw.x) + bfl(lw.x);
            Qr[i * 8 + 1] = bfh(hw.x) + bfh(lw.x);
            Qr[i * 8 + 2] = bfl(hw.y) + bfl(lw.y);
            Qr[i * 8 + 3] = bfh(hw.y) + bfh(lw.y);
            Qr[i * 8 + 4] = bfl(hw.z) + bfl(lw.z);
            Qr[i * 8 + 5] = bfh(hw.z) + bfh(lw.z);
            Qr[i * 8 + 6] = bfl(hw.w) + bfl(lw.w);
            Qr[i * 8 + 7] = bfh(hw.w) + bfh(lw.w);
        }
        for (int r = half; r < NREL; r += 2) {
            const float4* e = (const float4*)(rel_emb + r * HD_);
            float s = 0.f;
#pragma unroll
            for (int i = 0; i < 16; i++) {
                float4 ev = __ldg(&e[i]);
                s = fmaf(Qr[i * 4 + 0], ev.x, s);
                s = fmaf(Qr[i * 4 + 1], ev.y, s);
                s = fmaf(Qr[i * 4 + 2], ev.z, s);
                s = fmaf(Qr[i * 4 + 3], ev.w, s);
            }
            PtB[qsel * NREL + r] = __float2bfloat16(s);
        }
    }
    __syncthreads();

    // Resident Q A-frags
    uint32_t qah[4][4], qal[4][4];
    {
        int r = 16 * w + g;
#pragma unroll
        for (int kb = 0; kb < 4; kb++) {
            int kbase = kb * 32 + t4 * 4;
            qah[kb][0] = lds32b(sQh, r, kbase);
            qah[kb][1] = lds32b(sQh, r + 8, kbase);
            qah[kb][2] = lds32b(sQh, r, kbase + 16);
            qah[kb][3] = lds32b(sQh, r + 8, kbase + 16);
            qal[kb][0] = lds32b(sQl, r, kbase);
            qal[kb][1] = lds32b(sQl, r + 8, kbase);
            qal[kb][2] = lds32b(sQl, r, kbase + 16);
            qal[kb][3] = lds32b(sQl, r + 8, kbase + 16);
        }
    }

    float oacc[8][4];
#pragma unroll
    for (int j = 0; j < 8; j++)
#pragma unroll
        for (int i = 0; i < 4; i++) oacc[j][i] = 0.f;
    float rmax0 = -INFINITY, rmax1 = -INFINITY;
    float rsum0 = 0.f, rsum1 = 0.f;

    const int qg0 = q0 + 16 * w + g;
    const int ql0 = 16 * w + g;

#pragma unroll 1
    for (int kt = 0; kt < 16; kt++) {
        const int k0 = kt * 64;
        const int cur = kt & 1;
        asm volatile("cp.async.wait_group 0;");
        __syncthreads();
        if (kt < 15) {
            issue_kv(kt + 1, cur ^ 1);
            asm volatile("cp.async.commit_group;");
        }

        const uint8_t* sKh = dynsm + AAT_ST + cur * 32768;
        const uint8_t* sKl = sKh + 8192;
        const uint8_t* sVh = sKh + 16384;
        const uint8_t* sVl = sKh + 24576;

        // QK^T
        float sc[8][4];
#pragma unroll
        for (int j = 0; j < 8; j++)
#pragma unroll
            for (int i = 0; i < 4; i++) sc[j][i] = 0.f;
#pragma unroll
        for (int kb = 0; kb < 4; kb++) {
            int kbase = kb * 32 + t4 * 4;
#pragma unroll
            for (int j = 0; j < 8; j++) {
                int krow = 8 * j + g;
                uint32_t bh0 = lds32b(sKh, krow, kbase);
                uint32_t bh1 = lds32b(sKh, krow, kbase + 16);
                uint32_t bl0 = lds32b(sKl, krow, kbase);
                uint32_t bl1 = lds32b(sKl, krow, kbase + 16);
                mma16816(sc[j], qah[kb][0], qah[kb][1], qah[kb][2], qah[kb][3], bh0, bh1);
                mma16816(sc[j], qah[kb][0], qah[kb][1], qah[kb][2], qah[kb][3], bl0, bl1);
                mma16816(sc[j], qal[kb][0], qal[kb][1], qal[kb][2], qal[kb][3], bh0, bh1);
            }
        }

        // Bias + scale
#pragma unroll
        for (int j = 0; j < 8; j++) {
            int col = k0 + 8 * j + 2 * t4;
            int r00 = min(128, max(-128, col     - qg0)) + 128;
            int r01 = min(128, max(-128, col + 1 - qg0)) + 128;
            int r10 = min(128, max(-128, col     - qg0 - 8)) + 128;
            int r11 = min(128, max(-128, col + 1 - qg0 - 8)) + 128;
            sc[j][0] = (sc[j][0] + __bfloat162float(PtB[ql0 * NREL + r00])) * 0.125f;
            sc[j][1] = (sc[j][1] + __bfloat162float(PtB[ql0 * NREL + r01])) * 0.125f;
            sc[j][2] = (sc[j][2] + __bfloat162float(PtB[(ql0 + 8) * NREL + r10])) * 0.125f;
            sc[j][3] = (sc[j][3] + __bfloat162float(PtB[(ql0 + 8) * NREL + r11])) * 0.125f;
        }

        // Online softmax
        float m0 = -INFINITY, m1 = -INFINITY;
#pragma unroll
        for (int j = 0; j < 8; j++) {
            m0 = fmaxf(m0, fmaxf(sc[j][0], sc[j][1]));
            m1 = fmaxf(m1, fmaxf(sc[j][2], sc[j][3]));
        }
        m0 = fmaxf(m0, __shfl_xor_sync(0xffffffffu, m0, 1, 4));
        m0 = fmaxf(m0, __shfl_xor_sync(0xffffffffu, m0, 2, 4));
        m1 = fmaxf(m1, __shfl_xor_sync(0xffffffffu, m1, 1, 4));
        m1 = fmaxf(m1, __shfl_xor_sync(0xffffffffu, m1, 2, 4));

        float nm0 = fmaxf(rmax0, m0);
        float nm1 = fmaxf(rmax1, m1);
        float esc0 = __expf(rmax0 - nm0);
        float esc1 = __expf(rmax1 - nm1);
        rmax0 = nm0; rmax1 = nm1;

        float s0 = 0.f, s1 = 0.f;
#pragma unroll
        for (int j = 0; j < 8; j++) {
            sc[j][0] = __expf(sc[j][0] - nm0);
            sc[j][1] = __expf(sc[j][1] - nm0);
            sc[j][2] = __expf(sc[j][2] - nm1);
            sc[j][3] = __expf(sc[j][3] - nm1);
            s0 += sc[j][0] + sc[j][1];
            s1 += sc[j][2] + sc[j][3];
        }
        s0 += __shfl_xor_sync(0xffffffffu, s0, 1, 4);
        s0 += __shfl_xor_sync(0xffffffffu, s0, 2, 4);
        s1 += __shfl_xor_sync(0xffffffffu, s1, 1, 4);
        s1 += __shfl_xor_sync(0xffffffffu, s1, 2, 4);
        rsum0 = rsum0 * esc0 + s0;
        rsum1 = rsum1 * esc1 + s1;

#pragma unroll
        for (int j = 0; j < 8; j++) {
            oacc[j][0] *= esc0; oacc[j][1] *= esc0;
            oacc[j][2] *= esc1; oacc[j][3] *= esc1;
        }

        // PV
#pragma unroll
        for (int kb = 0; kb < 4; kb++) {
            uint32_t ah0, ah1, ah2, ah3, al0, al1, al2, al3;
            pack_hl(sc[2 * kb][0], sc[2 * kb][1], ah0, al0);
            pack_hl(sc[2 * kb][2], sc[2 * kb][3], ah1, al1);
            pack_hl(sc[2 * kb + 1][0], sc[2 * kb + 1][1], ah2, al2);
            pack_hl(sc[2 * kb + 1][2], sc[2 * kb + 1][3], ah3, al3);
            int kbase = kb * 32 + t4 * 4;
#pragma unroll
            for (int j = 0; j < 8; j++) {
                int vrow = 8 * j + g;
                uint32_t bh0 = lds32b(sVh, vrow, kbase);
                uint32_t bh1 = lds32b(sVh, vrow, kbase + 16);
                uint32_t bl0 = lds32b(sVl, vrow, kbase);
                uint32_t bl1 = lds32b(sVl, vrow, kbase + 16);
                mma16816(oacc[j], ah0, ah1, ah2, ah3, bh0, bh1);
                mma16816(oacc[j], ah0, ah1, ah2, ah3, bl0, bl1);
                mma16816(oacc[j], al0, al1, al2, al3, bh0, bh1);
            }
        }
        __syncthreads();   // done reading cur buffer before next overwrite
    }

    // Epilogue: normalize + write bf16 hi/lo
    float inv0 = 1.f / rsum0;
    float inv1 = 1.f / rsum1;
    size_t base0 = ((size_t)b * S_ + q0 + 16 * w + g) * H_ + n * HD_;
    size_t base1 = base0 + 8 * H_;
#pragma unroll
    for (int j = 0; j < 8; j++) {
        int col = 8 * j + 2 * t4;
        uint32_t h0, l0, h1, l1;
        pack_hl(oacc[j][0] * inv0, oacc[j][1] * inv0, h0, l0);
        pack_hl(oacc[j][2] * inv1, oacc[j][3] * inv1, h1, l1);
        *(uint32_t*)(Aout_h + base0 + col) = h0;
        *(uint32_t*)(Aout_l + base0 + col) = l0;
        *(uint32_t*)(Aout_h + base1 + col) = h1;
        *(uint32_t*)(Aout_l + base1 + col) = l1;
    }
}

// ---------------------------------------------------------------------------
// Launch
// ---------------------------------------------------------------------------
extern "C" void kernel_launch(void* const* d_in, const int* in_sizes, int n_in,
                              void* d_out, int out_size)
{
    const float* x   = (const float*)d_in[0];
    const float* Wq  = (const float*)d_in[1];
    const float* bq  = (const float*)d_in[2];
    const float* Wk  = (const float*)d_in[3];
    const float* bk  = (const float*)d_in[4];
    const float* Wv  = (const float*)d_in[5];
    const float* bv  = (const float*)d_in[6];
    const float* Wo  = (const float*)d_in[7];
    const float* bo  = (const float*)d_in[8];
    const float* rel = (const float*)d_in[9];
    float* out = (float*)d_out;

    float* pV;
    __nv_bfloat16 *xh, *xl, *wqh, *wql, *wkh, *wkl, *wvh, *wvl, *woh, *wol, *ah, *al;
    __nv_bfloat16 *qh, *ql, *kh, *kl, *vth, *vtl;
    cudaGetSymbolAddress((void**)&pV, g_V);
    cudaGetSymbolAddress((void**)&xh, g_xh);
    cudaGetSymbolAddress((void**)&xl, g_xl);
    cudaGetSymbolAddress((void**)&wqh, g_Wqh);
    cudaGetSymbolAddress((void**)&wql, g_Wql);
    cudaGetSymbolAddress((void**)&wkh, g_Wkh);
    cudaGetSymbolAddress((void**)&wkl, g_Wkl);
    cudaGetSymbolAddress((void**)&wvh, g_Wvh);
    cudaGetSymbolAddress((void**)&wvl, g_Wvl);
    cudaGetSymbolAddress((void**)&woh, g_Woh);
    cudaGetSymbolAddress((void**)&wol, g_Wol);
    cudaGetSymbolAddress((void**)&ah, g_ah);
    cudaGetSymbolAddress((void**)&al, g_al);
    cudaGetSymbolAddress((void**)&qh, g_Qh);
    cudaGetSymbolAddress((void**)&ql, g_Ql);
    cudaGetSymbolAddress((void**)&kh, g_Kh);
    cudaGetSymbolAddress((void**)&kl, g_Kl);
    cudaGetSymbolAddress((void**)&vth, g_Vth);
    cudaGetSymbolAddress((void**)&vtl, g_Vtl);

    cudaFuncSetAttribute(attn_mma, cudaFuncAttributeMaxDynamicSharedMemorySize, ATTN_SMEM);
    cudaFuncSetAttribute(gemm_mma, cudaFuncAttributeMaxDynamicSharedMemorySize, GEMM_SMEM);
    cudaFuncSetAttribute(gemm_qkv, cudaFuncAttributeMaxDynamicSharedMemorySize, GEMM_SMEM);

    const int nx4 = MTOT * H_ / 4;
    const int nw4 = H_ * H_ / 4;

    split_kernel<<<(nx4 + 255) / 256, 256>>>((const float4*)x, (uint2*)xh, (uint2*)xl, nx4);
    split_kernel<<<(nw4 + 255) / 256, 256>>>((const float4*)Wq, (uint2*)wqh, (uint2*)wql, nw4);
    split_kernel<<<(nw4 + 255) / 256, 256>>>((const float4*)Wk, (uint2*)wkh, (uint2*)wkl, nw4);
    split_kernel<<<(nw4 + 255) / 256, 256>>>((const float4*)Wv, (uint2*)wvh, (uint2*)wvl, nw4);
    split_kernel<<<(nw4 + 255) / 256, 256>>>((const float4*)Wo, (uint2*)woh, (uint2*)wol, nw4);

    dim3 qkv_grid(H_ / 128, MTOT / 128, 3);   // (8, 32, 3) = 768 blocks
    gemm_qkv<<<qkv_grid, 256, GEMM_SMEM>>>(xh, xl,
        wqh, wql, bq, qh, ql,
        wkh, wkl, bk, kh, kl,
        wvh, wvl, bv, pV);

    vtrans_kernel<<<dim3(S_ / 64, NH_, B_), 256>>>(pV, vth, vtl);

    dim3 attn_grid(S_ / 64, NH_, B_);
    attn_mma<<<attn_grid, 128, ATTN_SMEM>>>(qh, ql, kh, kl, vth, vtl, rel, ah, al);

    dim3 gemm_grid(H_ / 128, MTOT / 128);
    gemm_mma<<<gemm_grid, 256, GEMM_SMEM>>>(ah, al, woh, wol, bo, out);
}

// round 11
// speedup vs baseline: 11.4584x; 1.2602x over previous
#include <cuda_runtime.h>
#include <cuda_bf16.h>
#include <math.h>
#include <stdint.h>

// ---------------------------------------------------------------------------
// Problem constants
// ---------------------------------------------------------------------------
#define B_   4
#define S_   1024
#define H_   1024
#define NH_  16
#define HD_  64
#define NREL 257   // 2*128+1
#define PTS  264   // padded Pt row stride (even, >= 263)
#define MTOT (B_ * S_)   // 4096

// ---------------------------------------------------------------------------
// Scratch (device globals — no cudaMalloc allowed)
// ---------------------------------------------------------------------------
__device__ float g_V[MTOT * H_];

__device__ __nv_bfloat16 g_xh[MTOT * H_];
__device__ __nv_bfloat16 g_xl[MTOT * H_];
__device__ __nv_bfloat16 g_Wqh[H_ * H_];
__device__ __nv_bfloat16 g_Wql[H_ * H_];
__device__ __nv_bfloat16 g_Wkh[H_ * H_];
__device__ __nv_bfloat16 g_Wkl[H_ * H_];
__device__ __nv_bfloat16 g_Wvh[H_ * H_];
__device__ __nv_bfloat16 g_Wvl[H_ * H_];
__device__ __nv_bfloat16 g_Woh[H_ * H_];
__device__ __nv_bfloat16 g_Wol[H_ * H_];
__device__ __nv_bfloat16 g_ah[MTOT * H_];
__device__ __nv_bfloat16 g_al[MTOT * H_];

__device__ __nv_bfloat16 g_Qh[MTOT * H_];
__device__ __nv_bfloat16 g_Ql[MTOT * H_];
__device__ __nv_bfloat16 g_Kh[MTOT * H_];
__device__ __nv_bfloat16 g_Kl[MTOT * H_];
__device__ __nv_bfloat16 g_Vth[MTOT * H_];   // [b][head][d][s]
__device__ __nv_bfloat16 g_Vtl[MTOT * H_];
__device__ __nv_bfloat16 g_relB[NREL * HD_]; // bf16 copy of rel_emb [r][d]

// ---------------------------------------------------------------------------
// Helpers
// ---------------------------------------------------------------------------
__device__ __forceinline__ uint32_t smem_u32(const void* p) {
    uint32_t a;
    asm("{ .reg .u64 t; cvta.to.shared.u64 t, %1; cvt.u32.u64 %0, t; }"
        : "=r"(a) : "l"(p));
    return a;
}

#define CP16(dst_u32, src_ptr) \
    asm volatile("cp.async.cg.shared.global [%0], [%1], 16;" \
        :: "r"(dst_u32), "l"(src_ptr))

__device__ __forceinline__ void mma16816(float* c,
    uint32_t a0, uint32_t a1, uint32_t a2, uint32_t a3, uint32_t b0, uint32_t b1)
{
    asm volatile(
        "mma.sync.aligned.m16n8k16.row.col.f32.bf16.bf16.f32 "
        "{%0,%1,%2,%3}, {%4,%5,%6,%7}, {%8,%9}, {%0,%1,%2,%3};\n"
        : "+f"(c[0]), "+f"(c[1]), "+f"(c[2]), "+f"(c[3])
        : "r"(a0), "r"(a1), "r"(a2), "r"(a3), "r"(b0), "r"(b1));
}

// Swizzled offset within a tile of 64-byte rows (32 bf16). For GEMM.
__device__ __forceinline__ uint32_t swz(int row, int kbyte)
{
    return (uint32_t)(row * 64 + ((((kbyte >> 4) ^ ((row >> 1) & 3)) << 4) | (kbyte & 15)));
}
__device__ __forceinline__ uint32_t lds32(const uint8_t* base, int row, int kbyte)
{
    return *(const uint32_t*)(base + swz(row, kbyte));
}

// Swizzled offset within a tile of 128-byte rows (64 bf16). For attention.
__device__ __forceinline__ uint32_t swzb(int row, int kbyte)
{
    return (uint32_t)(row * 128 + ((((kbyte >> 4) ^ (row & 7)) << 4) | (kbyte & 15)));
}
__device__ __forceinline__ uint32_t lds32b(const uint8_t* base, int row, int kbyte)
{
    return *(const uint32_t*)(base + swzb(row, kbyte));
}

// Pack two fp32 into bf16x2 hi word + residual lo word.
__device__ __forceinline__ void pack_hl(float x0, float x1, uint32_t& h, uint32_t& l)
{
    asm("cvt.rn.bf16x2.f32 %0, %1, %2;" : "=r"(h) : "f"(x1), "f"(x0));
    float f0 = __uint_as_float(h << 16);
    float f1 = __uint_as_float(h & 0xffff0000u);
    float r0 = x0 - f0, r1 = x1 - f1;
    asm("cvt.rn.bf16x2.f32 %0, %1, %2;" : "=r"(l) : "f"(r1), "f"(r0));
}

__device__ __forceinline__ uint32_t pack_h(float x0, float x1)
{
    uint32_t h;
    asm("cvt.rn.bf16x2.f32 %0, %1, %2;" : "=r"(h) : "f"(x1), "f"(x0));
    return h;
}

// ---------------------------------------------------------------------------
// Fused split: x, Wq, Wk, Wv, Wo -> bf16 hi/lo; rel_emb -> bf16 (hi only).
// Grid = 4096 (x: 1M float4) + 4*1024 (weights: 256K float4 each) + 17 (rel).
// ---------------------------------------------------------------------------
#define SPLIT_BLOCKS (4096 + 4096 + 17)

__global__ __launch_bounds__(256) void split_all(
    const float4* __restrict__ x,  uint2* __restrict__ xh,  uint2* __restrict__ xl,
    const float4* __restrict__ Wq, uint2* __restrict__ wqh, uint2* __restrict__ wql,
    const float4* __restrict__ Wk, uint2* __restrict__ wkh, uint2* __restrict__ wkl,
    const float4* __restrict__ Wv, uint2* __restrict__ wvh, uint2* __restrict__ wvl,
    const float4* __restrict__ Wo, uint2* __restrict__ woh, uint2* __restrict__ wol,
    const float4* __restrict__ rel4, uint2* __restrict__ relB4)
{
    const int bx = blockIdx.x;
    const int tid = threadIdx.x;

    if (bx < 8192) {
        const float4* src;
        uint2 *hi, *lo;
        int i;
        if (bx < 4096) {
            src = x; hi = xh; lo = xl;
            i = bx * 256 + tid;              // covers 4096*256 = 1M float4
        } else {
            int wsel = (bx - 4096) >> 10;    // 1024 blocks per weight
            src = (wsel == 0) ? Wq : (wsel == 1) ? Wk : (wsel == 2) ? Wv : Wo;
            hi  = (wsel == 0) ? wqh : (wsel == 1) ? wkh : (wsel == 2) ? wvh : woh;
            lo  = (wsel == 0) ? wql : (wsel == 1) ? wkl : (wsel == 2) ? wvl : wol;
            i = ((bx - 4096) & 1023) * 256 + tid;   // covers 256K float4
        }
        float4 v = src[i];
        uint32_t h0, l0, h1, l1;
        pack_hl(v.x, v.y, h0, l0);
        pack_hl(v.z, v.w, h1, l1);
        hi[i] = make_uint2(h0, h1);
        lo[i] = make_uint2(l0, l1);
    } else {
        int i = (bx - 8192) * 256 + tid;
        if (i < (NREL * HD_ / 4)) {
            float4 v = rel4[i];
            relB4[i] = make_uint2(pack_h(v.x, v.y), pack_h(v.z, v.w));
        }
    }
}

// ---------------------------------------------------------------------------
// Transpose + split V: [b,s,head*64+d] fp32 -> [b,head,d,s] bf16 hi/lo
// ---------------------------------------------------------------------------
__global__ __launch_bounds__(256) void vtrans_kernel(
    const float* __restrict__ V, __nv_bfloat16* __restrict__ Vth,
    __nv_bfloat16* __restrict__ Vtl)
{
    __shared__ float t[64][68];
    const int s0 = blockIdx.x * 64;
    const int n = blockIdx.y;
    const int b = blockIdx.z;
    const int tid = threadIdx.x;

    for (int idx = tid; idx < 1024; idx += 256) {
        int row = idx >> 4, c4 = idx & 15;
        float4 v = *(const float4*)&V[((size_t)(b * S_) + s0 + row) * H_ + n * HD_ + c4 * 4];
        *(float4*)&t[row][c4 * 4] = v;
    }
    __syncthreads();
    for (int idx = tid; idx < 1024; idx += 256) {
        int d = idx >> 4, sg = idx & 15;
        float v0 = t[sg * 4 + 0][d];
        float v1 = t[sg * 4 + 1][d];
        float v2 = t[sg * 4 + 2][d];
        float v3 = t[sg * 4 + 3][d];
        uint32_t h0, l0, h1, l1;
        pack_hl(v0, v1, h0, l0);
        pack_hl(v2, v3, h1, l1);
        size_t o = ((size_t)((b * NH_ + n) * HD_) + d) * S_ + s0 + sg * 4;
        *(uint2*)(Vth + o) = make_uint2(h0, h1);
        *(uint2*)(Vtl + o) = make_uint2(l0, l1);
    }
}

// ---------------------------------------------------------------------------
// Fused QKV GEMM (gridDim.z = 3 selects weight/output set).
// C = x @ W^T + bias; z=0 -> Qh/Ql (bf16 split), z=1 -> Kh/Kl, z=2 -> V fp32.
// cp.async double-buffered, 128x128x32 tiles, 256 threads.
// ---------------------------------------------------------------------------
#define GEMM_SMEM 65536

__global__ __launch_bounds__(256) void gemm_qkv(
    const __nv_bfloat16* __restrict__ Ahg, const __nv_bfloat16* __restrict__ Alg,
    const __nv_bfloat16* __restrict__ Wqh, const __nv_bfloat16* __restrict__ Wql,
    const float* __restrict__ bq, __nv_bfloat16* __restrict__ Qh, __nv_bfloat16* __restrict__ Ql,
    const __nv_bfloat16* __restrict__ Wkh, const __nv_bfloat16* __restrict__ Wkl,
    const float* __restrict__ bk, __nv_bfloat16* __restrict__ Kh, __nv_bfloat16* __restrict__ Kl,
    const __nv_bfloat16* __restrict__ Wvh, const __nv_bfloat16* __restrict__ Wvl,
    const float* __restrict__ bv, float* __restrict__ V)
{
    extern __shared__ __align__(16) uint8_t gsm[];
    const uint32_t sb = smem_u32(gsm);

    const int z = blockIdx.z;
    const __nv_bfloat16* Bhg = (z == 0) ? Wqh : (z == 1) ? Wkh : Wvh;
    const __nv_bfloat16* Blg = (z == 0) ? Wql : (z == 1) ? Wkl : Wvl;
    const float* bias = (z == 0) ? bq : (z == 1) ? bk : bv;

    const int tid = threadIdx.x;
    const int lane = tid & 31;
    const int wid = tid >> 5;
    const int warp_m = wid >> 1;
    const int warp_n = wid & 1;
    const int m0 = blockIdx.y * 128;
    const int n0 = blockIdx.x * 128;
    const int g = lane >> 2;
    const int t4 = lane & 3;

    float acc[2][8][4];
#pragma unroll
    for (int mt = 0; mt < 2; mt++)
#pragma unroll
        for (int nt = 0; nt < 8; nt++)
#pragma unroll
            for (int i = 0; i < 4; i++) acc[mt][nt][i] = 0.f;

    auto issue = [&](int kt, int buf) {
#pragma unroll
        for (int l = 0; l < 2; l++) {
            int s2 = tid + l * 256;
            int row = s2 >> 2;
            int seg = s2 & 3;
            uint32_t soff = (uint32_t)(buf * 32768 + row * 64 + ((seg ^ ((row >> 1) & 3)) << 4));
            size_t ga = (size_t)(m0 + row) * H_ + kt * 32 + seg * 8;
            size_t gb = (size_t)(n0 + row) * H_ + kt * 32 + seg * 8;
            CP16(sb + soff,         Ahg + ga);
            CP16(sb + soff + 8192,  Alg + ga);
            CP16(sb + soff + 16384, Bhg + gb);
            CP16(sb + soff + 24576, Blg + gb);
        }
    };

    issue(0, 0);
    asm volatile("cp.async.commit_group;");

#pragma unroll 1
    for (int kt = 0; kt < 32; kt++) {
        const int cur = kt & 1;
        if (kt < 31) {
            issue(kt + 1, cur ^ 1);
            asm volatile("cp.async.commit_group;");
            asm volatile("cp.async.wait_group 1;");
        } else {
            asm volatile("cp.async.wait_group 0;");
        }
        __syncthreads();

        const uint8_t* bAh = gsm + cur * 32768;
        const uint8_t* bAl = bAh + 8192;
        const uint8_t* bBh = bAh + 16384;
        const uint8_t* bBl = bAh + 24576;

#pragma unroll
        for (int kk = 0; kk < 64; kk += 32) {
            const int kb = kk + t4 * 4;
            uint32_t ah[2][4], al[2][4];
#pragma unroll
            for (int mt = 0; mt < 2; mt++) {
                int r = warp_m * 32 + mt * 16 + g;
                ah[mt][0] = lds32(bAh, r, kb);
                ah[mt][1] = lds32(bAh, r + 8, kb);
                ah[mt][2] = lds32(bAh, r, kb + 16);
                ah[mt][3] = lds32(bAh, r + 8, kb + 16);
                al[mt][0] = lds32(bAl, r, kb);
                al[mt][1] = lds32(bAl, r + 8, kb);
                al[mt][2] = lds32(bAl, r, kb + 16);
                al[mt][3] = lds32(bAl, r + 8, kb + 16);
            }
#pragma unroll
            for (int nt = 0; nt < 8; nt++) {
                int n = warp_n * 64 + nt * 8 + g;
                uint32_t bh0 = lds32(bBh, n, kb);
                uint32_t bh1 = lds32(bBh, n, kb + 16);
                uint32_t bl0 = lds32(bBl, n, kb);
                uint32_t bl1 = lds32(bBl, n, kb + 16);
#pragma unroll
                for (int mt = 0; mt < 2; mt++) {
                    mma16816(acc[mt][nt], ah[mt][0], ah[mt][1], ah[mt][2], ah[mt][3], bh0, bh1);
                    mma16816(acc[mt][nt], ah[mt][0], ah[mt][1], ah[mt][2], ah[mt][3], bl0, bl1);
                    mma16816(acc[mt][nt], al[mt][0], al[mt][1], al[mt][2], al[mt][3], bh0, bh1);
                }
            }
        }
        __syncthreads();
    }

    __nv_bfloat16* Oh = (z == 0) ? Qh : Kh;
    __nv_bfloat16* Ol = (z == 0) ? Ql : Kl;
#pragma unroll
    for (int mt = 0; mt < 2; mt++) {
        int row = m0 + warp_m * 32 + mt * 16 + g;
#pragma unroll
        for (int nt = 0; nt < 8; nt++) {
            int col = n0 + warp_n * 64 + nt * 8 + t4 * 2;
            float2 bv2 = *(const float2*)&bias[col];
            float v0 = acc[mt][nt][0] + bv2.x, v1 = acc[mt][nt][1] + bv2.y;
            float v2 = acc[mt][nt][2] + bv2.x, v3 = acc[mt][nt][3] + bv2.y;
            if (z == 2) {
                *(float2*)&V[(size_t)row * H_ + col] = make_float2(v0, v1);
                *(float2*)&V[(size_t)(row + 8) * H_ + col] = make_float2(v2, v3);
            } else {
                uint32_t h0, l0, h1, l1;
                pack_hl(v0, v1, h0, l0);
                pack_hl(v2, v3, h1, l1);
                *(uint32_t*)(Oh + (size_t)row * H_ + col) = h0;
                *(uint32_t*)(Ol + (size_t)row * H_ + col) = l0;
                *(uint32_t*)(Oh + (size_t)(row + 8) * H_ + col) = h1;
                *(uint32_t*)(Ol + (size_t)(row + 8) * H_ + col) = l1;
            }
        }
    }
}

// ---------------------------------------------------------------------------
// Final output GEMM (fp32 epilogue): out = A @ Wo^T + bo
// ---------------------------------------------------------------------------
__global__ __launch_bounds__(256) void gemm_mma(
    const __nv_bfloat16* __restrict__ Ahg, const __nv_bfloat16* __restrict__ Alg,
    const __nv_bfloat16* __restrict__ Bhg, const __nv_bfloat16* __restrict__ Blg,
    const float* __restrict__ bias, float* __restrict__ C)
{
    extern __shared__ __align__(16) uint8_t gsm[];
    const uint32_t sb = smem_u32(gsm);

    const int tid = threadIdx.x;
    const int lane = tid & 31;
    const int wid = tid >> 5;
    const int warp_m = wid >> 1;
    const int warp_n = wid & 1;
    const int m0 = blockIdx.y * 128;
    const int n0 = blockIdx.x * 128;
    const int g = lane >> 2;
    const int t4 = lane & 3;

    float acc[2][8][4];
#pragma unroll
    for (int mt = 0; mt < 2; mt++)
#pragma unroll
        for (int nt = 0; nt < 8; nt++)
#pragma unroll
            for (int i = 0; i < 4; i++) acc[mt][nt][i] = 0.f;

    auto issue = [&](int kt, int buf) {
#pragma unroll
        for (int l = 0; l < 2; l++) {
            int s2 = tid + l * 256;
            int row = s2 >> 2;
            int seg = s2 & 3;
            uint32_t soff = (uint32_t)(buf * 32768 + row * 64 + ((seg ^ ((row >> 1) & 3)) << 4));
            size_t ga = (size_t)(m0 + row) * H_ + kt * 32 + seg * 8;
            size_t gb = (size_t)(n0 + row) * H_ + kt * 32 + seg * 8;
            CP16(sb + soff,         Ahg + ga);
            CP16(sb + soff + 8192,  Alg + ga);
            CP16(sb + soff + 16384, Bhg + gb);
            CP16(sb + soff + 24576, Blg + gb);
        }
    };

    issue(0, 0);
    asm volatile("cp.async.commit_group;");

#pragma unroll 1
    for (int kt = 0; kt < 32; kt++) {
        const int cur = kt & 1;
        if (kt < 31) {
            issue(kt + 1, cur ^ 1);
            asm volatile("cp.async.commit_group;");
            asm volatile("cp.async.wait_group 1;");
        } else {
            asm volatile("cp.async.wait_group 0;");
        }
        __syncthreads();

        const uint8_t* bAh = gsm + cur * 32768;
        const uint8_t* bAl = bAh + 8192;
        const uint8_t* bBh = bAh + 16384;
        const uint8_t* bBl = bAh + 24576;

#pragma unroll
        for (int kk = 0; kk < 64; kk += 32) {
            const int kb = kk + t4 * 4;
            uint32_t ah[2][4], al[2][4];
#pragma unroll
            for (int mt = 0; mt < 2; mt++) {
                int r = warp_m * 32 + mt * 16 + g;
                ah[mt][0] = lds32(bAh, r, kb);
                ah[mt][1] = lds32(bAh, r + 8, kb);
                ah[mt][2] = lds32(bAh, r, kb + 16);
                ah[mt][3] = lds32(bAh, r + 8, kb + 16);
                al[mt][0] = lds32(bAl, r, kb);
                al[mt][1] = lds32(bAl, r + 8, kb);
                al[mt][2] = lds32(bAl, r, kb + 16);
                al[mt][3] = lds32(bAl, r + 8, kb + 16);
            }
#pragma unroll
            for (int nt = 0; nt < 8; nt++) {
                int n = warp_n * 64 + nt * 8 + g;
                uint32_t bh0 = lds32(bBh, n, kb);
                uint32_t bh1 = lds32(bBh, n, kb + 16);
                uint32_t bl0 = lds32(bBl, n, kb);
                uint32_t bl1 = lds32(bBl, n, kb + 16);
#pragma unroll
                for (int mt = 0; mt < 2; mt++) {
                    mma16816(acc[mt][nt], ah[mt][0], ah[mt][1], ah[mt][2], ah[mt][3], bh0, bh1);
                    mma16816(acc[mt][nt], ah[mt][0], ah[mt][1], ah[mt][2], ah[mt][3], bl0, bl1);
                    mma16816(acc[mt][nt], al[mt][0], al[mt][1], al[mt][2], al[mt][3], bh0, bh1);
                }
            }
        }
        __syncthreads();
    }

#pragma unroll
    for (int mt = 0; mt < 2; mt++) {
        int row = m0 + warp_m * 32 + mt * 16 + g;
#pragma unroll
        for (int nt = 0; nt < 8; nt++) {
            int col = n0 + warp_n * 64 + nt * 8 + t4 * 2;
            float2 bv = *(const float2*)&bias[col];
            float2 o0, o1;
            o0.x = acc[mt][nt][0] + bv.x; o0.y = acc[mt][nt][1] + bv.y;
            o1.x = acc[mt][nt][2] + bv.x; o1.y = acc[mt][nt][3] + bv.y;
            *(float2*)&C[(size_t)row * H_ + col] = o0;
            *(float2*)&C[(size_t)(row + 8) * H_ + col] = o1;
        }
    }
}

// ---------------------------------------------------------------------------
// Tensor-core flash attention. 128 threads / 4 warps; q-tile 64; k-tiles 64.
// Pt bias table computed by MMA (resident Qh frags x relB). PtB overlays the
// dead Q tile. smem = PtB 33792 + 2 stages x 32768 = 99328 B -> 2 CTAs/SM.
// ---------------------------------------------------------------------------
#define AAT_PT 0
#define AAT_ST 33792
#define ATTN_SMEM (33792 + 65536)

__global__ __launch_bounds__(128) void attn_mma(
    const __nv_bfloat16* __restrict__ Qh, const __nv_bfloat16* __restrict__ Ql,
    const __nv_bfloat16* __restrict__ Kh, const __nv_bfloat16* __restrict__ Kl,
    const __nv_bfloat16* __restrict__ Vth, const __nv_bfloat16* __restrict__ Vtl,
    const __nv_bfloat16* __restrict__ relB,
    __nv_bfloat16* __restrict__ Aout_h, __nv_bfloat16* __restrict__ Aout_l)
{
    extern __shared__ __align__(16) uint8_t dynsm[];
    const uint32_t sbase = smem_u32(dynsm);
    uint8_t* sQh = dynsm;              // temporary, inside PtB region
    uint8_t* sQl = dynsm + 8192;
    __nv_bfloat16* PtB = (__nv_bfloat16*)(dynsm + AAT_PT);

    const int b  = blockIdx.z;
    const int n  = blockIdx.y;
    const int q0 = blockIdx.x * 64;
    const int tid = threadIdx.x;
    const int lane = tid & 31;
    const int w = tid >> 5;
    const int g = lane >> 2;
    const int t4 = lane & 3;

    const __nv_bfloat16* Vhb = Vth + (size_t)((b * NH_ + n) * HD_) * S_;
    const __nv_bfloat16* Vlb = Vtl + (size_t)((b * NH_ + n) * HD_) * S_;

    auto issue_kv = [&](int kt, int buf) {
        const int k0 = kt * 64;
        const uint32_t st = sbase + AAT_ST + buf * 32768;
#pragma unroll
        for (int l = 0; l < 4; l++) {
            int idx = tid + l * 128;
            int row = idx >> 3, seg = idx & 7;
            uint32_t off = (uint32_t)(row * 128 + ((seg ^ (row & 7)) << 4));
            size_t gk = ((size_t)(b * S_) + k0 + row) * H_ + n * HD_ + seg * 8;
            size_t gv = (size_t)row * S_ + k0 + seg * 8;
            CP16(st + off,         Kh + gk);
            CP16(st + off + 8192,  Kl + gk);
            CP16(st + off + 16384, Vhb + gv);
            CP16(st + off + 24576, Vlb + gv);
        }
    };

    // Q tile -> smem (temporary, in PtB region)
    for (int idx = tid; idx < 512; idx += 128) {
        int row = idx >> 3, seg = idx & 7;
        uint32_t off = (uint32_t)(row * 128 + ((seg ^ (row & 7)) << 4));
        size_t gq = ((size_t)(b * S_) + q0 + row) * H_ + n * HD_ + seg * 8;
        *(uint4*)(sQh + off) = *(const uint4*)(Qh + gq);
        *(uint4*)(sQl + off) = *(const uint4*)(Ql + gq);
    }

    // Prefetch first K/V tile
    issue_kv(0, 0);
    asm volatile("cp.async.commit_group;");
    __syncthreads();

    // Resident Q A-frags
    uint32_t qah[4][4], qal[4][4];
    {
        int r = 16 * w + g;
#pragma unroll
        for (int kb = 0; kb < 4; kb++) {
            int kbase = kb * 32 + t4 * 4;
            qah[kb][0] = lds32b(sQh, r, kbase);
            qah[kb][1] = lds32b(sQh, r + 8, kbase);
            qah[kb][2] = lds32b(sQh, r, kbase + 16);
            qah[kb][3] = lds32b(sQh, r + 8, kbase + 16);
            qal[kb][0] = lds32b(sQl, r, kbase);
            qal[kb][1] = lds32b(sQl, r + 8, kbase);
            qal[kb][2] = lds32b(sQl, r, kbase + 16);
            qal[kb][3] = lds32b(sQl, r + 8, kbase + 16);
        }
    }
    __syncthreads();   // Q smem dead; PtB may now overwrite it

    const int ql0 = 16 * w + g;
    const int qg0 = q0 + ql0;

    // Pt via MMA: Pt[q][r] = Qh[q] . relB[r]  (1-pass bf16, per-warp rows)
    {
#pragma unroll 4
        for (int j = 0; j < 33; j++) {
            int r = 8 * j + g;
            int rc = min(r, NREL - 1);
            const __nv_bfloat16* rb = relB + rc * HD_;
            float c[4] = {0.f, 0.f, 0.f, 0.f};
#pragma unroll
            for (int kb = 0; kb < 4; kb++) {
                uint32_t b0 = *(const uint32_t*)(rb + kb * 16 + 2 * t4);
                uint32_t b1 = *(const uint32_t*)(rb + kb * 16 + 2 * t4 + 8);
                mma16816(c, qah[kb][0], qah[kb][1], qah[kb][2], qah[kb][3], b0, b1);
            }
            int col = 8 * j + 2 * t4;
            *(uint32_t*)(PtB + ql0 * PTS + col) = pack_h(c[0], c[1]);
            *(uint32_t*)(PtB + (ql0 + 8) * PTS + col) = pack_h(c[2], c[3]);
        }
        __syncwarp();   // cross-lane smem dependency within warp
    }

    float oacc[8][4];
#pragma unroll
    for (int j = 0; j < 8; j++)
#pragma unroll
        for (int i = 0; i < 4; i++) oacc[j][i] = 0.f;
    float rmax0 = -INFINITY, rmax1 = -INFINITY;
    float rsum0 = 0.f, rsum1 = 0.f;

#pragma unroll 1
    for (int kt = 0; kt < 16; kt++) {
        const int k0 = kt * 64;
        const int cur = kt & 1;
        asm volatile("cp.async.wait_group 0;");
        __syncthreads();
        if (kt < 15) {
            issue_kv(kt + 1, cur ^ 1);
            asm volatile("cp.async.commit_group;");
        }

        const uint8_t* sKh = dynsm + AAT_ST + cur * 32768;
        const uint8_t* sKl = sKh + 8192;
        const uint8_t* sVh = sKh + 16384;
        const uint8_t* sVl = sKh + 24576;

        // QK^T
        float sc[8][4];
#pragma unroll
        for (int j = 0; j < 8; j++)
#pragma unroll
            for (int i = 0; i < 4; i++) sc[j][i] = 0.f;
#pragma unroll
        for (int kb = 0; kb < 4; kb++) {
            int kbase = kb * 32 + t4 * 4;
#pragma unroll
            for (int j = 0; j < 8; j++) {
                int krow = 8 * j + g;
                uint32_t bh0 = lds32b(sKh, krow, kbase);
                uint32_t bh1 = lds32b(sKh, krow, kbase + 16);
                uint32_t bl0 = lds32b(sKl, krow, kbase);
                uint32_t bl1 = lds32b(sKl, krow, kbase + 16);
                mma16816(sc[j], qah[kb][0], qah[kb][1], qah[kb][2], qah[kb][3], bh0, bh1);
                mma16816(sc[j], qah[kb][0], qah[kb][1], qah[kb][2], qah[kb][3], bl0, bl1);
                mma16816(sc[j], qal[kb][0], qal[kb][1], qal[kb][2], qal[kb][3], bh0, bh1);
            }
        }

        // Bias + scale
#pragma unroll
        for (int j = 0; j < 8; j++) {
            int col = k0 + 8 * j + 2 * t4;
            int r00 = min(128, max(-128, col     - qg0)) + 128;
            int r01 = min(128, max(-128, col + 1 - qg0)) + 128;
            int r10 = min(128, max(-128, col     - qg0 - 8)) + 128;
            int r11 = min(128, max(-128, col + 1 - qg0 - 8)) + 128;
            sc[j][0] = (sc[j][0] + __bfloat162float(PtB[ql0 * PTS + r00])) * 0.125f;
            sc[j][1] = (sc[j][1] + __bfloat162float(PtB[ql0 * PTS + r01])) * 0.125f;
            sc[j][2] = (sc[j][2] + __bfloat162float(PtB[(ql0 + 8) * PTS + r10])) * 0.125f;
            sc[j][3] = (sc[j][3] + __bfloat162float(PtB[(ql0 + 8) * PTS + r11])) * 0.125f;
        }

        // Online softmax
        float m0 = -INFINITY, m1 = -INFINITY;
#pragma unroll
        for (int j = 0; j < 8; j++) {
            m0 = fmaxf(m0, fmaxf(sc[j][0], sc[j][1]));
            m1 = fmaxf(m1, fmaxf(sc[j][2], sc[j][3]));
        }
        m0 = fmaxf(m0, __shfl_xor_sync(0xffffffffu, m0, 1, 4));
        m0 = fmaxf(m0, __shfl_xor_sync(0xffffffffu, m0, 2, 4));
        m1 = fmaxf(m1, __shfl_xor_sync(0xffffffffu, m1, 1, 4));
        m1 = fmaxf(m1, __shfl_xor_sync(0xffffffffu, m1, 2, 4));

        float nm0 = fmaxf(rmax0, m0);
        float nm1 = fmaxf(rmax1, m1);
        float esc0 = __expf(rmax0 - nm0);
        float esc1 = __expf(rmax1 - nm1);
        rmax0 = nm0; rmax1 = nm1;

        float s0 = 0.f, s1 = 0.f;
#pragma unroll
        for (int j = 0; j < 8; j++) {
            sc[j][0] = __expf(sc[j][0] - nm0);
            sc[j][1] = __expf(sc[j][1] - nm0);
            sc[j][2] = __expf(sc[j][2] - nm1);
            sc[j][3] = __expf(sc[j][3] - nm1);
            s0 += sc[j][0] + sc[j][1];
            s1 += sc[j][2] + sc[j][3];
        }
        s0 += __shfl_xor_sync(0xffffffffu, s0, 1, 4);
        s0 += __shfl_xor_sync(0xffffffffu, s0, 2, 4);
        s1 += __shfl_xor_sync(0xffffffffu, s1, 1, 4);
        s1 += __shfl_xor_sync(0xffffffffu, s1, 2, 4);
        rsum0 = rsum0 * esc0 + s0;
        rsum1 = rsum1 * esc1 + s1;

#pragma unroll
        for (int j = 0; j < 8; j++) {
            oacc[j][0] *= esc0; oacc[j][1] *= esc0;
            oacc[j][2] *= esc1; oacc[j][3] *= esc1;
        }

        // PV
#pragma unroll
        for (int kb = 0; kb < 4; kb++) {
            uint32_t ah0, ah1, ah2, ah3, al0, al1, al2, al3;
            pack_hl(sc[2 * kb][0], sc[2 * kb][1], ah0, al0);
            pack_hl(sc[2 * kb][2], sc[2 * kb][3], ah1, al1);
            pack_hl(sc[2 * kb + 1][0], sc[2 * kb + 1][1], ah2, al2);
            pack_hl(sc[2 * kb + 1][2], sc[2 * kb + 1][3], ah3, al3);
            int kbase = kb * 32 + t4 * 4;
#pragma unroll
            for (int j = 0; j < 8; j++) {
                int vrow = 8 * j + g;
                uint32_t bh0 = lds32b(sVh, vrow, kbase);
                uint32_t bh1 = lds32b(sVh, vrow, kbase + 16);
                uint32_t bl0 = lds32b(sVl, vrow, kbase);
                uint32_t bl1 = lds32b(sVl, vrow, kbase + 16);
                mma16816(oacc[j], ah0, ah1, ah2, ah3, bh0, bh1);
                mma16816(oacc[j], ah0, ah1, ah2, ah3, bl0, bl1);
                mma16816(oacc[j], al0, al1, al2, al3, bh0, bh1);
            }
        }
        __syncthreads();   // done reading cur buffer before next overwrite
    }

    // Epilogue: normalize + write bf16 hi/lo
    float inv0 = 1.f / rsum0;
    float inv1 = 1.f / rsum1;
    size_t base0 = ((size_t)b * S_ + q0 + 16 * w + g) * H_ + n * HD_;
    size_t base1 = base0 + 8 * H_;
#pragma unroll
    for (int j = 0; j < 8; j++) {
        int col = 8 * j + 2 * t4;
        uint32_t h0, l0, h1, l1;
        pack_hl(oacc[j][0] * inv0, oacc[j][1] * inv0, h0, l0);
        pack_hl(oacc[j][2] * inv1, oacc[j][3] * inv1, h1, l1);
        *(uint32_t*)(Aout_h + base0 + col) = h0;
        *(uint32_t*)(Aout_l + base0 + col) = l0;
        *(uint32_t*)(Aout_h + base1 + col) = h1;
        *(uint32_t*)(Aout_l + base1 + col) = l1;
    }
}

// ---------------------------------------------------------------------------
// Launch
// ---------------------------------------------------------------------------
extern "C" void kernel_launch(void* const* d_in, const int* in_sizes, int n_in,
                              void* d_out, int out_size)
{
    const float* x   = (const float*)d_in[0];
    const float* Wq  = (const float*)d_in[1];
    const float* bq  = (const float*)d_in[2];
    const float* Wk  = (const float*)d_in[3];
    const float* bk  = (const float*)d_in[4];
    const float* Wv  = (const float*)d_in[5];
    const float* bv  = (const float*)d_in[6];
    const float* Wo  = (const float*)d_in[7];
    const float* bo  = (const float*)d_in[8];
    const float* rel = (const float*)d_in[9];
    float* out = (float*)d_out;

    float* pV;
    __nv_bfloat16 *xh, *xl, *wqh, *wql, *wkh, *wkl, *wvh, *wvl, *woh, *wol, *ah, *al;
    __nv_bfloat16 *qh, *ql, *kh, *kl, *vth, *vtl, *relB;
    cudaGetSymbolAddress((void**)&pV, g_V);
    cudaGetSymbolAddress((void**)&xh, g_xh);
    cudaGetSymbolAddress((void**)&xl, g_xl);
    cudaGetSymbolAddress((void**)&wqh, g_Wqh);
    cudaGetSymbolAddress((void**)&wql, g_Wql);
    cudaGetSymbolAddress((void**)&wkh, g_Wkh);
    cudaGetSymbolAddress((void**)&wkl, g_Wkl);
    cudaGetSymbolAddress((void**)&wvh, g_Wvh);
    cudaGetSymbolAddress((void**)&wvl, g_Wvl);
    cudaGetSymbolAddress((void**)&woh, g_Woh);
    cudaGetSymbolAddress((void**)&wol, g_Wol);
    cudaGetSymbolAddress((void**)&ah, g_ah);
    cudaGetSymbolAddress((void**)&al, g_al);
    cudaGetSymbolAddress((void**)&qh, g_Qh);
    cudaGetSymbolAddress((void**)&ql, g_Ql);
    cudaGetSymbolAddress((void**)&kh, g_Kh);
    cudaGetSymbolAddress((void**)&kl, g_Kl);
    cudaGetSymbolAddress((void**)&vth, g_Vth);
    cudaGetSymbolAddress((void**)&vtl, g_Vtl);
    cudaGetSymbolAddress((void**)&relB, g_relB);

    cudaFuncSetAttribute(attn_mma, cudaFuncAttributeMaxDynamicSharedMemorySize, ATTN_SMEM);
    cudaFuncSetAttribute(gemm_mma, cudaFuncAttributeMaxDynamicSharedMemorySize, GEMM_SMEM);
    cudaFuncSetAttribute(gemm_qkv, cudaFuncAttributeMaxDynamicSharedMemorySize, GEMM_SMEM);

    // Fused splits: x (4096 blocks), 4 weights (1024 each), rel (17).
    split_all<<<SPLIT_BLOCKS, 256>>>(
        (const float4*)x,  (uint2*)xh,  (uint2*)xl,
        (const float4*)Wq, (uint2*)wqh, (uint2*)wql,
        (const float4*)Wk, (uint2*)wkh, (uint2*)wkl,
        (const float4*)Wv, (uint2*)wvh, (uint2*)wvl,
        (const float4*)Wo, (uint2*)woh, (uint2*)wol,
        (const float4*)rel, (uint2*)relB);

    dim3 qkv_grid(H_ / 128, MTOT / 128, 3);   // (8, 32, 3) = 768 blocks
    gemm_qkv<<<qkv_grid, 256, GEMM_SMEM>>>(xh, xl,
        wqh, wql, bq, qh, ql,
        wkh, wkl, bk, kh, kl,
        wvh, wvl, bv, pV);

    vtrans_kernel<<<dim3(S_ / 64, NH_, B_), 256>>>(pV, vth, vtl);

    dim3 attn_grid(S_ / 64, NH_, B_);
    attn_mma<<<attn_grid, 128, ATTN_SMEM>>>(qh, ql, kh, kl, vth, vtl, relB, ah, al);

    dim3 gemm_grid(H_ / 128, MTOT / 128);
    gemm_mma<<<gemm_grid, 256, GEMM_SMEM>>>(ah, al, woh, wol, bo, out);
}

// round 12
// speedup vs baseline: 12.8976x; 1.1256x over previous
#include <cuda_runtime.h>
#include <cuda_bf16.h>
#include <math.h>
#include <stdint.h>

// ---------------------------------------------------------------------------
// Problem constants
// ---------------------------------------------------------------------------
#define B_   4
#define S_   1024
#define H_   1024
#define NH_  16
#define HD_  64
#define NREL 257   // 2*128+1
#define PTS  264   // padded Pt row stride (even, >= 263)
#define MTOT (B_ * S_)   // 4096

// ---------------------------------------------------------------------------
// Scratch (device globals — no cudaMalloc allowed)
// ---------------------------------------------------------------------------
__device__ float g_V[MTOT * H_];

__device__ __nv_bfloat16 g_xh[MTOT * H_];
__device__ __nv_bfloat16 g_xl[MTOT * H_];
__device__ __nv_bfloat16 g_Wqh[H_ * H_];
__device__ __nv_bfloat16 g_Wql[H_ * H_];
__device__ __nv_bfloat16 g_Wkh[H_ * H_];
__device__ __nv_bfloat16 g_Wkl[H_ * H_];
__device__ __nv_bfloat16 g_Wvh[H_ * H_];
__device__ __nv_bfloat16 g_Wvl[H_ * H_];
__device__ __nv_bfloat16 g_Woh[H_ * H_];
__device__ __nv_bfloat16 g_Wol[H_ * H_];
__device__ __nv_bfloat16 g_ah[MTOT * H_];
__device__ __nv_bfloat16 g_al[MTOT * H_];

__device__ __nv_bfloat16 g_Qh[MTOT * H_];
__device__ __nv_bfloat16 g_Ql[MTOT * H_];
__device__ __nv_bfloat16 g_Kh[MTOT * H_];
__device__ __nv_bfloat16 g_Kl[MTOT * H_];
__device__ __nv_bfloat16 g_Vth[MTOT * H_];   // [b][head][d][s]
__device__ __nv_bfloat16 g_Vtl[MTOT * H_];
__device__ __nv_bfloat16 g_relB[NREL * HD_]; // bf16 copy of rel_emb [r][d]

// ---------------------------------------------------------------------------
// Helpers
// ---------------------------------------------------------------------------
__device__ __forceinline__ uint32_t smem_u32(const void* p) {
    uint32_t a;
    asm("{ .reg .u64 t; cvta.to.shared.u64 t, %1; cvt.u32.u64 %0, t; }"
        : "=r"(a) : "l"(p));
    return a;
}

#define CP16(dst_u32, src_ptr) \
    asm volatile("cp.async.cg.shared.global [%0], [%1], 16;" \
        :: "r"(dst_u32), "l"(src_ptr))

__device__ __forceinline__ void mma16816(float* c,
    uint32_t a0, uint32_t a1, uint32_t a2, uint32_t a3, uint32_t b0, uint32_t b1)
{
    asm volatile(
        "mma.sync.aligned.m16n8k16.row.col.f32.bf16.bf16.f32 "
        "{%0,%1,%2,%3}, {%4,%5,%6,%7}, {%8,%9}, {%0,%1,%2,%3};\n"
        : "+f"(c[0]), "+f"(c[1]), "+f"(c[2]), "+f"(c[3])
        : "r"(a0), "r"(a1), "r"(a2), "r"(a3), "r"(b0), "r"(b1));
}

__device__ __forceinline__ void ldsm_x4(uint32_t& r0, uint32_t& r1,
                                        uint32_t& r2, uint32_t& r3, uint32_t addr)
{
    asm volatile("ldmatrix.sync.aligned.m8n8.x4.shared.b16 {%0,%1,%2,%3}, [%4];"
                 : "=r"(r0), "=r"(r1), "=r"(r2), "=r"(r3) : "r"(addr));
}

// Swizzled offset, 64-byte rows (GEMM tiles); kbyte multiple of 16.
__device__ __forceinline__ uint32_t swz_u(uint32_t row, uint32_t kbyte)
{
    return row * 64 + ((((kbyte >> 4) ^ ((row >> 1) & 3)) << 4));
}
// Swizzled offset, 128-byte rows (attention tiles); kbyte multiple of 16.
__device__ __forceinline__ uint32_t swzb_u(uint32_t row, uint32_t kbyte)
{
    return row * 128 + ((((kbyte >> 4) ^ (row & 7)) << 4));
}
// Scalar variants (arbitrary kbyte)
__device__ __forceinline__ uint32_t swzb(int row, int kbyte)
{
    return (uint32_t)(row * 128 + ((((kbyte >> 4) ^ (row & 7)) << 4) | (kbyte & 15)));
}
__device__ __forceinline__ uint32_t lds32b(const uint8_t* base, int row, int kbyte)
{
    return *(const uint32_t*)(base + swzb(row, kbyte));
}

// Pack two fp32 into bf16x2 hi word + residual lo word.
__device__ __forceinline__ void pack_hl(float x0, float x1, uint32_t& h, uint32_t& l)
{
    asm("cvt.rn.bf16x2.f32 %0, %1, %2;" : "=r"(h) : "f"(x1), "f"(x0));
    float f0 = __uint_as_float(h << 16);
    float f1 = __uint_as_float(h & 0xffff0000u);
    float r0 = x0 - f0, r1 = x1 - f1;
    asm("cvt.rn.bf16x2.f32 %0, %1, %2;" : "=r"(l) : "f"(r1), "f"(r0));
}

__device__ __forceinline__ uint32_t pack_h(float x0, float x1)
{
    uint32_t h;
    asm("cvt.rn.bf16x2.f32 %0, %1, %2;" : "=r"(h) : "f"(x1), "f"(x0));
    return h;
}

// ---------------------------------------------------------------------------
// Fused split: x, Wq, Wk, Wv, Wo -> bf16 hi/lo; rel_emb -> bf16 (hi only).
// Grid = 4096 (x: 1M float4) + 4*1024 (weights: 256K float4 each) + 17 (rel).
// ---------------------------------------------------------------------------
#define SPLIT_BLOCKS (4096 + 4096 + 17)

__global__ __launch_bounds__(256) void split_all(
    const float4* __restrict__ x,  uint2* __restrict__ xh,  uint2* __restrict__ xl,
    const float4* __restrict__ Wq, uint2* __restrict__ wqh, uint2* __restrict__ wql,
    const float4* __restrict__ Wk, uint2* __restrict__ wkh, uint2* __restrict__ wkl,
    const float4* __restrict__ Wv, uint2* __restrict__ wvh, uint2* __restrict__ wvl,
    const float4* __restrict__ Wo, uint2* __restrict__ woh, uint2* __restrict__ wol,
    const float4* __restrict__ rel4, uint2* __restrict__ relB4)
{
    const int bx = blockIdx.x;
    const int tid = threadIdx.x;

    if (bx < 8192) {
        const float4* src;
        uint2 *hi, *lo;
        int i;
        if (bx < 4096) {
            src = x; hi = xh; lo = xl;
            i = bx * 256 + tid;
        } else {
            int wsel = (bx - 4096) >> 10;
            src = (wsel == 0) ? Wq : (wsel == 1) ? Wk : (wsel == 2) ? Wv : Wo;
            hi  = (wsel == 0) ? wqh : (wsel == 1) ? wkh : (wsel == 2) ? wvh : woh;
            lo  = (wsel == 0) ? wql : (wsel == 1) ? wkl : (wsel == 2) ? wvl : wol;
            i = ((bx - 4096) & 1023) * 256 + tid;
        }
        float4 v = src[i];
        uint32_t h0, l0, h1, l1;
        pack_hl(v.x, v.y, h0, l0);
        pack_hl(v.z, v.w, h1, l1);
        hi[i] = make_uint2(h0, h1);
        lo[i] = make_uint2(l0, l1);
    } else {
        int i = (bx - 8192) * 256 + tid;
        if (i < (NREL * HD_ / 4)) {
            float4 v = rel4[i];
            relB4[i] = make_uint2(pack_h(v.x, v.y), pack_h(v.z, v.w));
        }
    }
}

// ---------------------------------------------------------------------------
// Transpose + split V: [b,s,head*64+d] fp32 -> [b,head,d,s] bf16 hi/lo
// ---------------------------------------------------------------------------
__global__ __launch_bounds__(256) void vtrans_kernel(
    const float* __restrict__ V, __nv_bfloat16* __restrict__ Vth,
    __nv_bfloat16* __restrict__ Vtl)
{
    __shared__ float t[64][68];
    const int s0 = blockIdx.x * 64;
    const int n = blockIdx.y;
    const int b = blockIdx.z;
    const int tid = threadIdx.x;

    for (int idx = tid; idx < 1024; idx += 256) {
        int row = idx >> 4, c4 = idx & 15;
        float4 v = *(const float4*)&V[((size_t)(b * S_) + s0 + row) * H_ + n * HD_ + c4 * 4];
        *(float4*)&t[row][c4 * 4] = v;
    }
    __syncthreads();
    for (int idx = tid; idx < 1024; idx += 256) {
        int d = idx >> 4, sg = idx & 15;
        float v0 = t[sg * 4 + 0][d];
        float v1 = t[sg * 4 + 1][d];
        float v2 = t[sg * 4 + 2][d];
        float v3 = t[sg * 4 + 3][d];
        uint32_t h0, l0, h1, l1;
        pack_hl(v0, v1, h0, l0);
        pack_hl(v2, v3, h1, l1);
        size_t o = ((size_t)((b * NH_ + n) * HD_) + d) * S_ + s0 + sg * 4;
        *(uint2*)(Vth + o) = make_uint2(h0, h1);
        *(uint2*)(Vtl + o) = make_uint2(l0, l1);
    }
}

// ---------------------------------------------------------------------------
// GEMM mainloop body (shared by gemm_qkv / gemm_mma) via macro-free inline:
// cp.async double-buffered, 128x128x32 tiles, 256 threads, ldmatrix frags.
// ---------------------------------------------------------------------------
#define GEMM_SMEM 65536

__device__ __forceinline__ void gemm_core(
    const __nv_bfloat16* Ahg, const __nv_bfloat16* Alg,
    const __nv_bfloat16* Bhg, const __nv_bfloat16* Blg,
    uint8_t* gsm, uint32_t sb, int m0, int n0,
    int warp_m, int warp_n, int lane, int tid, float acc[2][8][4])
{
    auto issue = [&](int kt, int buf) {
#pragma unroll
        for (int l = 0; l < 2; l++) {
            int s2 = tid + l * 256;
            int row = s2 >> 2;
            int seg = s2 & 3;
            uint32_t soff = (uint32_t)(buf * 32768 + row * 64 + ((seg ^ ((row >> 1) & 3)) << 4));
            size_t ga = (size_t)(m0 + row) * H_ + kt * 32 + seg * 8;
            size_t gb = (size_t)(n0 + row) * H_ + kt * 32 + seg * 8;
            CP16(sb + soff,         Ahg + ga);
            CP16(sb + soff + 8192,  Alg + ga);
            CP16(sb + soff + 16384, Bhg + gb);
            CP16(sb + soff + 24576, Blg + gb);
        }
    };

    const int mmi = lane >> 3;
    const int rr = lane & 7;

    issue(0, 0);
    asm volatile("cp.async.commit_group;");

#pragma unroll 1
    for (int kt = 0; kt < 32; kt++) {
        const int cur = kt & 1;
        if (kt < 31) {
            issue(kt + 1, cur ^ 1);
            asm volatile("cp.async.commit_group;");
            asm volatile("cp.async.wait_group 1;");
        } else {
            asm volatile("cp.async.wait_group 0;");
        }
        __syncthreads();

        const uint32_t uAh = sb + cur * 32768;
        const uint32_t uAl = uAh + 8192;
        const uint32_t uBh = uAh + 16384;
        const uint32_t uBl = uAh + 24576;

#pragma unroll
        for (int kk = 0; kk < 64; kk += 32) {
            uint32_t ah[2][4], al[2][4];
#pragma unroll
            for (int mt = 0; mt < 2; mt++) {
                uint32_t arow = warp_m * 32 + mt * 16 + ((mmi & 1) << 3) + rr;
                uint32_t abyte = kk + ((mmi >> 1) << 4);
                uint32_t aoff = swz_u(arow, abyte);
                ldsm_x4(ah[mt][0], ah[mt][1], ah[mt][2], ah[mt][3], uAh + aoff);
                ldsm_x4(al[mt][0], al[mt][1], al[mt][2], al[mt][3], uAl + aoff);
            }
#pragma unroll
            for (int p = 0; p < 4; p++) {
                uint32_t brow = warp_n * 64 + 16 * p + ((mmi >> 1) << 3) + rr;
                uint32_t bbyte = kk + ((mmi & 1) << 4);
                uint32_t boff = swz_u(brow, bbyte);
                uint32_t bh0, bh1, bh2, bh3, bl0, bl1, bl2, bl3;
                ldsm_x4(bh0, bh1, bh2, bh3, uBh + boff);
                ldsm_x4(bl0, bl1, bl2, bl3, uBl + boff);
#pragma unroll
                for (int mt = 0; mt < 2; mt++) {
                    mma16816(acc[mt][2 * p], ah[mt][0], ah[mt][1], ah[mt][2], ah[mt][3], bh0, bh1);
                    mma16816(acc[mt][2 * p], ah[mt][0], ah[mt][1], ah[mt][2], ah[mt][3], bl0, bl1);
                    mma16816(acc[mt][2 * p], al[mt][0], al[mt][1], al[mt][2], al[mt][3], bh0, bh1);
                    mma16816(acc[mt][2 * p + 1], ah[mt][0], ah[mt][1], ah[mt][2], ah[mt][3], bh2, bh3);
                    mma16816(acc[mt][2 * p + 1], ah[mt][0], ah[mt][1], ah[mt][2], ah[mt][3], bl2, bl3);
                    mma16816(acc[mt][2 * p + 1], al[mt][0], al[mt][1], al[mt][2], al[mt][3], bh2, bh3);
                }
            }
        }
        __syncthreads();
    }
}

// ---------------------------------------------------------------------------
// Fused QKV GEMM (gridDim.z = 3): z=0 -> Qh/Ql, z=1 -> Kh/Kl, z=2 -> V fp32.
// ---------------------------------------------------------------------------
__global__ __launch_bounds__(256) void gemm_qkv(
    const __nv_bfloat16* __restrict__ Ahg, const __nv_bfloat16* __restrict__ Alg,
    const __nv_bfloat16* __restrict__ Wqh, const __nv_bfloat16* __restrict__ Wql,
    const float* __restrict__ bq, __nv_bfloat16* __restrict__ Qh, __nv_bfloat16* __restrict__ Ql,
    const __nv_bfloat16* __restrict__ Wkh, const __nv_bfloat16* __restrict__ Wkl,
    const float* __restrict__ bk, __nv_bfloat16* __restrict__ Kh, __nv_bfloat16* __restrict__ Kl,
    const __nv_bfloat16* __restrict__ Wvh, const __nv_bfloat16* __restrict__ Wvl,
    const float* __restrict__ bv, float* __restrict__ V)
{
    extern __shared__ __align__(16) uint8_t gsm[];
    const uint32_t sb = smem_u32(gsm);

    const int z = blockIdx.z;
    const __nv_bfloat16* Bhg = (z == 0) ? Wqh : (z == 1) ? Wkh : Wvh;
    const __nv_bfloat16* Blg = (z == 0) ? Wql : (z == 1) ? Wkl : Wvl;
    const float* bias = (z == 0) ? bq : (z == 1) ? bk : bv;

    const int tid = threadIdx.x;
    const int lane = tid & 31;
    const int wid = tid >> 5;
    const int warp_m = wid >> 1;
    const int warp_n = wid & 1;
    const int m0 = blockIdx.y * 128;
    const int n0 = blockIdx.x * 128;
    const int g = lane >> 2;
    const int t4 = lane & 3;

    float acc[2][8][4];
#pragma unroll
    for (int mt = 0; mt < 2; mt++)
#pragma unroll
        for (int nt = 0; nt < 8; nt++)
#pragma unroll
            for (int i = 0; i < 4; i++) acc[mt][nt][i] = 0.f;

    gemm_core(Ahg, Alg, Bhg, Blg, gsm, sb, m0, n0, warp_m, warp_n, lane, tid, acc);

    __nv_bfloat16* Oh = (z == 0) ? Qh : Kh;
    __nv_bfloat16* Ol = (z == 0) ? Ql : Kl;
#pragma unroll
    for (int mt = 0; mt < 2; mt++) {
        int row = m0 + warp_m * 32 + mt * 16 + g;
#pragma unroll
        for (int nt = 0; nt < 8; nt++) {
            int col = n0 + warp_n * 64 + nt * 8 + t4 * 2;
            float2 bv2 = *(const float2*)&bias[col];
            float v0 = acc[mt][nt][0] + bv2.x, v1 = acc[mt][nt][1] + bv2.y;
            float v2 = acc[mt][nt][2] + bv2.x, v3 = acc[mt][nt][3] + bv2.y;
            if (z == 2) {
                *(float2*)&V[(size_t)row * H_ + col] = make_float2(v0, v1);
                *(float2*)&V[(size_t)(row + 8) * H_ + col] = make_float2(v2, v3);
            } else {
                uint32_t h0, l0, h1, l1;
                pack_hl(v0, v1, h0, l0);
                pack_hl(v2, v3, h1, l1);
                *(uint32_t*)(Oh + (size_t)row * H_ + col) = h0;
                *(uint32_t*)(Ol + (size_t)row * H_ + col) = l0;
                *(uint32_t*)(Oh + (size_t)(row + 8) * H_ + col) = h1;
                *(uint32_t*)(Ol + (size_t)(row + 8) * H_ + col) = l1;
            }
        }
    }
}

// ---------------------------------------------------------------------------
// Final output GEMM (fp32 epilogue): out = A @ Wo^T + bo
// ---------------------------------------------------------------------------
__global__ __launch_bounds__(256) void gemm_mma(
    const __nv_bfloat16* __restrict__ Ahg, const __nv_bfloat16* __restrict__ Alg,
    const __nv_bfloat16* __restrict__ Bhg, const __nv_bfloat16* __restrict__ Blg,
    const float* __restrict__ bias, float* __restrict__ C)
{
    extern __shared__ __align__(16) uint8_t gsm[];
    const uint32_t sb = smem_u32(gsm);

    const int tid = threadIdx.x;
    const int lane = tid & 31;
    const int wid = tid >> 5;
    const int warp_m = wid >> 1;
    const int warp_n = wid & 1;
    const int m0 = blockIdx.y * 128;
    const int n0 = blockIdx.x * 128;
    const int g = lane >> 2;
    const int t4 = lane & 3;

    float acc[2][8][4];
#pragma unroll
    for (int mt = 0; mt < 2; mt++)
#pragma unroll
        for (int nt = 0; nt < 8; nt++)
#pragma unroll
            for (int i = 0; i < 4; i++) acc[mt][nt][i] = 0.f;

    gemm_core(Ahg, Alg, Bhg, Blg, gsm, sb, m0, n0, warp_m, warp_n, lane, tid, acc);

#pragma unroll
    for (int mt = 0; mt < 2; mt++) {
        int row = m0 + warp_m * 32 + mt * 16 + g;
#pragma unroll
        for (int nt = 0; nt < 8; nt++) {
            int col = n0 + warp_n * 64 + nt * 8 + t4 * 2;
            float2 bv = *(const float2*)&bias[col];
            float2 o0, o1;
            o0.x = acc[mt][nt][0] + bv.x; o0.y = acc[mt][nt][1] + bv.y;
            o1.x = acc[mt][nt][2] + bv.x; o1.y = acc[mt][nt][3] + bv.y;
            *(float2*)&C[(size_t)row * H_ + col] = o0;
            *(float2*)&C[(size_t)(row + 8) * H_ + col] = o1;
        }
    }
}

// ---------------------------------------------------------------------------
// Tensor-core flash attention. 128 threads / 4 warps; q-tile 64; k-tiles 64.
// ldmatrix fragment loads; Pt via MMA; PtB overlays dead Q tile.
// smem = PtB 33792 + 2 stages x 32768 = 99328 B -> 2 CTAs/SM.
// ---------------------------------------------------------------------------
#define AAT_PT 0
#define AAT_ST 33792
#define ATTN_SMEM (33792 + 65536)

__global__ __launch_bounds__(128) void attn_mma(
    const __nv_bfloat16* __restrict__ Qh, const __nv_bfloat16* __restrict__ Ql,
    const __nv_bfloat16* __restrict__ Kh, const __nv_bfloat16* __restrict__ Kl,
    const __nv_bfloat16* __restrict__ Vth, const __nv_bfloat16* __restrict__ Vtl,
    const __nv_bfloat16* __restrict__ relB,
    __nv_bfloat16* __restrict__ Aout_h, __nv_bfloat16* __restrict__ Aout_l)
{
    extern __shared__ __align__(16) uint8_t dynsm[];
    const uint32_t sbase = smem_u32(dynsm);
    uint8_t* sQh = dynsm;              // temporary, inside PtB region
    uint8_t* sQl = dynsm + 8192;
    __nv_bfloat16* PtB = (__nv_bfloat16*)(dynsm + AAT_PT);

    const int b  = blockIdx.z;
    const int n  = blockIdx.y;
    const int q0 = blockIdx.x * 64;
    const int tid = threadIdx.x;
    const int lane = tid & 31;
    const int w = tid >> 5;
    const int g = lane >> 2;
    const int t4 = lane & 3;
    const int mmi = lane >> 3;
    const int rr = lane & 7;

    const __nv_bfloat16* Vhb = Vth + (size_t)((b * NH_ + n) * HD_) * S_;
    const __nv_bfloat16* Vlb = Vtl + (size_t)((b * NH_ + n) * HD_) * S_;

    auto issue_kv = [&](int kt, int buf) {
        const int k0 = kt * 64;
        const uint32_t st = sbase + AAT_ST + buf * 32768;
#pragma unroll
        for (int l = 0; l < 4; l++) {
            int idx = tid + l * 128;
            int row = idx >> 3, seg = idx & 7;
            uint32_t off = (uint32_t)(row * 128 + ((seg ^ (row & 7)) << 4));
            size_t gk = ((size_t)(b * S_) + k0 + row) * H_ + n * HD_ + seg * 8;
            size_t gv = (size_t)row * S_ + k0 + seg * 8;
            CP16(st + off,         Kh + gk);
            CP16(st + off + 8192,  Kl + gk);
            CP16(st + off + 16384, Vhb + gv);
            CP16(st + off + 24576, Vlb + gv);
        }
    };

    // Q tile -> smem (temporary, in PtB region)
    for (int idx = tid; idx < 512; idx += 128) {
        int row = idx >> 3, seg = idx & 7;
        uint32_t off = (uint32_t)(row * 128 + ((seg ^ (row & 7)) << 4));
        size_t gq = ((size_t)(b * S_) + q0 + row) * H_ + n * HD_ + seg * 8;
        *(uint4*)(sQh + off) = *(const uint4*)(Qh + gq);
        *(uint4*)(sQl + off) = *(const uint4*)(Ql + gq);
    }

    // Prefetch first K/V tile
    issue_kv(0, 0);
    asm volatile("cp.async.commit_group;");
    __syncthreads();

    // Resident Q A-frags (ldmatrix: A layout m0..m3 = rows/rows+8 x klo/khi)
    uint32_t qah[4][4], qal[4][4];
    {
        const uint32_t uQh = sbase;
        const uint32_t uQl = sbase + 8192;
#pragma unroll
        for (int kb = 0; kb < 4; kb++) {
            uint32_t arow = 16 * w + ((mmi & 1) << 3) + rr;
            uint32_t abyte = kb * 32 + ((mmi >> 1) << 4);
            uint32_t aoff = swzb_u(arow, abyte);
            ldsm_x4(qah[kb][0], qah[kb][1], qah[kb][2], qah[kb][3], uQh + aoff);
            ldsm_x4(qal[kb][0], qal[kb][1], qal[kb][2], qal[kb][3], uQl + aoff);
        }
    }
    __syncthreads();   // Q smem dead; PtB may now overwrite it

    const int ql0 = 16 * w + g;
    const int qg0 = q0 + ql0;

    // Pt via MMA: Pt[q][r] = Qh[q] . relB[r]  (1-pass bf16, per-warp rows)
    {
#pragma unroll 4
        for (int j = 0; j < 33; j++) {
            int r = 8 * j + g;
            int rc = min(r, NREL - 1);
            const __nv_bfloat16* rb = relB + rc * HD_;
            float c[4] = {0.f, 0.f, 0.f, 0.f};
#pragma unroll
            for (int kb = 0; kb < 4; kb++) {
                uint32_t b0 = *(const uint32_t*)(rb + kb * 16 + 2 * t4);
                uint32_t b1 = *(const uint32_t*)(rb + kb * 16 + 2 * t4 + 8);
                mma16816(c, qah[kb][0], qah[kb][1], qah[kb][2], qah[kb][3], b0, b1);
            }
            int col = 8 * j + 2 * t4;
            *(uint32_t*)(PtB + ql0 * PTS + col) = pack_h(c[0], c[1]);
            *(uint32_t*)(PtB + (ql0 + 8) * PTS + col) = pack_h(c[2], c[3]);
        }
        __syncwarp();   // cross-lane smem dependency within warp
    }

    float oacc[8][4];
#pragma unroll
    for (int j = 0; j < 8; j++)
#pragma unroll
        for (int i = 0; i < 4; i++) oacc[j][i] = 0.f;
    float rmax0 = -INFINITY, rmax1 = -INFINITY;
    float rsum0 = 0.f, rsum1 = 0.f;

#pragma unroll 1
    for (int kt = 0; kt < 16; kt++) {
        const int k0 = kt * 64;
        const int cur = kt & 1;
        asm volatile("cp.async.wait_group 0;");
        __syncthreads();
        if (kt < 15) {
            issue_kv(kt + 1, cur ^ 1);
            asm volatile("cp.async.commit_group;");
        }

        const uint32_t uKh = sbase + AAT_ST + cur * 32768;
        const uint32_t uKl = uKh + 8192;
        const uint32_t uVh = uKh + 16384;
        const uint32_t uVl = uKh + 24576;

        // QK^T: ldmatrix B loads (jp pairs), 3-pass split MMA
        float sc[8][4];
#pragma unroll
        for (int j = 0; j < 8; j++)
#pragma unroll
            for (int i = 0; i < 4; i++) sc[j][i] = 0.f;
#pragma unroll
        for (int kb = 0; kb < 4; kb++) {
#pragma unroll
            for (int jp = 0; jp < 4; jp++) {
                uint32_t brow = 16 * jp + ((mmi >> 1) << 3) + rr;
                uint32_t bbyte = kb * 32 + ((mmi & 1) << 4);
                uint32_t boff = swzb_u(brow, bbyte);
                uint32_t bh0, bh1, bh2, bh3, bl0, bl1, bl2, bl3;
                ldsm_x4(bh0, bh1, bh2, bh3, uKh + boff);
                ldsm_x4(bl0, bl1, bl2, bl3, uKl + boff);
                mma16816(sc[2 * jp], qah[kb][0], qah[kb][1], qah[kb][2], qah[kb][3], bh0, bh1);
                mma16816(sc[2 * jp], qah[kb][0], qah[kb][1], qah[kb][2], qah[kb][3], bl0, bl1);
                mma16816(sc[2 * jp], qal[kb][0], qal[kb][1], qal[kb][2], qal[kb][3], bh0, bh1);
                mma16816(sc[2 * jp + 1], qah[kb][0], qah[kb][1], qah[kb][2], qah[kb][3], bh2, bh3);
                mma16816(sc[2 * jp + 1], qah[kb][0], qah[kb][1], qah[kb][2], qah[kb][3], bl2, bl3);
                mma16816(sc[2 * jp + 1], qal[kb][0], qal[kb][1], qal[kb][2], qal[kb][3], bh2, bh3);
            }
        }

        // Bias + scale
#pragma unroll
        for (int j = 0; j < 8; j++) {
            int col = k0 + 8 * j + 2 * t4;
            int r00 = min(128, max(-128, col     - qg0)) + 128;
            int r01 = min(128, max(-128, col + 1 - qg0)) + 128;
            int r10 = min(128, max(-128, col     - qg0 - 8)) + 128;
            int r11 = min(128, max(-128, col + 1 - qg0 - 8)) + 128;
            sc[j][0] = (sc[j][0] + __bfloat162float(PtB[ql0 * PTS + r00])) * 0.125f;
            sc[j][1] = (sc[j][1] + __bfloat162float(PtB[ql0 * PTS + r01])) * 0.125f;
            sc[j][2] = (sc[j][2] + __bfloat162float(PtB[(ql0 + 8) * PTS + r10])) * 0.125f;
            sc[j][3] = (sc[j][3] + __bfloat162float(PtB[(ql0 + 8) * PTS + r11])) * 0.125f;
        }

        // Online softmax
        float m0 = -INFINITY, m1 = -INFINITY;
#pragma unroll
        for (int j = 0; j < 8; j++) {
            m0 = fmaxf(m0, fmaxf(sc[j][0], sc[j][1]));
            m1 = fmaxf(m1, fmaxf(sc[j][2], sc[j][3]));
        }
        m0 = fmaxf(m0, __shfl_xor_sync(0xffffffffu, m0, 1, 4));
        m0 = fmaxf(m0, __shfl_xor_sync(0xffffffffu, m0, 2, 4));
        m1 = fmaxf(m1, __shfl_xor_sync(0xffffffffu, m1, 1, 4));
        m1 = fmaxf(m1, __shfl_xor_sync(0xffffffffu, m1, 2, 4));

        float nm0 = fmaxf(rmax0, m0);
        float nm1 = fmaxf(rmax1, m1);
        float esc0 = __expf(rmax0 - nm0);
        float esc1 = __expf(rmax1 - nm1);
        rmax0 = nm0; rmax1 = nm1;

        float s0 = 0.f, s1 = 0.f;
#pragma unroll
        for (int j = 0; j < 8; j++) {
            sc[j][0] = __expf(sc[j][0] - nm0);
            sc[j][1] = __expf(sc[j][1] - nm0);
            sc[j][2] = __expf(sc[j][2] - nm1);
            sc[j][3] = __expf(sc[j][3] - nm1);
            s0 += sc[j][0] + sc[j][1];
            s1 += sc[j][2] + sc[j][3];
        }
        s0 += __shfl_xor_sync(0xffffffffu, s0, 1, 4);
        s0 += __shfl_xor_sync(0xffffffffu, s0, 2, 4);
        s1 += __shfl_xor_sync(0xffffffffu, s1, 1, 4);
        s1 += __shfl_xor_sync(0xffffffffu, s1, 2, 4);
        rsum0 = rsum0 * esc0 + s0;
        rsum1 = rsum1 * esc1 + s1;

#pragma unroll
        for (int j = 0; j < 8; j++) {
            oacc[j][0] *= esc0; oacc[j][1] *= esc0;
            oacc[j][2] *= esc1; oacc[j][3] *= esc1;
        }

        // PV: ldmatrix B loads over V^T
#pragma unroll
        for (int kb = 0; kb < 4; kb++) {
            uint32_t ah0, ah1, ah2, ah3, al0, al1, al2, al3;
            pack_hl(sc[2 * kb][0], sc[2 * kb][1], ah0, al0);
            pack_hl(sc[2 * kb][2], sc[2 * kb][3], ah1, al1);
            pack_hl(sc[2 * kb + 1][0], sc[2 * kb + 1][1], ah2, al2);
            pack_hl(sc[2 * kb + 1][2], sc[2 * kb + 1][3], ah3, al3);
#pragma unroll
            for (int jp = 0; jp < 4; jp++) {
                uint32_t brow = 16 * jp + ((mmi >> 1) << 3) + rr;
                uint32_t bbyte = kb * 32 + ((mmi & 1) << 4);
                uint32_t boff = swzb_u(brow, bbyte);
                uint32_t bh0, bh1, bh2, bh3, bl0, bl1, bl2, bl3;
                ldsm_x4(bh0, bh1, bh2, bh3, uVh + boff);
                ldsm_x4(bl0, bl1, bl2, bl3, uVl + boff);
                mma16816(oacc[2 * jp], ah0, ah1, ah2, ah3, bh0, bh1);
                mma16816(oacc[2 * jp], ah0, ah1, ah2, ah3, bl0, bl1);
                mma16816(oacc[2 * jp], al0, al1, al2, al3, bh0, bh1);
                mma16816(oacc[2 * jp + 1], ah0, ah1, ah2, ah3, bh2, bh3);
                mma16816(oacc[2 * jp + 1], ah0, ah1, ah2, ah3, bl2, bl3);
                mma16816(oacc[2 * jp + 1], al0, al1, al2, al3, bh2, bh3);
            }
        }
        __syncthreads();   // done reading cur buffer before next overwrite
    }

    // Epilogue: normalize + write bf16 hi/lo
    float inv0 = 1.f / rsum0;
    float inv1 = 1.f / rsum1;
    size_t base0 = ((size_t)b * S_ + q0 + 16 * w + g) * H_ + n * HD_;
    size_t base1 = base0 + 8 * H_;
#pragma unroll
    for (int j = 0; j < 8; j++) {
        int col = 8 * j + 2 * t4;
        uint32_t h0, l0, h1, l1;
        pack_hl(oacc[j][0] * inv0, oacc[j][1] * inv0, h0, l0);
        pack_hl(oacc[j][2] * inv1, oacc[j][3] * inv1, h1, l1);
        *(uint32_t*)(Aout_h + base0 + col) = h0;
        *(uint32_t*)(Aout_l + base0 + col) = l0;
        *(uint32_t*)(Aout_h + base1 + col) = h1;
        *(uint32_t*)(Aout_l + base1 + col) = l1;
    }
}

// ---------------------------------------------------------------------------
// Launch
// ---------------------------------------------------------------------------
extern "C" void kernel_launch(void* const* d_in, const int* in_sizes, int n_in,
                              void* d_out, int out_size)
{
    const float* x   = (const float*)d_in[0];
    const float* Wq  = (const float*)d_in[1];
    const float* bq  = (const float*)d_in[2];
    const float* Wk  = (const float*)d_in[3];
    const float* bk  = (const float*)d_in[4];
    const float* Wv  = (const float*)d_in[5];
    const float* bv  = (const float*)d_in[6];
    const float* Wo  = (const float*)d_in[7];
    const float* bo  = (const float*)d_in[8];
    const float* rel = (const float*)d_in[9];
    float* out = (float*)d_out;

    float* pV;
    __nv_bfloat16 *xh, *xl, *wqh, *wql, *wkh, *wkl, *wvh, *wvl, *woh, *wol, *ah, *al;
    __nv_bfloat16 *qh, *ql, *kh, *kl, *vth, *vtl, *relB;
    cudaGetSymbolAddress((void**)&pV, g_V);
    cudaGetSymbolAddress((void**)&xh, g_xh);
    cudaGetSymbolAddress((void**)&xl, g_xl);
    cudaGetSymbolAddress((void**)&wqh, g_Wqh);
    cudaGetSymbolAddress((void**)&wql, g_Wql);
    cudaGetSymbolAddress((void**)&wkh, g_Wkh);
    cudaGetSymbolAddress((void**)&wkl, g_Wkl);
    cudaGetSymbolAddress((void**)&wvh, g_Wvh);
    cudaGetSymbolAddress((void**)&wvl, g_Wvl);
    cudaGetSymbolAddress((void**)&woh, g_Woh);
    cudaGetSymbolAddress((void**)&wol, g_Wol);
    cudaGetSymbolAddress((void**)&ah, g_ah);
    cudaGetSymbolAddress((void**)&al, g_al);
    cudaGetSymbolAddress((void**)&qh, g_Qh);
    cudaGetSymbolAddress((void**)&ql, g_Ql);
    cudaGetSymbolAddress((void**)&kh, g_Kh);
    cudaGetSymbolAddress((void**)&kl, g_Kl);
    cudaGetSymbolAddress((void**)&vth, g_Vth);
    cudaGetSymbolAddress((void**)&vtl, g_Vtl);
    cudaGetSymbolAddress((void**)&relB, g_relB);

    cudaFuncSetAttribute(attn_mma, cudaFuncAttributeMaxDynamicSharedMemorySize, ATTN_SMEM);
    cudaFuncSetAttribute(gemm_mma, cudaFuncAttributeMaxDynamicSharedMemorySize, GEMM_SMEM);
    cudaFuncSetAttribute(gemm_qkv, cudaFuncAttributeMaxDynamicSharedMemorySize, GEMM_SMEM);

    split_all<<<SPLIT_BLOCKS, 256>>>(
        (const float4*)x,  (uint2*)xh,  (uint2*)xl,
        (const float4*)Wq, (uint2*)wqh, (uint2*)wql,
        (const float4*)Wk, (uint2*)wkh, (uint2*)wkl,
        (const float4*)Wv, (uint2*)wvh, (uint2*)wvl,
        (const float4*)Wo, (uint2*)woh, (uint2*)wol,
        (const float4*)rel, (uint2*)relB);

    dim3 qkv_grid(H_ / 128, MTOT / 128, 3);   // (8, 32, 3) = 768 blocks
    gemm_qkv<<<qkv_grid, 256, GEMM_SMEM>>>(xh, xl,
        wqh, wql, bq, qh, ql,
        wkh, wkl, bk, kh, kl,
        wvh, wvl, bv, pV);

    vtrans_kernel<<<dim3(S_ / 64, NH_, B_), 256>>>(pV, vth, vtl);

    dim3 attn_grid(S_ / 64, NH_, B_);
    attn_mma<<<attn_grid, 128, ATTN_SMEM>>>(qh, ql, kh, kl, vth, vtl, relB, ah, al);

    dim3 gemm_grid(H_ / 128, MTOT / 128);
    gemm_mma<<<gemm_grid, 256, GEMM_SMEM>>>(ah, al, woh, wol, bo, out);
}